// round 2
// baseline (speedup 1.0000x reference)
#include <cuda_runtime.h>
#include <math.h>

#define SEQ 2048
#define DM  2048
#define NH  16
#define DH  128
#define HALF 64

// Scratch (allocation-free: device globals)
__device__ float g_Q[SEQ * DM];
__device__ float g_K[SEQ * DM];
__device__ float g_V[SEQ * DM];
__device__ float g_A[SEQ * DM];
__device__ float g_cos[SEQ * HALF];
__device__ float g_sin[SEQ * HALF];

// ---------------------------------------------------------------------------
// RoPE tables: cos/sin of s * inv_freq(j), computed in double for accuracy.
// inv_freq = (phi-1) / 10000^(j/64)
// ---------------------------------------------------------------------------
__global__ void rope_tables_kernel() {
    int idx = blockIdx.x * blockDim.x + threadIdx.x;
    if (idx >= SEQ * HALF) return;
    int s = idx / HALF;
    int j = idx % HALF;
    double inv = 0.61803398874989484820 / pow(10000.0, (double)j / 64.0);
    double ang = (double)s * inv;
    double si, co;
    sincos(ang, &si, &co);
    g_cos[idx] = (float)co;
    g_sin[idx] = (float)si;
}

// ---------------------------------------------------------------------------
// Apply RoPE in place to Q and K. One thread per (s, h, j) pair.
// ---------------------------------------------------------------------------
__global__ void rope_apply_kernel() {
    int idx = blockIdx.x * blockDim.x + threadIdx.x;
    if (idx >= SEQ * NH * HALF) return;
    int s   = idx / (NH * HALF);
    int rem = idx % (NH * HALF);
    int h   = rem / HALF;
    int j   = rem % HALF;
    int base = s * DM + h * DH + j;
    float c  = g_cos[s * HALF + j];
    float sn = g_sin[s * HALF + j];
    float q1 = g_Q[base], q2 = g_Q[base + HALF];
    g_Q[base]        = q1 * c - q2 * sn;
    g_Q[base + HALF] = q1 * sn + q2 * c;
    float k1 = g_K[base], k2 = g_K[base + HALF];
    g_K[base]        = k1 * c - k2 * sn;
    g_K[base + HALF] = k1 * sn + k2 * c;
}

// ---------------------------------------------------------------------------
// 2048x2048x2048 fp32 GEMM, row-major. 128x128 block tile, K-step 8,
// 256 threads, each computes 8x8. C = A @ B.
// ---------------------------------------------------------------------------
__global__ void __launch_bounds__(256, 2) gemm_f32(const float* __restrict__ A,
                                                   const float* __restrict__ B,
                                                   float* __restrict__ C) {
    __shared__ float As[8][128];   // [kk][m]
    __shared__ float Bs[8][128];   // [kk][n]

    int t  = threadIdx.x;
    int tx = t & 15;
    int ty = t >> 4;
    int m0 = blockIdx.y * 128;
    int n0 = blockIdx.x * 128;

    float acc[8][8];
    #pragma unroll
    for (int i = 0; i < 8; i++)
        #pragma unroll
        for (int j = 0; j < 8; j++) acc[i][j] = 0.f;

    // A loader: row ar (0..127), col group ac (0 or 4)
    int ar = t >> 1;
    int ac = (t & 1) * 4;
    // B loader: row bk (0..7), col bc (0..124 step 4)
    int bk = t >> 5;
    int bc = (t & 31) * 4;

    const float* Ap = A + (size_t)(m0 + ar) * DM + ac;
    const float* Bp = B + (size_t)bk * DM + n0 + bc;

    for (int k0 = 0; k0 < DM; k0 += 8) {
        float4 av = *(const float4*)(Ap + k0);
        float4 bv = *(const float4*)(Bp + (size_t)k0 * DM);
        __syncthreads();   // previous compute done before smem overwrite
        As[ac + 0][ar] = av.x;
        As[ac + 1][ar] = av.y;
        As[ac + 2][ar] = av.z;
        As[ac + 3][ar] = av.w;
        *(float4*)&Bs[bk][bc] = bv;
        __syncthreads();

        #pragma unroll
        for (int kk = 0; kk < 8; kk++) {
            float4 a0 = *(float4*)&As[kk][ty * 8];
            float4 a1 = *(float4*)&As[kk][ty * 8 + 4];
            float4 b0 = *(float4*)&Bs[kk][tx * 8];
            float4 b1 = *(float4*)&Bs[kk][tx * 8 + 4];
            float a[8] = {a0.x, a0.y, a0.z, a0.w, a1.x, a1.y, a1.z, a1.w};
            float b[8] = {b0.x, b0.y, b0.z, b0.w, b1.x, b1.y, b1.z, b1.w};
            #pragma unroll
            for (int i = 0; i < 8; i++)
                #pragma unroll
                for (int j = 0; j < 8; j++)
                    acc[i][j] += a[i] * b[j];
        }
    }

    #pragma unroll
    for (int i = 0; i < 8; i++) {
        float* cp = C + (size_t)(m0 + ty * 8 + i) * DM + n0 + tx * 8;
        *(float4*)cp       = make_float4(acc[i][0], acc[i][1], acc[i][2], acc[i][3]);
        *(float4*)(cp + 4) = make_float4(acc[i][4], acc[i][5], acc[i][6], acc[i][7]);
    }
}

// ---------------------------------------------------------------------------
// Causal flash attention, one block per (head, 64-query tile).
// Online softmax. Smem: Q [64][132] (padded), K [64][128], V [64][128],
// scores transposed St[j][i] [64][64], row stats.
// ---------------------------------------------------------------------------
#define BQ 64
#define BK 64
#define QST 132

__global__ void __launch_bounds__(256) flash_kernel(const float* __restrict__ Qg,
                                                    const float* __restrict__ Kg,
                                                    const float* __restrict__ Vg,
                                                    float* __restrict__ Og) {
    extern __shared__ float sm[];
    float* Qv    = sm;                    // [64][132]
    float* Kv    = Qv + BQ * QST;         // [64][128]
    float* Vv    = Kv + BK * DH;          // [64][128]
    float* St    = Vv + BK * DH;          // [64][64], St[j*64+i]
    float* rowm  = St + BQ * BK;          // [64]
    float* rowl  = rowm + BQ;             // [64]
    float* alpha = rowl + BQ;             // [64]

    int t  = threadIdx.x;
    int tx = t & 15;
    int ty = t >> 4;
    int h  = blockIdx.y;
    int qt = (int)gridDim.x - 1 - (int)blockIdx.x;  // heavy blocks first
    int q0 = qt * BQ;

    // Load Q tile (coalesced float4, padded smem rows)
    {
        int c4 = t & 31;     // float4 column 0..31
        int r  = t >> 5;     // 0..7
        #pragma unroll
        for (int p = 0; p < 8; p++) {
            int rr = r + p * 8;
            float4 v = *(const float4*)&Qg[(size_t)(q0 + rr) * DM + h * DH + c4 * 4];
            *(float4*)&Qv[rr * QST + c4 * 4] = v;
        }
    }
    if (t < BQ) { rowm[t] = -1e30f; rowl[t] = 0.f; }

    float o[4][8];
    #pragma unroll
    for (int i = 0; i < 4; i++)
        #pragma unroll
        for (int j = 0; j < 8; j++) o[i][j] = 0.f;

    __syncthreads();

    const float scale = 0.08838834764831845f;  // 1/sqrt(128)

    for (int kt = 0; kt <= qt; kt++) {
        int k0 = kt * BK;
        // Load K, V tiles
        {
            int c4 = t & 31;
            int r  = t >> 5;
            #pragma unroll
            for (int p = 0; p < 8; p++) {
                int rr = r + p * 8;
                *(float4*)&Kv[rr * DH + c4 * 4] =
                    *(const float4*)&Kg[(size_t)(k0 + rr) * DM + h * DH + c4 * 4];
                *(float4*)&Vv[rr * DH + c4 * 4] =
                    *(const float4*)&Vg[(size_t)(k0 + rr) * DM + h * DH + c4 * 4];
            }
        }
        __syncthreads();

        // QK^T: micro-tile 4x4, i = tx*4+ii (query), j = ty*4+jj (key)
        float sa[4][4];
        #pragma unroll
        for (int ii = 0; ii < 4; ii++)
            #pragma unroll
            for (int jj = 0; jj < 4; jj++) sa[ii][jj] = 0.f;

        #pragma unroll 8
        for (int kk = 0; kk < DH; kk += 4) {
            float4 qf[4], kf[4];
            #pragma unroll
            for (int ii = 0; ii < 4; ii++)
                qf[ii] = *(float4*)&Qv[(tx * 4 + ii) * QST + kk];
            #pragma unroll
            for (int jj = 0; jj < 4; jj++)
                kf[jj] = *(float4*)&Kv[(ty * 4 + jj) * DH + kk];
            #pragma unroll
            for (int ii = 0; ii < 4; ii++)
                #pragma unroll
                for (int jj = 0; jj < 4; jj++)
                    sa[ii][jj] += qf[ii].x * kf[jj].x + qf[ii].y * kf[jj].y +
                                  qf[ii].z * kf[jj].z + qf[ii].w * kf[jj].w;
        }

        bool diag = (kt == qt);
        #pragma unroll
        for (int jj = 0; jj < 4; jj++)
            #pragma unroll
            for (int ii = 0; ii < 4; ii++) {
                int i = tx * 4 + ii;
                int j = ty * 4 + jj;
                float v = sa[ii][jj] * scale;
                if (diag && (j > i)) v = -1e9f;
                St[j * BQ + i] = v;   // conflict-free: lanes vary i contiguously
            }
        __syncthreads();

        // Pass A: row max + correction factor (64 threads, one per query row)
        if (t < BQ) {
            float m = -1e30f;
            #pragma unroll 8
            for (int j = 0; j < BK; j++) m = fmaxf(m, St[j * BQ + t]);
            float mo = rowm[t];
            float mn = fmaxf(mo, m);
            rowm[t]  = mn;
            alpha[t] = expf(mo - mn);
        }
        __syncthreads();

        // Pass B: exponentiate in place (all 256 threads), rescale O by alpha
        #pragma unroll
        for (int p = 0; p < 16; p++) {
            int e = t + p * 256;
            int i = e & 63;
            St[e] = expf(St[e] - rowm[i]);
        }
        {
            float al[4];
            #pragma unroll
            for (int ii = 0; ii < 4; ii++) al[ii] = alpha[ty * 4 + ii];
            #pragma unroll
            for (int ii = 0; ii < 4; ii++)
                #pragma unroll
                for (int jj = 0; jj < 8; jj++) o[ii][jj] *= al[ii];
        }
        __syncthreads();

        // Pass C: row sums -> running denominator
        if (t < BQ) {
            float ssum = 0.f;
            #pragma unroll 8
            for (int j = 0; j < BK; j++) ssum += St[j * BQ + t];
            rowl[t] = rowl[t] * alpha[t] + ssum;
        }

        // PV: O[i][c] += P[i][r] * V[r][c], i = ty*4+ii, c = tx*8+jj
        #pragma unroll 4
        for (int r = 0; r < BK; r++) {
            float4 pv = *(float4*)&St[r * BQ + ty * 4];
            float4 v0 = *(float4*)&Vv[r * DH + tx * 8];
            float4 v1 = *(float4*)&Vv[r * DH + tx * 8 + 4];
            float pr[4] = {pv.x, pv.y, pv.z, pv.w};
            float vv[8] = {v0.x, v0.y, v0.z, v0.w, v1.x, v1.y, v1.z, v1.w};
            #pragma unroll
            for (int ii = 0; ii < 4; ii++)
                #pragma unroll
                for (int jj = 0; jj < 8; jj++)
                    o[ii][jj] += pr[ii] * vv[jj];
        }
        __syncthreads();  // before next tile overwrites K/V/St; also publishes rowl
    }

    // Epilogue: normalize and store
    #pragma unroll
    for (int ii = 0; ii < 4; ii++) {
        float inv = 1.f / rowl[ty * 4 + ii];
        float* op = Og + (size_t)(q0 + ty * 4 + ii) * DM + h * DH + tx * 8;
        *(float4*)op       = make_float4(o[ii][0] * inv, o[ii][1] * inv,
                                         o[ii][2] * inv, o[ii][3] * inv);
        *(float4*)(op + 4) = make_float4(o[ii][4] * inv, o[ii][5] * inv,
                                         o[ii][6] * inv, o[ii][7] * inv);
    }
}

// ---------------------------------------------------------------------------
extern "C" void kernel_launch(void* const* d_in, const int* in_sizes, int n_in,
                              void* d_out, int out_size) {
    const float* x  = (const float*)d_in[0];
    const float* Wq = (const float*)d_in[1];
    const float* Wk = (const float*)d_in[2];
    const float* Wv = (const float*)d_in[3];
    const float* Wo = (const float*)d_in[4];
    float* out = (float*)d_out;

    float *pQ, *pK, *pV, *pA;
    cudaGetSymbolAddress((void**)&pQ, g_Q);
    cudaGetSymbolAddress((void**)&pK, g_K);
    cudaGetSymbolAddress((void**)&pV, g_V);
    cudaGetSymbolAddress((void**)&pA, g_A);

    // RoPE tables
    rope_tables_kernel<<<(SEQ * HALF + 255) / 256, 256>>>();

    // Q/K/V projections
    dim3 ggrid(DM / 128, SEQ / 128);
    gemm_f32<<<ggrid, 256>>>(x, Wq, pQ);
    gemm_f32<<<ggrid, 256>>>(x, Wk, pK);
    gemm_f32<<<ggrid, 256>>>(x, Wv, pV);

    // RoPE on Q, K
    rope_apply_kernel<<<(SEQ * NH * HALF) / 256, 256>>>();

    // Flash attention
    size_t smem = (size_t)(BQ * QST + BK * DH + BK * DH + BQ * BK + 3 * BQ) * sizeof(float);
    cudaFuncSetAttribute(flash_kernel, cudaFuncAttributeMaxDynamicSharedMemorySize, (int)smem);
    flash_kernel<<<dim3(SEQ / BQ, NH), 256, smem>>>(pQ, pK, pV, pA);

    // Output projection
    gemm_f32<<<ggrid, 256>>>(pA, Wo, out);
}

// round 4
// speedup vs baseline: 1.4614x; 1.4614x over previous
#include <cuda_runtime.h>
#include <cuda_bf16.h>
#include <math.h>
#include <stdint.h>

#define SEQ 2048
#define DM  2048
#define NH  16
#define DH  128
#define HALF 64

// ---------------- scratch (device globals; allocation-free) ----------------
__device__ float g_Q[SEQ * DM];
__device__ float g_K[SEQ * DM];
__device__ float g_V[SEQ * DM];
__device__ float g_A[SEQ * DM];
__device__ float g_cos[SEQ * HALF];
__device__ float g_sin[SEQ * HALF];
// bf16 split operands
__device__ __nv_bfloat16 g_xh[SEQ * DM];
__device__ __nv_bfloat16 g_xl[SEQ * DM];
__device__ __nv_bfloat16 g_Wqh[DM * DM];
__device__ __nv_bfloat16 g_Wql[DM * DM];
__device__ __nv_bfloat16 g_Wkh[DM * DM];
__device__ __nv_bfloat16 g_Wkl[DM * DM];
__device__ __nv_bfloat16 g_Wvh[DM * DM];
__device__ __nv_bfloat16 g_Wvl[DM * DM];
__device__ __nv_bfloat16 g_Woh[DM * DM];
__device__ __nv_bfloat16 g_Wol[DM * DM];

// ---------------- prep kernels ----------------
__global__ void rope_tables_kernel() {
    int idx = blockIdx.x * blockDim.x + threadIdx.x;
    if (idx >= SEQ * HALF) return;
    int s = idx / HALF;
    int j = idx % HALF;
    double inv = 0.61803398874989484820 / pow(10000.0, (double)j / 64.0);
    double ang = (double)s * inv;
    double si, co;
    sincos(ang, &si, &co);
    g_cos[idx] = (float)co;
    g_sin[idx] = (float)si;
}

__global__ void rope_apply_kernel() {
    int idx = blockIdx.x * blockDim.x + threadIdx.x;
    if (idx >= SEQ * NH * HALF) return;
    int s   = idx / (NH * HALF);
    int rem = idx % (NH * HALF);
    int h   = rem / HALF;
    int j   = rem % HALF;
    int base = s * DM + h * DH + j;
    float c  = g_cos[s * HALF + j];
    float sn = g_sin[s * HALF + j];
    float q1 = g_Q[base], q2 = g_Q[base + HALF];
    g_Q[base]        = q1 * c - q2 * sn;
    g_Q[base + HALF] = q1 * sn + q2 * c;
    float k1 = g_K[base], k2 = g_K[base + HALF];
    g_K[base]        = k1 * c - k2 * sn;
    g_K[base + HALF] = k1 * sn + k2 * c;
}

// fp32 -> (hi, lo) bf16 split, elementwise
__global__ void split_f32(const float* __restrict__ s, __nv_bfloat16* __restrict__ h,
                          __nv_bfloat16* __restrict__ l, int n) {
    int i = blockIdx.x * blockDim.x + threadIdx.x;
    if (i >= n) return;
    float x = s[i];
    __nv_bfloat16 hh = __float2bfloat16(x);
    h[i] = hh;
    l[i] = __float2bfloat16(x - __bfloat162float(hh));
}

// W[K][N] fp32 -> Wt_hi[N][K], Wt_lo[N][K] bf16 (transpose + split)
__global__ void transpose_split(const float* __restrict__ W, __nv_bfloat16* __restrict__ Th,
                                __nv_bfloat16* __restrict__ Tl) {
    __shared__ float tile[32][33];
    int bx = blockIdx.x * 32;  // n
    int by = blockIdx.y * 32;  // k
    int tx = threadIdx.x, ty = threadIdx.y;  // 32 x 8
    #pragma unroll
    for (int i = 0; i < 32; i += 8)
        tile[ty + i][tx] = W[(size_t)(by + ty + i) * DM + bx + tx];
    __syncthreads();
    #pragma unroll
    for (int i = 0; i < 32; i += 8) {
        float x = tile[tx][ty + i];
        __nv_bfloat16 hh = __float2bfloat16(x);
        size_t o = (size_t)(bx + ty + i) * DM + by + tx;
        Th[o] = hh;
        Tl[o] = __float2bfloat16(x - __bfloat162float(hh));
    }
}

// ---------------------------------------------------------------------------
// Split-bf16 GEMM via mma.sync (HMMA, works on plain sm_100).
// C[2048,2048] = A @ B with A as (Ah+Al) row-major [M,K] and B transposed as
// Bt (Bh+Bl) [N,K]. C = Ah*Bh^T + Ah*Bl^T + Al*Bh^T (3 passes, acc in regs).
// CTA 128x128, 8 warps (2 M x 4 N), warp tile 64x32, K staged 64.
// ---------------------------------------------------------------------------
#define AST 72   // smem row stride in bf16 (64 + 8 pad; 36 words -> conflict-free)

__device__ __forceinline__ void mma16816(float c[4], const uint32_t a[4], const uint32_t b[2]) {
    asm volatile(
        "mma.sync.aligned.m16n8k16.row.col.f32.bf16.bf16.f32 "
        "{%0,%1,%2,%3}, {%4,%5,%6,%7}, {%8,%9}, {%0,%1,%2,%3};"
        : "+f"(c[0]), "+f"(c[1]), "+f"(c[2]), "+f"(c[3])
        : "r"(a[0]), "r"(a[1]), "r"(a[2]), "r"(a[3]), "r"(b[0]), "r"(b[1]));
}

__global__ void __launch_bounds__(256, 2) gemm_mma(
    const __nv_bfloat16* __restrict__ Ah, const __nv_bfloat16* __restrict__ Al,
    const __nv_bfloat16* __restrict__ Bh, const __nv_bfloat16* __restrict__ Bl,
    float* __restrict__ C) {
    __shared__ __nv_bfloat16 As[128 * AST];
    __shared__ __nv_bfloat16 Bs[128 * AST];

    int t    = threadIdx.x;
    int wid  = t >> 5;
    int lane = t & 31;
    int wm   = (wid & 1) * 64;
    int wn   = (wid >> 1) * 32;
    int g    = lane >> 2;   // 0..7
    int q    = lane & 3;    // 0..3

    int m0 = blockIdx.y * 128;
    int n0 = blockIdx.x * 128;

    // loader mapping: idx = t + i*256; r = idx>>3 (row 0..127), c = idx&7 (8-elem chunk)
    int lr = t >> 3;
    int lc = t & 7;

    float acc[4][4][4];
    #pragma unroll
    for (int mt = 0; mt < 4; mt++)
        #pragma unroll
        for (int nt = 0; nt < 4; nt++)
            #pragma unroll
            for (int e = 0; e < 4; e++) acc[mt][nt][e] = 0.f;

    const __nv_bfloat16* APASS[3] = {Ah, Ah, Al};
    const __nv_bfloat16* BPASS[3] = {Bh, Bl, Bh};

    for (int pass = 0; pass < 3; pass++) {
        const __nv_bfloat16* Ag = APASS[pass];
        const __nv_bfloat16* Bg = BPASS[pass];
        for (int s = 0; s < 32; s++) {
            int k0 = s * 64;
            uint4 av[4], bv[4];
            #pragma unroll
            for (int i = 0; i < 4; i++) {
                int r = lr + i * 32;
                av[i] = *(const uint4*)(Ag + (size_t)(m0 + r) * DM + k0 + lc * 8);
                bv[i] = *(const uint4*)(Bg + (size_t)(n0 + r) * DM + k0 + lc * 8);
            }
            __syncthreads();   // previous stage's mma done before overwrite
            #pragma unroll
            for (int i = 0; i < 4; i++) {
                int r = lr + i * 32;
                *(uint4*)(As + r * AST + lc * 8) = av[i];
                *(uint4*)(Bs + r * AST + lc * 8) = bv[i];
            }
            __syncthreads();

            #pragma unroll
            for (int kk = 0; kk < 64; kk += 16) {
                uint32_t a[4][4], b[4][2];
                #pragma unroll
                for (int mt = 0; mt < 4; mt++) {
                    const __nv_bfloat16* p = As + (wm + mt * 16 + g) * AST + kk + q * 2;
                    a[mt][0] = *(const uint32_t*)p;
                    a[mt][1] = *(const uint32_t*)(p + 8 * AST);
                    a[mt][2] = *(const uint32_t*)(p + 8);
                    a[mt][3] = *(const uint32_t*)(p + 8 * AST + 8);
                }
                #pragma unroll
                for (int nt = 0; nt < 4; nt++) {
                    const __nv_bfloat16* p = Bs + (wn + nt * 8 + g) * AST + kk + q * 2;
                    b[nt][0] = *(const uint32_t*)p;
                    b[nt][1] = *(const uint32_t*)(p + 8);
                }
                #pragma unroll
                for (int mt = 0; mt < 4; mt++)
                    #pragma unroll
                    for (int nt = 0; nt < 4; nt++)
                        mma16816(acc[mt][nt], a[mt], b[nt]);
            }
        }
    }

    // epilogue: c0,c1 -> (row, col..col+1); c2,c3 -> (row+8, col..col+1)
    #pragma unroll
    for (int mt = 0; mt < 4; mt++) {
        int row = m0 + wm + mt * 16 + g;
        #pragma unroll
        for (int nt = 0; nt < 4; nt++) {
            int col = n0 + wn + nt * 8 + q * 2;
            *(float2*)(C + (size_t)row * DM + col)       = make_float2(acc[mt][nt][0], acc[mt][nt][1]);
            *(float2*)(C + (size_t)(row + 8) * DM + col) = make_float2(acc[mt][nt][2], acc[mt][nt][3]);
        }
    }
}

// ---------------------------------------------------------------------------
// Causal flash attention (fp32), unchanged.
// ---------------------------------------------------------------------------
#define BQ 64
#define BK 64
#define QST 132

__global__ void __launch_bounds__(256) flash_kernel(const float* __restrict__ Qg,
                                                    const float* __restrict__ Kg,
                                                    const float* __restrict__ Vg,
                                                    float* __restrict__ Og) {
    extern __shared__ float smf[];
    float* Qv    = smf;
    float* Kv    = Qv + BQ * QST;
    float* Vv    = Kv + BK * DH;
    float* St    = Vv + BK * DH;
    float* rowm  = St + BQ * BK;
    float* rowl  = rowm + BQ;
    float* alpha = rowl + BQ;

    int t  = threadIdx.x;
    int tx = t & 15;
    int ty = t >> 4;
    int h  = blockIdx.y;
    int qt = (int)gridDim.x - 1 - (int)blockIdx.x;
    int q0 = qt * BQ;

    {
        int c4 = t & 31;
        int r  = t >> 5;
        #pragma unroll
        for (int p = 0; p < 8; p++) {
            int rr = r + p * 8;
            float4 v = *(const float4*)&Qg[(size_t)(q0 + rr) * DM + h * DH + c4 * 4];
            *(float4*)&Qv[rr * QST + c4 * 4] = v;
        }
    }
    if (t < BQ) { rowm[t] = -1e30f; rowl[t] = 0.f; }

    float o[4][8];
    #pragma unroll
    for (int i = 0; i < 4; i++)
        #pragma unroll
        for (int j = 0; j < 8; j++) o[i][j] = 0.f;

    __syncthreads();

    const float scale = 0.08838834764831845f;

    for (int kt = 0; kt <= qt; kt++) {
        int k0 = kt * BK;
        {
            int c4 = t & 31;
            int r  = t >> 5;
            #pragma unroll
            for (int p = 0; p < 8; p++) {
                int rr = r + p * 8;
                *(float4*)&Kv[rr * DH + c4 * 4] =
                    *(const float4*)&Kg[(size_t)(k0 + rr) * DM + h * DH + c4 * 4];
                *(float4*)&Vv[rr * DH + c4 * 4] =
                    *(const float4*)&Vg[(size_t)(k0 + rr) * DM + h * DH + c4 * 4];
            }
        }
        __syncthreads();

        float sa[4][4];
        #pragma unroll
        for (int ii = 0; ii < 4; ii++)
            #pragma unroll
            for (int jj = 0; jj < 4; jj++) sa[ii][jj] = 0.f;

        #pragma unroll 8
        for (int kk = 0; kk < DH; kk += 4) {
            float4 qf[4], kf[4];
            #pragma unroll
            for (int ii = 0; ii < 4; ii++)
                qf[ii] = *(float4*)&Qv[(tx * 4 + ii) * QST + kk];
            #pragma unroll
            for (int jj = 0; jj < 4; jj++)
                kf[jj] = *(float4*)&Kv[(ty * 4 + jj) * DH + kk];
            #pragma unroll
            for (int ii = 0; ii < 4; ii++)
                #pragma unroll
                for (int jj = 0; jj < 4; jj++)
                    sa[ii][jj] += qf[ii].x * kf[jj].x + qf[ii].y * kf[jj].y +
                                  qf[ii].z * kf[jj].z + qf[ii].w * kf[jj].w;
        }

        bool diag = (kt == qt);
        #pragma unroll
        for (int jj = 0; jj < 4; jj++)
            #pragma unroll
            for (int ii = 0; ii < 4; ii++) {
                int i = tx * 4 + ii;
                int j = ty * 4 + jj;
                float v = sa[ii][jj] * scale;
                if (diag && (j > i)) v = -1e9f;
                St[j * BQ + i] = v;
            }
        __syncthreads();

        if (t < BQ) {
            float m = -1e30f;
            #pragma unroll 8
            for (int j = 0; j < BK; j++) m = fmaxf(m, St[j * BQ + t]);
            float mo = rowm[t];
            float mn = fmaxf(mo, m);
            rowm[t]  = mn;
            alpha[t] = expf(mo - mn);
        }
        __syncthreads();

        #pragma unroll
        for (int p = 0; p < 16; p++) {
            int e = t + p * 256;
            int i = e & 63;
            St[e] = expf(St[e] - rowm[i]);
        }
        {
            float al[4];
            #pragma unroll
            for (int ii = 0; ii < 4; ii++) al[ii] = alpha[ty * 4 + ii];
            #pragma unroll
            for (int ii = 0; ii < 4; ii++)
                #pragma unroll
                for (int jj = 0; jj < 8; jj++) o[ii][jj] *= al[ii];
        }
        __syncthreads();

        if (t < BQ) {
            float ssum = 0.f;
            #pragma unroll 8
            for (int j = 0; j < BK; j++) ssum += St[j * BQ + t];
            rowl[t] = rowl[t] * alpha[t] + ssum;
        }

        #pragma unroll 4
        for (int r = 0; r < BK; r++) {
            float4 pv = *(float4*)&St[r * BQ + ty * 4];
            float4 v0 = *(float4*)&Vv[r * DH + tx * 8];
            float4 v1 = *(float4*)&Vv[r * DH + tx * 8 + 4];
            float pr[4] = {pv.x, pv.y, pv.z, pv.w};
            float vv[8] = {v0.x, v0.y, v0.z, v0.w, v1.x, v1.y, v1.z, v1.w};
            #pragma unroll
            for (int ii = 0; ii < 4; ii++)
                #pragma unroll
                for (int jj = 0; jj < 8; jj++)
                    o[ii][jj] += pr[ii] * vv[jj];
        }
        __syncthreads();
    }

    #pragma unroll
    for (int ii = 0; ii < 4; ii++) {
        float inv = 1.f / rowl[ty * 4 + ii];
        float* op = Og + (size_t)(q0 + ty * 4 + ii) * DM + h * DH + tx * 8;
        *(float4*)op       = make_float4(o[ii][0] * inv, o[ii][1] * inv,
                                         o[ii][2] * inv, o[ii][3] * inv);
        *(float4*)(op + 4) = make_float4(o[ii][4] * inv, o[ii][5] * inv,
                                         o[ii][6] * inv, o[ii][7] * inv);
    }
}

// ---------------------------------------------------------------------------
extern "C" void kernel_launch(void* const* d_in, const int* in_sizes, int n_in,
                              void* d_out, int out_size) {
    const float* x  = (const float*)d_in[0];
    const float* Wq = (const float*)d_in[1];
    const float* Wk = (const float*)d_in[2];
    const float* Wv = (const float*)d_in[3];
    const float* Wo = (const float*)d_in[4];
    float* out = (float*)d_out;

    float *pQ, *pK, *pV, *pA;
    cudaGetSymbolAddress((void**)&pQ, g_Q);
    cudaGetSymbolAddress((void**)&pK, g_K);
    cudaGetSymbolAddress((void**)&pV, g_V);
    cudaGetSymbolAddress((void**)&pA, g_A);
    __nv_bfloat16 *xh, *xl, *wqh, *wql, *wkh, *wkl, *wvh, *wvl, *woh, *wol;
    cudaGetSymbolAddress((void**)&xh, g_xh);
    cudaGetSymbolAddress((void**)&xl, g_xl);
    cudaGetSymbolAddress((void**)&wqh, g_Wqh);
    cudaGetSymbolAddress((void**)&wql, g_Wql);
    cudaGetSymbolAddress((void**)&wkh, g_Wkh);
    cudaGetSymbolAddress((void**)&wkl, g_Wkl);
    cudaGetSymbolAddress((void**)&wvh, g_Wvh);
    cudaGetSymbolAddress((void**)&wvl, g_Wvl);
    cudaGetSymbolAddress((void**)&woh, g_Woh);
    cudaGetSymbolAddress((void**)&wol, g_Wol);

    rope_tables_kernel<<<(SEQ * HALF + 255) / 256, 256>>>();

    // split x, transpose+split weights
    split_f32<<<(SEQ * DM + 255) / 256, 256>>>(x, xh, xl, SEQ * DM);
    dim3 tgrid(DM / 32, DM / 32), tblk(32, 8);
    transpose_split<<<tgrid, tblk>>>(Wq, wqh, wql);
    transpose_split<<<tgrid, tblk>>>(Wk, wkh, wkl);
    transpose_split<<<tgrid, tblk>>>(Wv, wvh, wvl);
    transpose_split<<<tgrid, tblk>>>(Wo, woh, wol);

    // HMMA GEMMs: Q/K/V projections
    dim3 ggrid(DM / 128, SEQ / 128);  // 16 x 16
    gemm_mma<<<ggrid, 256>>>(xh, xl, wqh, wql, pQ);
    gemm_mma<<<ggrid, 256>>>(xh, xl, wkh, wkl, pK);
    gemm_mma<<<ggrid, 256>>>(xh, xl, wvh, wvl, pV);

    rope_apply_kernel<<<(SEQ * NH * HALF) / 256, 256>>>();

    size_t fsmem = (size_t)(BQ * QST + BK * DH + BK * DH + BQ * BK + 3 * BQ) * sizeof(float);
    cudaFuncSetAttribute(flash_kernel, cudaFuncAttributeMaxDynamicSharedMemorySize, (int)fsmem);
    flash_kernel<<<dim3(SEQ / BQ, NH), 256, fsmem>>>(pQ, pK, pV, pA);

    // output projection: split attn output, reuse xh/xl scratch
    split_f32<<<(SEQ * DM + 255) / 256, 256>>>(pA, xh, xl, SEQ * DM);
    gemm_mma<<<ggrid, 256>>>(xh, xl, woh, wol, out);
}

// round 5
// speedup vs baseline: 2.6084x; 1.7849x over previous
#include <cuda_runtime.h>
#include <cuda_bf16.h>
#include <math.h>
#include <stdint.h>

#define SEQ 2048
#define DM  2048
#define NH  16
#define DH  128
#define HALF 64

// ---------------- scratch (device globals; allocation-free) ----------------
__device__ float g_Q[SEQ * DM];
__device__ float g_K[SEQ * DM];
__device__ float g_V[SEQ * DM];
__device__ float g_cos[SEQ * HALF];
__device__ float g_sin[SEQ * HALF];
// bf16 split operands
__device__ __nv_bfloat16 g_xh[SEQ * DM];
__device__ __nv_bfloat16 g_xl[SEQ * DM];
__device__ __nv_bfloat16 g_Wqh[DM * DM];
__device__ __nv_bfloat16 g_Wql[DM * DM];
__device__ __nv_bfloat16 g_Wkh[DM * DM];
__device__ __nv_bfloat16 g_Wkl[DM * DM];
__device__ __nv_bfloat16 g_Wvh[DM * DM];
__device__ __nv_bfloat16 g_Wvl[DM * DM];
__device__ __nv_bfloat16 g_Woh[DM * DM];
__device__ __nv_bfloat16 g_Wol[DM * DM];
// flash operands (bf16 splits)
__device__ __nv_bfloat16 g_Qh[SEQ * DM];
__device__ __nv_bfloat16 g_Ql[SEQ * DM];
__device__ __nv_bfloat16 g_Kh[SEQ * DM];
__device__ __nv_bfloat16 g_Kl[SEQ * DM];
__device__ __nv_bfloat16 g_Vth[DM * SEQ];   // V transposed: [col][seq]
__device__ __nv_bfloat16 g_Vtl[DM * SEQ];

// ---------------- small helpers ----------------
__device__ __forceinline__ float ex2f(float x) {
    float y;
    asm("ex2.approx.ftz.f32 %0, %1;" : "=f"(y) : "f"(x));
    return y;
}
__device__ __forceinline__ uint32_t pack2(__nv_bfloat16 lo, __nv_bfloat16 hi) {
    __nv_bfloat162 v(lo, hi);   // .x = lo (lower 16 bits)
    return *(uint32_t*)&v;
}
__device__ __forceinline__ void mma16816(float c[4], const uint32_t a[4], const uint32_t b[2]) {
    asm volatile(
        "mma.sync.aligned.m16n8k16.row.col.f32.bf16.bf16.f32 "
        "{%0,%1,%2,%3}, {%4,%5,%6,%7}, {%8,%9}, {%0,%1,%2,%3};"
        : "+f"(c[0]), "+f"(c[1]), "+f"(c[2]), "+f"(c[3])
        : "r"(a[0]), "r"(a[1]), "r"(a[2]), "r"(a[3]), "r"(b[0]), "r"(b[1]));
}

// ---------------- prep kernels ----------------
__global__ void rope_tables_kernel() {
    int idx = blockIdx.x * blockDim.x + threadIdx.x;
    if (idx >= SEQ * HALF) return;
    int s = idx / HALF;
    int j = idx % HALF;
    double inv = 0.61803398874989484820 / pow(10000.0, (double)j / 64.0);
    double ang = (double)s * inv;
    double si, co;
    sincos(ang, &si, &co);
    g_cos[idx] = (float)co;
    g_sin[idx] = (float)si;
}

// RoPE on fp32 Q,K -> writes bf16 hi/lo splits directly
__global__ void rope_apply_split() {
    int idx = blockIdx.x * blockDim.x + threadIdx.x;
    if (idx >= SEQ * NH * HALF) return;
    int s   = idx / (NH * HALF);
    int rem = idx % (NH * HALF);
    int h   = rem / HALF;
    int j   = rem % HALF;
    int base = s * DM + h * DH + j;
    float c  = g_cos[s * HALF + j];
    float sn = g_sin[s * HALF + j];

    float q1 = g_Q[base], q2 = g_Q[base + HALF];
    float qa = q1 * c - q2 * sn;
    float qb = q1 * sn + q2 * c;
    __nv_bfloat16 ha = __float2bfloat16(qa), hb = __float2bfloat16(qb);
    g_Qh[base] = ha;        g_Ql[base] = __float2bfloat16(qa - __bfloat162float(ha));
    g_Qh[base + HALF] = hb; g_Ql[base + HALF] = __float2bfloat16(qb - __bfloat162float(hb));

    float k1 = g_K[base], k2 = g_K[base + HALF];
    float ka = k1 * c - k2 * sn;
    float kb = k1 * sn + k2 * c;
    __nv_bfloat16 hc = __float2bfloat16(ka), hd = __float2bfloat16(kb);
    g_Kh[base] = hc;        g_Kl[base] = __float2bfloat16(ka - __bfloat162float(hc));
    g_Kh[base + HALF] = hd; g_Kl[base + HALF] = __float2bfloat16(kb - __bfloat162float(hd));
}

// fp32 -> (hi, lo) bf16 split, elementwise
__global__ void split_f32(const float* __restrict__ s, __nv_bfloat16* __restrict__ h,
                          __nv_bfloat16* __restrict__ l, int n) {
    int i = blockIdx.x * blockDim.x + threadIdx.x;
    if (i >= n) return;
    float x = s[i];
    __nv_bfloat16 hh = __float2bfloat16(x);
    h[i] = hh;
    l[i] = __float2bfloat16(x - __bfloat162float(hh));
}

// generic 2048x2048 transpose + split: T[c][s] = M[s][c]
__global__ void transpose_split(const float* __restrict__ W, __nv_bfloat16* __restrict__ Th,
                                __nv_bfloat16* __restrict__ Tl) {
    __shared__ float tile[32][33];
    int bx = blockIdx.x * 32;
    int by = blockIdx.y * 32;
    int tx = threadIdx.x, ty = threadIdx.y;  // 32 x 8
    #pragma unroll
    for (int i = 0; i < 32; i += 8)
        tile[ty + i][tx] = W[(size_t)(by + ty + i) * DM + bx + tx];
    __syncthreads();
    #pragma unroll
    for (int i = 0; i < 32; i += 8) {
        float x = tile[tx][ty + i];
        __nv_bfloat16 hh = __float2bfloat16(x);
        size_t o = (size_t)(bx + ty + i) * DM + by + tx;
        Th[o] = hh;
        Tl[o] = __float2bfloat16(x - __bfloat162float(hh));
    }
}

// V [s][c] -> Vt [c][s] with split (output row length SEQ)
__global__ void v_transpose_split(const float* __restrict__ V, __nv_bfloat16* __restrict__ Th,
                                  __nv_bfloat16* __restrict__ Tl) {
    __shared__ float tile[32][33];
    int bx = blockIdx.x * 32;   // c
    int by = blockIdx.y * 32;   // s
    int tx = threadIdx.x, ty = threadIdx.y;
    #pragma unroll
    for (int i = 0; i < 32; i += 8)
        tile[ty + i][tx] = V[(size_t)(by + ty + i) * DM + bx + tx];
    __syncthreads();
    #pragma unroll
    for (int i = 0; i < 32; i += 8) {
        float x = tile[tx][ty + i];
        __nv_bfloat16 hh = __float2bfloat16(x);
        size_t o = (size_t)(bx + ty + i) * SEQ + by + tx;
        Th[o] = hh;
        Tl[o] = __float2bfloat16(x - __bfloat162float(hh));
    }
}

// ---------------------------------------------------------------------------
// Split-bf16 GEMM via mma.sync (from R4, passing).
// ---------------------------------------------------------------------------
#define AST 72

__global__ void __launch_bounds__(256, 2) gemm_mma(
    const __nv_bfloat16* __restrict__ Ah, const __nv_bfloat16* __restrict__ Al,
    const __nv_bfloat16* __restrict__ Bh, const __nv_bfloat16* __restrict__ Bl,
    float* __restrict__ C) {
    __shared__ __nv_bfloat16 As[128 * AST];
    __shared__ __nv_bfloat16 Bs[128 * AST];

    int t    = threadIdx.x;
    int wid  = t >> 5;
    int lane = t & 31;
    int wm   = (wid & 1) * 64;
    int wn   = (wid >> 1) * 32;
    int g    = lane >> 2;
    int q    = lane & 3;

    int m0 = blockIdx.y * 128;
    int n0 = blockIdx.x * 128;

    int lr = t >> 3;
    int lc = t & 7;

    float acc[4][4][4];
    #pragma unroll
    for (int mt = 0; mt < 4; mt++)
        #pragma unroll
        for (int nt = 0; nt < 4; nt++)
            #pragma unroll
            for (int e = 0; e < 4; e++) acc[mt][nt][e] = 0.f;

    const __nv_bfloat16* APASS[3] = {Ah, Ah, Al};
    const __nv_bfloat16* BPASS[3] = {Bh, Bl, Bh};

    for (int pass = 0; pass < 3; pass++) {
        const __nv_bfloat16* Ag = APASS[pass];
        const __nv_bfloat16* Bg = BPASS[pass];
        for (int s = 0; s < 32; s++) {
            int k0 = s * 64;
            uint4 av[4], bv[4];
            #pragma unroll
            for (int i = 0; i < 4; i++) {
                int r = lr + i * 32;
                av[i] = *(const uint4*)(Ag + (size_t)(m0 + r) * DM + k0 + lc * 8);
                bv[i] = *(const uint4*)(Bg + (size_t)(n0 + r) * DM + k0 + lc * 8);
            }
            __syncthreads();
            #pragma unroll
            for (int i = 0; i < 4; i++) {
                int r = lr + i * 32;
                *(uint4*)(As + r * AST + lc * 8) = av[i];
                *(uint4*)(Bs + r * AST + lc * 8) = bv[i];
            }
            __syncthreads();

            #pragma unroll
            for (int kk = 0; kk < 64; kk += 16) {
                uint32_t a[4][4], b[4][2];
                #pragma unroll
                for (int mt = 0; mt < 4; mt++) {
                    const __nv_bfloat16* p = As + (wm + mt * 16 + g) * AST + kk + q * 2;
                    a[mt][0] = *(const uint32_t*)p;
                    a[mt][1] = *(const uint32_t*)(p + 8 * AST);
                    a[mt][2] = *(const uint32_t*)(p + 8);
                    a[mt][3] = *(const uint32_t*)(p + 8 * AST + 8);
                }
                #pragma unroll
                for (int nt = 0; nt < 4; nt++) {
                    const __nv_bfloat16* p = Bs + (wn + nt * 8 + g) * AST + kk + q * 2;
                    b[nt][0] = *(const uint32_t*)p;
                    b[nt][1] = *(const uint32_t*)(p + 8);
                }
                #pragma unroll
                for (int mt = 0; mt < 4; mt++)
                    #pragma unroll
                    for (int nt = 0; nt < 4; nt++)
                        mma16816(acc[mt][nt], a[mt], b[nt]);
            }
        }
    }

    #pragma unroll
    for (int mt = 0; mt < 4; mt++) {
        int row = m0 + wm + mt * 16 + g;
        #pragma unroll
        for (int nt = 0; nt < 4; nt++) {
            int col = n0 + wn + nt * 8 + q * 2;
            *(float2*)(C + (size_t)row * DM + col)       = make_float2(acc[mt][nt][0], acc[mt][nt][1]);
            *(float2*)(C + (size_t)(row + 8) * DM + col) = make_float2(acc[mt][nt][2], acc[mt][nt][3]);
        }
    }
}

// ---------------------------------------------------------------------------
// Flash attention with split-bf16 mma.sync. CTA = (head, 128-query tile),
// 8 warps x 16 rows. K-tiles of 64. Online softmax in base-2 (MUFU ex2).
// Writes attn output directly as bf16 hi/lo splits (inputs to Wo GEMM).
// ---------------------------------------------------------------------------
#define QKSTR 136   // bf16 row stride for Q/K smem tiles (128 + 8)
#define VSTR  72    // bf16 row stride for Vt smem tiles (64 + 8)

__global__ void __launch_bounds__(256, 1) flash_mma(
    const __nv_bfloat16* __restrict__ Qh_, const __nv_bfloat16* __restrict__ Ql_,
    const __nv_bfloat16* __restrict__ Kh_, const __nv_bfloat16* __restrict__ Kl_,
    const __nv_bfloat16* __restrict__ Vh_, const __nv_bfloat16* __restrict__ Vl_,
    __nv_bfloat16* __restrict__ Oh_, __nv_bfloat16* __restrict__ Ol_) {
    extern __shared__ __nv_bfloat16 sb[];
    __nv_bfloat16* sQh = sb;                    // [128][136]
    __nv_bfloat16* sQl = sQh + 128 * QKSTR;
    __nv_bfloat16* sKh = sQl + 128 * QKSTR;     // [64][136]
    __nv_bfloat16* sKl = sKh + 64 * QKSTR;
    __nv_bfloat16* sVh = sKl + 64 * QKSTR;      // [128][72]
    __nv_bfloat16* sVl = sVh + 128 * VSTR;

    int t = threadIdx.x, wid = t >> 5, lane = t & 31;
    int g = lane >> 2, q = lane & 3;
    int h  = blockIdx.y;
    int qt = (int)gridDim.x - 1 - (int)blockIdx.x;
    int q0 = qt * 128;

    // Load Q tile (hi + lo)
    #pragma unroll
    for (int i = 0; i < 8; i++) {
        int idx = t + i * 256;
        int r = idx >> 4, c = idx & 15;
        *(uint4*)(sQh + r * QKSTR + c * 8) = *(const uint4*)(Qh_ + (size_t)(q0 + r) * DM + h * DH + c * 8);
        *(uint4*)(sQl + r * QKSTR + c * 8) = *(const uint4*)(Ql_ + (size_t)(q0 + r) * DM + h * DH + c * 8);
    }

    float o[16][4];
    #pragma unroll
    for (int nt = 0; nt < 16; nt++)
        #pragma unroll
        for (int e = 0; e < 4; e++) o[nt][e] = 0.f;
    float m0r = -1e30f, m1r = -1e30f, l0r = 0.f, l1r = 0.f;

    const float SC2 = 0.08838834764831845f * 1.4426950408889634f;  // scale * log2(e)
    int nkt = 2 * qt + 2;
    int i0 = q0 + wid * 16 + g;

    for (int kt = 0; kt < nkt; kt++) {
        int k0 = kt * 64;
        __syncthreads();   // previous iter's smem reads done (also orders Q store/read at kt=0)
        #pragma unroll
        for (int i = 0; i < 4; i++) {
            int idx = t + i * 256;
            int rk = idx >> 4, ck = idx & 15;
            *(uint4*)(sKh + rk * QKSTR + ck * 8) = *(const uint4*)(Kh_ + (size_t)(k0 + rk) * DM + h * DH + ck * 8);
            *(uint4*)(sKl + rk * QKSTR + ck * 8) = *(const uint4*)(Kl_ + (size_t)(k0 + rk) * DM + h * DH + ck * 8);
            int rv = idx >> 3, cv = idx & 7;
            *(uint4*)(sVh + rv * VSTR + cv * 8) = *(const uint4*)(Vh_ + (size_t)(h * DH + rv) * SEQ + k0 + cv * 8);
            *(uint4*)(sVl + rv * VSTR + cv * 8) = *(const uint4*)(Vl_ + (size_t)(h * DH + rv) * SEQ + k0 + cv * 8);
        }
        __syncthreads();

        // ---- S = Q K^T (3-pass split) ----
        float s[8][4];
        #pragma unroll
        for (int nt = 0; nt < 8; nt++)
            #pragma unroll
            for (int e = 0; e < 4; e++) s[nt][e] = 0.f;

        #pragma unroll
        for (int pass = 0; pass < 3; pass++) {
            const __nv_bfloat16* Aq = (pass == 2) ? sQl : sQh;
            const __nv_bfloat16* Bk = (pass == 1) ? sKl : sKh;
            #pragma unroll
            for (int kc = 0; kc < 8; kc++) {
                uint32_t a[4];
                const __nv_bfloat16* ap = Aq + (wid * 16 + g) * QKSTR + kc * 16 + q * 2;
                a[0] = *(const uint32_t*)ap;
                a[1] = *(const uint32_t*)(ap + 8 * QKSTR);
                a[2] = *(const uint32_t*)(ap + 8);
                a[3] = *(const uint32_t*)(ap + 8 * QKSTR + 8);
                #pragma unroll
                for (int nt = 0; nt < 8; nt++) {
                    uint32_t b[2];
                    const __nv_bfloat16* bp = Bk + (nt * 8 + g) * QKSTR + kc * 16 + q * 2;
                    b[0] = *(const uint32_t*)bp;
                    b[1] = *(const uint32_t*)(bp + 8);
                    mma16816(s[nt], a, b);
                }
            }
        }

        // ---- scale + causal mask ----
        bool diag = (kt >= nkt - 2);
        #pragma unroll
        for (int nt = 0; nt < 8; nt++) {
            int j0 = k0 + nt * 8 + q * 2;
            #pragma unroll
            for (int e = 0; e < 4; e++) {
                float v = s[nt][e] * SC2;
                if (diag) {
                    int i = i0 + ((e >= 2) ? 8 : 0);
                    int j = j0 + (e & 1);
                    if (j > i) v = -1e30f;
                }
                s[nt][e] = v;
            }
        }

        // ---- online softmax stats ----
        float mt0 = -1e30f, mt1 = -1e30f;
        #pragma unroll
        for (int nt = 0; nt < 8; nt++) {
            mt0 = fmaxf(mt0, fmaxf(s[nt][0], s[nt][1]));
            mt1 = fmaxf(mt1, fmaxf(s[nt][2], s[nt][3]));
        }
        mt0 = fmaxf(mt0, __shfl_xor_sync(0xffffffffu, mt0, 1));
        mt0 = fmaxf(mt0, __shfl_xor_sync(0xffffffffu, mt0, 2));
        mt1 = fmaxf(mt1, __shfl_xor_sync(0xffffffffu, mt1, 1));
        mt1 = fmaxf(mt1, __shfl_xor_sync(0xffffffffu, mt1, 2));
        float mn0 = fmaxf(m0r, mt0), mn1 = fmaxf(m1r, mt1);
        float al0 = ex2f(m0r - mn0), al1 = ex2f(m1r - mn1);
        m0r = mn0; m1r = mn1;

        float sum0 = 0.f, sum1 = 0.f;
        #pragma unroll
        for (int nt = 0; nt < 8; nt++) {
            s[nt][0] = ex2f(s[nt][0] - mn0);
            s[nt][1] = ex2f(s[nt][1] - mn0);
            s[nt][2] = ex2f(s[nt][2] - mn1);
            s[nt][3] = ex2f(s[nt][3] - mn1);
            sum0 += s[nt][0] + s[nt][1];
            sum1 += s[nt][2] + s[nt][3];
        }
        sum0 += __shfl_xor_sync(0xffffffffu, sum0, 1);
        sum0 += __shfl_xor_sync(0xffffffffu, sum0, 2);
        sum1 += __shfl_xor_sync(0xffffffffu, sum1, 1);
        sum1 += __shfl_xor_sync(0xffffffffu, sum1, 2);
        l0r = l0r * al0 + sum0;
        l1r = l1r * al1 + sum1;

        // rescale O
        #pragma unroll
        for (int nt = 0; nt < 16; nt++) {
            o[nt][0] *= al0; o[nt][1] *= al0;
            o[nt][2] *= al1; o[nt][3] *= al1;
        }

        // ---- pack P into bf16 hi/lo A-fragments (pure register repack) ----
        uint32_t Ph0[8], Ph1[8], Pl0[8], Pl1[8];
        #pragma unroll
        for (int nt = 0; nt < 8; nt++) {
            float p0 = s[nt][0], p1 = s[nt][1], p2 = s[nt][2], p3 = s[nt][3];
            __nv_bfloat16 b0 = __float2bfloat16(p0), b1 = __float2bfloat16(p1);
            __nv_bfloat16 b2 = __float2bfloat16(p2), b3 = __float2bfloat16(p3);
            Ph0[nt] = pack2(b0, b1);
            Ph1[nt] = pack2(b2, b3);
            Pl0[nt] = pack2(__float2bfloat16(p0 - __bfloat162float(b0)),
                            __float2bfloat16(p1 - __bfloat162float(b1)));
            Pl1[nt] = pack2(__float2bfloat16(p2 - __bfloat162float(b2)),
                            __float2bfloat16(p3 - __bfloat162float(b3)));
        }

        // ---- O += P V (3-pass split) ----
        #pragma unroll
        for (int pass = 0; pass < 3; pass++) {
            const uint32_t* A0 = (pass == 1) ? Pl0 : Ph0;
            const uint32_t* A1 = (pass == 1) ? Pl1 : Ph1;
            const __nv_bfloat16* Bv = (pass == 2) ? sVl : sVh;
            #pragma unroll
            for (int kc = 0; kc < 4; kc++) {
                uint32_t a[4] = {A0[2 * kc], A1[2 * kc], A0[2 * kc + 1], A1[2 * kc + 1]};
                #pragma unroll
                for (int nt = 0; nt < 16; nt++) {
                    uint32_t b[2];
                    const __nv_bfloat16* bp = Bv + (nt * 8 + g) * VSTR + kc * 16 + q * 2;
                    b[0] = *(const uint32_t*)bp;
                    b[1] = *(const uint32_t*)(bp + 8);
                    mma16816(o[nt], a, b);
                }
            }
        }
    }

    // ---- epilogue: normalize, split to bf16 hi/lo, store ----
    float inv0 = 1.f / l0r, inv1 = 1.f / l1r;
    int row0 = q0 + wid * 16 + g;
    #pragma unroll
    for (int nt = 0; nt < 16; nt++) {
        int col = h * DH + nt * 8 + q * 2;
        float f0 = o[nt][0] * inv0, f1 = o[nt][1] * inv0;
        float f2 = o[nt][2] * inv1, f3 = o[nt][3] * inv1;
        __nv_bfloat16 b0 = __float2bfloat16(f0), b1 = __float2bfloat16(f1);
        __nv_bfloat16 b2 = __float2bfloat16(f2), b3 = __float2bfloat16(f3);
        *(uint32_t*)(Oh_ + (size_t)row0 * DM + col)       = pack2(b0, b1);
        *(uint32_t*)(Oh_ + (size_t)(row0 + 8) * DM + col) = pack2(b2, b3);
        *(uint32_t*)(Ol_ + (size_t)row0 * DM + col)       =
            pack2(__float2bfloat16(f0 - __bfloat162float(b0)),
                  __float2bfloat16(f1 - __bfloat162float(b1)));
        *(uint32_t*)(Ol_ + (size_t)(row0 + 8) * DM + col) =
            pack2(__float2bfloat16(f2 - __bfloat162float(b2)),
                  __float2bfloat16(f3 - __bfloat162float(b3)));
    }
}

// ---------------------------------------------------------------------------
extern "C" void kernel_launch(void* const* d_in, const int* in_sizes, int n_in,
                              void* d_out, int out_size) {
    const float* x  = (const float*)d_in[0];
    const float* Wq = (const float*)d_in[1];
    const float* Wk = (const float*)d_in[2];
    const float* Wv = (const float*)d_in[3];
    const float* Wo = (const float*)d_in[4];
    float* out = (float*)d_out;

    float *pQ, *pK, *pV;
    cudaGetSymbolAddress((void**)&pQ, g_Q);
    cudaGetSymbolAddress((void**)&pK, g_K);
    cudaGetSymbolAddress((void**)&pV, g_V);
    __nv_bfloat16 *xh, *xl, *wqh, *wql, *wkh, *wkl, *wvh, *wvl, *woh, *wol;
    __nv_bfloat16 *qh, *ql, *kh, *kl, *vth, *vtl;
    cudaGetSymbolAddress((void**)&xh, g_xh);
    cudaGetSymbolAddress((void**)&xl, g_xl);
    cudaGetSymbolAddress((void**)&wqh, g_Wqh);
    cudaGetSymbolAddress((void**)&wql, g_Wql);
    cudaGetSymbolAddress((void**)&wkh, g_Wkh);
    cudaGetSymbolAddress((void**)&wkl, g_Wkl);
    cudaGetSymbolAddress((void**)&wvh, g_Wvh);
    cudaGetSymbolAddress((void**)&wvl, g_Wvl);
    cudaGetSymbolAddress((void**)&woh, g_Woh);
    cudaGetSymbolAddress((void**)&wol, g_Wol);
    cudaGetSymbolAddress((void**)&qh, g_Qh);
    cudaGetSymbolAddress((void**)&ql, g_Ql);
    cudaGetSymbolAddress((void**)&kh, g_Kh);
    cudaGetSymbolAddress((void**)&kl, g_Kl);
    cudaGetSymbolAddress((void**)&vth, g_Vth);
    cudaGetSymbolAddress((void**)&vtl, g_Vtl);

    rope_tables_kernel<<<(SEQ * HALF + 255) / 256, 256>>>();

    split_f32<<<(SEQ * DM + 255) / 256, 256>>>(x, xh, xl, SEQ * DM);
    dim3 tgrid(DM / 32, DM / 32), tblk(32, 8);
    transpose_split<<<tgrid, tblk>>>(Wq, wqh, wql);
    transpose_split<<<tgrid, tblk>>>(Wk, wkh, wkl);
    transpose_split<<<tgrid, tblk>>>(Wv, wvh, wvl);
    transpose_split<<<tgrid, tblk>>>(Wo, woh, wol);

    dim3 ggrid(DM / 128, SEQ / 128);
    gemm_mma<<<ggrid, 256>>>(xh, xl, wqh, wql, pQ);
    gemm_mma<<<ggrid, 256>>>(xh, xl, wkh, wkl, pK);
    gemm_mma<<<ggrid, 256>>>(xh, xl, wvh, wvl, pV);

    rope_apply_split<<<(SEQ * NH * HALF) / 256, 256>>>();
    v_transpose_split<<<tgrid, tblk>>>(pV, vth, vtl);

    size_t fsmem = (size_t)(2 * 128 * QKSTR + 2 * 64 * QKSTR + 2 * 128 * VSTR) * sizeof(__nv_bfloat16);
    cudaFuncSetAttribute(flash_mma, cudaFuncAttributeMaxDynamicSharedMemorySize, (int)fsmem);
    // flash writes attn output splits directly into xh/xl (free after QKV gemms)
    flash_mma<<<dim3(SEQ / 128, NH), 256, fsmem>>>(qh, ql, kh, kl, vth, vtl, xh, xl);

    gemm_mma<<<ggrid, 256>>>(xh, xl, woh, wol, out);
}

// round 6
// speedup vs baseline: 2.7501x; 1.0543x over previous
#include <cuda_runtime.h>
#include <cuda_bf16.h>
#include <math.h>
#include <stdint.h>

#define SEQ 2048
#define DM  2048
#define NH  16
#define DH  128
#define HALF 64

// ---------------- scratch (device globals; allocation-free) ----------------
__device__ float g_Q[SEQ * DM];
__device__ float g_K[SEQ * DM];
__device__ float g_V[SEQ * DM];
__device__ float g_cos[SEQ * HALF];
__device__ float g_sin[SEQ * HALF];
__device__ __nv_bfloat16 g_xh[SEQ * DM];
__device__ __nv_bfloat16 g_xl[SEQ * DM];
__device__ __nv_bfloat16 g_Wqh[DM * DM];
__device__ __nv_bfloat16 g_Wql[DM * DM];
__device__ __nv_bfloat16 g_Wkh[DM * DM];
__device__ __nv_bfloat16 g_Wkl[DM * DM];
__device__ __nv_bfloat16 g_Wvh[DM * DM];
__device__ __nv_bfloat16 g_Wvl[DM * DM];
__device__ __nv_bfloat16 g_Woh[DM * DM];
__device__ __nv_bfloat16 g_Wol[DM * DM];
__device__ __nv_bfloat16 g_Qh[SEQ * DM];
__device__ __nv_bfloat16 g_Ql[SEQ * DM];
__device__ __nv_bfloat16 g_Kh[SEQ * DM];
__device__ __nv_bfloat16 g_Kl[SEQ * DM];
__device__ __nv_bfloat16 g_Vth[DM * SEQ];
__device__ __nv_bfloat16 g_Vtl[DM * SEQ];

// ---------------- helpers ----------------
__device__ __forceinline__ float ex2f(float x) {
    float y;
    asm("ex2.approx.ftz.f32 %0, %1;" : "=f"(y) : "f"(x));
    return y;
}
__device__ __forceinline__ uint32_t pack2(__nv_bfloat16 lo, __nv_bfloat16 hi) {
    __nv_bfloat162 v(lo, hi);
    return *(uint32_t*)&v;
}
__device__ __forceinline__ void mma16816(float c[4], const uint32_t a[4], const uint32_t b[2]) {
    asm volatile(
        "mma.sync.aligned.m16n8k16.row.col.f32.bf16.bf16.f32 "
        "{%0,%1,%2,%3}, {%4,%5,%6,%7}, {%8,%9}, {%0,%1,%2,%3};"
        : "+f"(c[0]), "+f"(c[1]), "+f"(c[2]), "+f"(c[3])
        : "r"(a[0]), "r"(a[1]), "r"(a[2]), "r"(a[3]), "r"(b[0]), "r"(b[1]));
}
__device__ __forceinline__ void cpa16(void* dst, const void* src) {
    uint32_t d = (uint32_t)__cvta_generic_to_shared(dst);
    asm volatile("cp.async.cg.shared.global [%0], [%1], 16;" :: "r"(d), "l"(src) : "memory");
}
#define CP_COMMIT() asm volatile("cp.async.commit_group;" ::: "memory")
#define CP_WAIT1()  asm volatile("cp.async.wait_group 1;" ::: "memory")
#define CP_WAIT0()  asm volatile("cp.async.wait_group 0;" ::: "memory")

// ---------------- prep kernels ----------------
__global__ void rope_tables_kernel() {
    int idx = blockIdx.x * blockDim.x + threadIdx.x;
    if (idx >= SEQ * HALF) return;
    int s = idx / HALF;
    int j = idx % HALF;
    double inv = 0.61803398874989484820 / pow(10000.0, (double)j / 64.0);
    double ang = (double)s * inv;
    double si, co;
    sincos(ang, &si, &co);
    g_cos[idx] = (float)co;
    g_sin[idx] = (float)si;
}

__global__ void rope_apply_split() {
    int idx = blockIdx.x * blockDim.x + threadIdx.x;
    if (idx >= SEQ * NH * HALF) return;
    int s   = idx / (NH * HALF);
    int rem = idx % (NH * HALF);
    int h   = rem / HALF;
    int j   = rem % HALF;
    int base = s * DM + h * DH + j;
    float c  = g_cos[s * HALF + j];
    float sn = g_sin[s * HALF + j];

    float q1 = g_Q[base], q2 = g_Q[base + HALF];
    float qa = q1 * c - q2 * sn;
    float qb = q1 * sn + q2 * c;
    __nv_bfloat16 ha = __float2bfloat16(qa), hb = __float2bfloat16(qb);
    g_Qh[base] = ha;        g_Ql[base] = __float2bfloat16(qa - __bfloat162float(ha));
    g_Qh[base + HALF] = hb; g_Ql[base + HALF] = __float2bfloat16(qb - __bfloat162float(hb));

    float k1 = g_K[base], k2 = g_K[base + HALF];
    float ka = k1 * c - k2 * sn;
    float kb = k1 * sn + k2 * c;
    __nv_bfloat16 hc = __float2bfloat16(ka), hd = __float2bfloat16(kb);
    g_Kh[base] = hc;        g_Kl[base] = __float2bfloat16(ka - __bfloat162float(hc));
    g_Kh[base + HALF] = hd; g_Kl[base + HALF] = __float2bfloat16(kb - __bfloat162float(hd));
}

__global__ void split_f32(const float* __restrict__ s, __nv_bfloat16* __restrict__ h,
                          __nv_bfloat16* __restrict__ l, int n) {
    int i = blockIdx.x * blockDim.x + threadIdx.x;
    if (i >= n) return;
    float x = s[i];
    __nv_bfloat16 hh = __float2bfloat16(x);
    h[i] = hh;
    l[i] = __float2bfloat16(x - __bfloat162float(hh));
}

__global__ void transpose_split(const float* __restrict__ W, __nv_bfloat16* __restrict__ Th,
                                __nv_bfloat16* __restrict__ Tl) {
    __shared__ float tile[32][33];
    int bx = blockIdx.x * 32;
    int by = blockIdx.y * 32;
    int tx = threadIdx.x, ty = threadIdx.y;
    #pragma unroll
    for (int i = 0; i < 32; i += 8)
        tile[ty + i][tx] = W[(size_t)(by + ty + i) * DM + bx + tx];
    __syncthreads();
    #pragma unroll
    for (int i = 0; i < 32; i += 8) {
        float x = tile[tx][ty + i];
        __nv_bfloat16 hh = __float2bfloat16(x);
        size_t o = (size_t)(bx + ty + i) * DM + by + tx;
        Th[o] = hh;
        Tl[o] = __float2bfloat16(x - __bfloat162float(hh));
    }
}

__global__ void v_transpose_split(const float* __restrict__ V, __nv_bfloat16* __restrict__ Th,
                                  __nv_bfloat16* __restrict__ Tl) {
    __shared__ float tile[32][33];
    int bx = blockIdx.x * 32;
    int by = blockIdx.y * 32;
    int tx = threadIdx.x, ty = threadIdx.y;
    #pragma unroll
    for (int i = 0; i < 32; i += 8)
        tile[ty + i][tx] = V[(size_t)(by + ty + i) * DM + bx + tx];
    __syncthreads();
    #pragma unroll
    for (int i = 0; i < 32; i += 8) {
        float x = tile[tx][ty + i];
        __nv_bfloat16 hh = __float2bfloat16(x);
        size_t o = (size_t)(bx + ty + i) * SEQ + by + tx;
        Th[o] = hh;
        Tl[o] = __float2bfloat16(x - __bfloat162float(hh));
    }
}

// ---------------------------------------------------------------------------
// Split-bf16 GEMM, cp.async double-buffered.
// ---------------------------------------------------------------------------
#define AST 72
#define GBUF (2 * 128 * AST)   // elements per stage buffer (As + Bs)

__global__ void __launch_bounds__(256, 2) gemm_mma(
    const __nv_bfloat16* __restrict__ Ah, const __nv_bfloat16* __restrict__ Al,
    const __nv_bfloat16* __restrict__ Bh, const __nv_bfloat16* __restrict__ Bl,
    float* __restrict__ C) {
    extern __shared__ __nv_bfloat16 dsm[];

    int t    = threadIdx.x;
    int wid  = t >> 5;
    int lane = t & 31;
    int wm   = (wid & 1) * 64;
    int wn   = (wid >> 1) * 32;
    int g    = lane >> 2;
    int q    = lane & 3;
    int m0 = blockIdx.y * 128;
    int n0 = blockIdx.x * 128;
    int lr = t >> 3;
    int lc = t & 7;

    const __nv_bfloat16* APASS[3] = {Ah, Ah, Al};
    const __nv_bfloat16* BPASS[3] = {Bh, Bl, Bh};

    float acc[4][4][4];
    #pragma unroll
    for (int mt = 0; mt < 4; mt++)
        #pragma unroll
        for (int nt = 0; nt < 4; nt++)
            #pragma unroll
            for (int e = 0; e < 4; e++) acc[mt][nt][e] = 0.f;

    // stage loader: stage ss -> buffer ss&1
    auto issue = [&](int ss) {
        int pass = ss >> 5;
        int k0   = (ss & 31) * 64;
        const __nv_bfloat16* Ag = APASS[pass];
        const __nv_bfloat16* Bg = BPASS[pass];
        __nv_bfloat16* As = dsm + (ss & 1) * GBUF;
        __nv_bfloat16* Bs = As + 128 * AST;
        #pragma unroll
        for (int i = 0; i < 4; i++) {
            int r = lr + i * 32;
            cpa16(As + r * AST + lc * 8, Ag + (size_t)(m0 + r) * DM + k0 + lc * 8);
            cpa16(Bs + r * AST + lc * 8, Bg + (size_t)(n0 + r) * DM + k0 + lc * 8);
        }
        CP_COMMIT();
    };

    issue(0);
    for (int ss = 0; ss < 96; ss++) {
        if (ss + 1 < 96) { issue(ss + 1); CP_WAIT1(); }
        else             { CP_WAIT0(); }
        __syncthreads();

        const __nv_bfloat16* As = dsm + (ss & 1) * GBUF;
        const __nv_bfloat16* Bs = As + 128 * AST;
        #pragma unroll
        for (int kk = 0; kk < 64; kk += 16) {
            uint32_t a[4][4], b[4][2];
            #pragma unroll
            for (int mt = 0; mt < 4; mt++) {
                const __nv_bfloat16* p = As + (wm + mt * 16 + g) * AST + kk + q * 2;
                a[mt][0] = *(const uint32_t*)p;
                a[mt][1] = *(const uint32_t*)(p + 8 * AST);
                a[mt][2] = *(const uint32_t*)(p + 8);
                a[mt][3] = *(const uint32_t*)(p + 8 * AST + 8);
            }
            #pragma unroll
            for (int nt = 0; nt < 4; nt++) {
                const __nv_bfloat16* p = Bs + (wn + nt * 8 + g) * AST + kk + q * 2;
                b[nt][0] = *(const uint32_t*)p;
                b[nt][1] = *(const uint32_t*)(p + 8);
            }
            #pragma unroll
            for (int mt = 0; mt < 4; mt++)
                #pragma unroll
                for (int nt = 0; nt < 4; nt++)
                    mma16816(acc[mt][nt], a[mt], b[nt]);
        }
        __syncthreads();
    }

    #pragma unroll
    for (int mt = 0; mt < 4; mt++) {
        int row = m0 + wm + mt * 16 + g;
        #pragma unroll
        for (int nt = 0; nt < 4; nt++) {
            int col = n0 + wn + nt * 8 + q * 2;
            *(float2*)(C + (size_t)row * DM + col)       = make_float2(acc[mt][nt][0], acc[mt][nt][1]);
            *(float2*)(C + (size_t)(row + 8) * DM + col) = make_float2(acc[mt][nt][2], acc[mt][nt][3]);
        }
    }
}

// ---------------------------------------------------------------------------
// Flash attention, split-bf16 mma, cp.async double-buffered K/V.
// ---------------------------------------------------------------------------
#define QKSTR 136
#define VSTR  72
#define QSZ (128 * QKSTR)
#define KSZ (64 * QKSTR)
#define VSZ (128 * VSTR)
#define FBUF (2 * KSZ + 2 * VSZ)

__global__ void __launch_bounds__(256, 1) flash_mma(
    const __nv_bfloat16* __restrict__ Qh_, const __nv_bfloat16* __restrict__ Ql_,
    const __nv_bfloat16* __restrict__ Kh_, const __nv_bfloat16* __restrict__ Kl_,
    const __nv_bfloat16* __restrict__ Vh_, const __nv_bfloat16* __restrict__ Vl_,
    __nv_bfloat16* __restrict__ Oh_, __nv_bfloat16* __restrict__ Ol_) {
    extern __shared__ __nv_bfloat16 sb[];
    __nv_bfloat16* sQh = sb;
    __nv_bfloat16* sQl = sQh + QSZ;

    int t = threadIdx.x, wid = t >> 5, lane = t & 31;
    int g = lane >> 2, q = lane & 3;
    int h  = blockIdx.y;
    int qt = (int)gridDim.x - 1 - (int)blockIdx.x;
    int q0 = qt * 128;

    // Q tile load (one cp.async group)
    #pragma unroll
    for (int i = 0; i < 8; i++) {
        int idx = t + i * 256;
        int r = idx >> 4, c = idx & 15;
        cpa16(sQh + r * QKSTR + c * 8, Qh_ + (size_t)(q0 + r) * DM + h * DH + c * 8);
        cpa16(sQl + r * QKSTR + c * 8, Ql_ + (size_t)(q0 + r) * DM + h * DH + c * 8);
    }
    CP_COMMIT();

    int nkt = 2 * qt + 2;

    // K/V stage loader
    auto issue_kv = [&](int kt) {
        int k0 = kt * 64;
        __nv_bfloat16* base = sb + 2 * QSZ + (kt & 1) * FBUF;
        #pragma unroll
        for (int i = 0; i < 4; i++) {
            int idx = t + i * 256;
            int rk = idx >> 4, ck = idx & 15;
            cpa16(base + rk * QKSTR + ck * 8,       Kh_ + (size_t)(k0 + rk) * DM + h * DH + ck * 8);
            cpa16(base + KSZ + rk * QKSTR + ck * 8, Kl_ + (size_t)(k0 + rk) * DM + h * DH + ck * 8);
            int rv = idx >> 3, cv = idx & 7;
            cpa16(base + 2 * KSZ + rv * VSTR + cv * 8,
                  Vh_ + (size_t)(h * DH + rv) * SEQ + k0 + cv * 8);
            cpa16(base + 2 * KSZ + VSZ + rv * VSTR + cv * 8,
                  Vl_ + (size_t)(h * DH + rv) * SEQ + k0 + cv * 8);
        }
        CP_COMMIT();
    };
    issue_kv(0);

    float o[16][4];
    #pragma unroll
    for (int nt = 0; nt < 16; nt++)
        #pragma unroll
        for (int e = 0; e < 4; e++) o[nt][e] = 0.f;
    float m0r = -1e30f, m1r = -1e30f, l0r = 0.f, l1r = 0.f;

    const float SC2 = 0.08838834764831845f * 1.4426950408889634f;
    int i0 = q0 + wid * 16 + g;

    for (int kt = 0; kt < nkt; kt++) {
        if (kt + 1 < nkt) { issue_kv(kt + 1); CP_WAIT1(); }
        else              { CP_WAIT0(); }
        __syncthreads();

        const __nv_bfloat16* base = sb + 2 * QSZ + (kt & 1) * FBUF;
        const __nv_bfloat16* bKh = base;
        const __nv_bfloat16* bKl = base + KSZ;
        const __nv_bfloat16* bVh = base + 2 * KSZ;
        const __nv_bfloat16* bVl = base + 2 * KSZ + VSZ;
        int k0 = kt * 64;

        // ---- S = Q K^T (3-pass split) ----
        float s[8][4];
        #pragma unroll
        for (int nt = 0; nt < 8; nt++)
            #pragma unroll
            for (int e = 0; e < 4; e++) s[nt][e] = 0.f;

        #pragma unroll
        for (int pass = 0; pass < 3; pass++) {
            const __nv_bfloat16* Aq = (pass == 2) ? sQl : sQh;
            const __nv_bfloat16* Bk = (pass == 1) ? bKl : bKh;
            #pragma unroll
            for (int kc = 0; kc < 8; kc++) {
                uint32_t a[4];
                const __nv_bfloat16* ap = Aq + (wid * 16 + g) * QKSTR + kc * 16 + q * 2;
                a[0] = *(const uint32_t*)ap;
                a[1] = *(const uint32_t*)(ap + 8 * QKSTR);
                a[2] = *(const uint32_t*)(ap + 8);
                a[3] = *(const uint32_t*)(ap + 8 * QKSTR + 8);
                #pragma unroll
                for (int nt = 0; nt < 8; nt++) {
                    uint32_t b[2];
                    const __nv_bfloat16* bp = Bk + (nt * 8 + g) * QKSTR + kc * 16 + q * 2;
                    b[0] = *(const uint32_t*)bp;
                    b[1] = *(const uint32_t*)(bp + 8);
                    mma16816(s[nt], a, b);
                }
            }
        }

        // ---- scale + causal mask ----
        bool diag = (kt >= nkt - 2);
        #pragma unroll
        for (int nt = 0; nt < 8; nt++) {
            int j0 = k0 + nt * 8 + q * 2;
            #pragma unroll
            for (int e = 0; e < 4; e++) {
                float v = s[nt][e] * SC2;
                if (diag) {
                    int i = i0 + ((e >= 2) ? 8 : 0);
                    int j = j0 + (e & 1);
                    if (j > i) v = -1e30f;
                }
                s[nt][e] = v;
            }
        }

        // ---- online softmax ----
        float mt0 = -1e30f, mt1 = -1e30f;
        #pragma unroll
        for (int nt = 0; nt < 8; nt++) {
            mt0 = fmaxf(mt0, fmaxf(s[nt][0], s[nt][1]));
            mt1 = fmaxf(mt1, fmaxf(s[nt][2], s[nt][3]));
        }
        mt0 = fmaxf(mt0, __shfl_xor_sync(0xffffffffu, mt0, 1));
        mt0 = fmaxf(mt0, __shfl_xor_sync(0xffffffffu, mt0, 2));
        mt1 = fmaxf(mt1, __shfl_xor_sync(0xffffffffu, mt1, 1));
        mt1 = fmaxf(mt1, __shfl_xor_sync(0xffffffffu, mt1, 2));
        float mn0 = fmaxf(m0r, mt0), mn1 = fmaxf(m1r, mt1);
        float al0 = ex2f(m0r - mn0), al1 = ex2f(m1r - mn1);
        m0r = mn0; m1r = mn1;

        float sum0 = 0.f, sum1 = 0.f;
        #pragma unroll
        for (int nt = 0; nt < 8; nt++) {
            s[nt][0] = ex2f(s[nt][0] - mn0);
            s[nt][1] = ex2f(s[nt][1] - mn0);
            s[nt][2] = ex2f(s[nt][2] - mn1);
            s[nt][3] = ex2f(s[nt][3] - mn1);
            sum0 += s[nt][0] + s[nt][1];
            sum1 += s[nt][2] + s[nt][3];
        }
        sum0 += __shfl_xor_sync(0xffffffffu, sum0, 1);
        sum0 += __shfl_xor_sync(0xffffffffu, sum0, 2);
        sum1 += __shfl_xor_sync(0xffffffffu, sum1, 1);
        sum1 += __shfl_xor_sync(0xffffffffu, sum1, 2);
        l0r = l0r * al0 + sum0;
        l1r = l1r * al1 + sum1;

        #pragma unroll
        for (int nt = 0; nt < 16; nt++) {
            o[nt][0] *= al0; o[nt][1] *= al0;
            o[nt][2] *= al1; o[nt][3] *= al1;
        }

        // ---- pack P (hi/lo split) ----
        uint32_t Ph0[8], Ph1[8], Pl0[8], Pl1[8];
        #pragma unroll
        for (int nt = 0; nt < 8; nt++) {
            float p0 = s[nt][0], p1 = s[nt][1], p2 = s[nt][2], p3 = s[nt][3];
            __nv_bfloat16 b0 = __float2bfloat16(p0), b1 = __float2bfloat16(p1);
            __nv_bfloat16 b2 = __float2bfloat16(p2), b3 = __float2bfloat16(p3);
            Ph0[nt] = pack2(b0, b1);
            Ph1[nt] = pack2(b2, b3);
            Pl0[nt] = pack2(__float2bfloat16(p0 - __bfloat162float(b0)),
                            __float2bfloat16(p1 - __bfloat162float(b1)));
            Pl1[nt] = pack2(__float2bfloat16(p2 - __bfloat162float(b2)),
                            __float2bfloat16(p3 - __bfloat162float(b3)));
        }

        // ---- O += P V (3-pass split) ----
        #pragma unroll
        for (int pass = 0; pass < 3; pass++) {
            const uint32_t* A0 = (pass == 1) ? Pl0 : Ph0;
            const uint32_t* A1 = (pass == 1) ? Pl1 : Ph1;
            const __nv_bfloat16* Bv = (pass == 2) ? bVl : bVh;
            #pragma unroll
            for (int kc = 0; kc < 4; kc++) {
                uint32_t a[4] = {A0[2 * kc], A1[2 * kc], A0[2 * kc + 1], A1[2 * kc + 1]};
                #pragma unroll
                for (int nt = 0; nt < 16; nt++) {
                    uint32_t b[2];
                    const __nv_bfloat16* bp = Bv + (nt * 8 + g) * VSTR + kc * 16 + q * 2;
                    b[0] = *(const uint32_t*)bp;
                    b[1] = *(const uint32_t*)(bp + 8);
                    mma16816(o[nt], a, b);
                }
            }
        }
        __syncthreads();
    }

    // ---- epilogue ----
    float inv0 = 1.f / l0r, inv1 = 1.f / l1r;
    int row0 = q0 + wid * 16 + g;
    #pragma unroll
    for (int nt = 0; nt < 16; nt++) {
        int col = h * DH + nt * 8 + q * 2;
        float f0 = o[nt][0] * inv0, f1 = o[nt][1] * inv0;
        float f2 = o[nt][2] * inv1, f3 = o[nt][3] * inv1;
        __nv_bfloat16 b0 = __float2bfloat16(f0), b1 = __float2bfloat16(f1);
        __nv_bfloat16 b2 = __float2bfloat16(f2), b3 = __float2bfloat16(f3);
        *(uint32_t*)(Oh_ + (size_t)row0 * DM + col)       = pack2(b0, b1);
        *(uint32_t*)(Oh_ + (size_t)(row0 + 8) * DM + col) = pack2(b2, b3);
        *(uint32_t*)(Ol_ + (size_t)row0 * DM + col)       =
            pack2(__float2bfloat16(f0 - __bfloat162float(b0)),
                  __float2bfloat16(f1 - __bfloat162float(b1)));
        *(uint32_t*)(Ol_ + (size_t)(row0 + 8) * DM + col) =
            pack2(__float2bfloat16(f2 - __bfloat162float(b2)),
                  __float2bfloat16(f3 - __bfloat162float(b3)));
    }
}

// ---------------------------------------------------------------------------
extern "C" void kernel_launch(void* const* d_in, const int* in_sizes, int n_in,
                              void* d_out, int out_size) {
    const float* x  = (const float*)d_in[0];
    const float* Wq = (const float*)d_in[1];
    const float* Wk = (const float*)d_in[2];
    const float* Wv = (const float*)d_in[3];
    const float* Wo = (const float*)d_in[4];
    float* out = (float*)d_out;

    float *pQ, *pK, *pV;
    cudaGetSymbolAddress((void**)&pQ, g_Q);
    cudaGetSymbolAddress((void**)&pK, g_K);
    cudaGetSymbolAddress((void**)&pV, g_V);
    __nv_bfloat16 *xh, *xl, *wqh, *wql, *wkh, *wkl, *wvh, *wvl, *woh, *wol;
    __nv_bfloat16 *qh, *ql, *kh, *kl, *vth, *vtl;
    cudaGetSymbolAddress((void**)&xh, g_xh);
    cudaGetSymbolAddress((void**)&xl, g_xl);
    cudaGetSymbolAddress((void**)&wqh, g_Wqh);
    cudaGetSymbolAddress((void**)&wql, g_Wql);
    cudaGetSymbolAddress((void**)&wkh, g_Wkh);
    cudaGetSymbolAddress((void**)&wkl, g_Wkl);
    cudaGetSymbolAddress((void**)&wvh, g_Wvh);
    cudaGetSymbolAddress((void**)&wvl, g_Wvl);
    cudaGetSymbolAddress((void**)&woh, g_Woh);
    cudaGetSymbolAddress((void**)&wol, g_Wol);
    cudaGetSymbolAddress((void**)&qh, g_Qh);
    cudaGetSymbolAddress((void**)&ql, g_Ql);
    cudaGetSymbolAddress((void**)&kh, g_Kh);
    cudaGetSymbolAddress((void**)&kl, g_Kl);
    cudaGetSymbolAddress((void**)&vth, g_Vth);
    cudaGetSymbolAddress((void**)&vtl, g_Vtl);

    rope_tables_kernel<<<(SEQ * HALF + 255) / 256, 256>>>();

    split_f32<<<(SEQ * DM + 255) / 256, 256>>>(x, xh, xl, SEQ * DM);
    dim3 tgrid(DM / 32, DM / 32), tblk(32, 8);
    transpose_split<<<tgrid, tblk>>>(Wq, wqh, wql);
    transpose_split<<<tgrid, tblk>>>(Wk, wkh, wkl);
    transpose_split<<<tgrid, tblk>>>(Wv, wvh, wvl);
    transpose_split<<<tgrid, tblk>>>(Wo, woh, wol);

    size_t gsmem = (size_t)(2 * GBUF) * sizeof(__nv_bfloat16);   // 73728
    cudaFuncSetAttribute(gemm_mma, cudaFuncAttributeMaxDynamicSharedMemorySize, (int)gsmem);
    dim3 ggrid(DM / 128, SEQ / 128);
    gemm_mma<<<ggrid, 256, gsmem>>>(xh, xl, wqh, wql, pQ);
    gemm_mma<<<ggrid, 256, gsmem>>>(xh, xl, wkh, wkl, pK);
    gemm_mma<<<ggrid, 256, gsmem>>>(xh, xl, wvh, wvl, pV);

    rope_apply_split<<<(SEQ * NH * HALF) / 256, 256>>>();
    v_transpose_split<<<tgrid, tblk>>>(pV, vth, vtl);

    size_t fsmem = (size_t)(2 * QSZ + 2 * FBUF) * sizeof(__nv_bfloat16);  // 212992
    cudaFuncSetAttribute(flash_mma, cudaFuncAttributeMaxDynamicSharedMemorySize, (int)fsmem);
    flash_mma<<<dim3(SEQ / 128, NH), 256, fsmem>>>(qh, ql, kh, kl, vth, vtl, xh, xl);

    gemm_mma<<<ggrid, 256, gsmem>>>(xh, xl, woh, wol, out);
}

// round 7
// speedup vs baseline: 2.7555x; 1.0019x over previous
#include <cuda_runtime.h>
#include <cuda_bf16.h>
#include <math.h>
#include <stdint.h>

#define SEQ 2048
#define DM  2048
#define NH  16
#define DH  128
#define HALF 64

// ---------------- scratch (device globals; allocation-free) ----------------
__device__ float g_Q[SEQ * DM];
__device__ float g_K[SEQ * DM];
__device__ float g_V[SEQ * DM];
__device__ float g_cos[SEQ * HALF];
__device__ float g_sin[SEQ * HALF];
__device__ __nv_bfloat16 g_xh[SEQ * DM];
__device__ __nv_bfloat16 g_xl[SEQ * DM];
__device__ __nv_bfloat16 g_Wqh[DM * DM];
__device__ __nv_bfloat16 g_Wql[DM * DM];
__device__ __nv_bfloat16 g_Wkh[DM * DM];
__device__ __nv_bfloat16 g_Wkl[DM * DM];
__device__ __nv_bfloat16 g_Wvh[DM * DM];
__device__ __nv_bfloat16 g_Wvl[DM * DM];
__device__ __nv_bfloat16 g_Woh[DM * DM];
__device__ __nv_bfloat16 g_Wol[DM * DM];
__device__ __nv_bfloat16 g_Qh[SEQ * DM];
__device__ __nv_bfloat16 g_Ql[SEQ * DM];
__device__ __nv_bfloat16 g_Kh[SEQ * DM];
__device__ __nv_bfloat16 g_Kl[SEQ * DM];
__device__ __nv_bfloat16 g_Vth[DM * SEQ];
__device__ __nv_bfloat16 g_Vtl[DM * SEQ];

// ---------------- helpers ----------------
__device__ __forceinline__ float ex2f(float x) {
    float y;
    asm("ex2.approx.ftz.f32 %0, %1;" : "=f"(y) : "f"(x));
    return y;
}
__device__ __forceinline__ uint32_t pack2(__nv_bfloat16 lo, __nv_bfloat16 hi) {
    __nv_bfloat162 v(lo, hi);
    return *(uint32_t*)&v;
}
__device__ __forceinline__ void mma16816(float c[4], const uint32_t a[4], const uint32_t b[2]) {
    asm volatile(
        "mma.sync.aligned.m16n8k16.row.col.f32.bf16.bf16.f32 "
        "{%0,%1,%2,%3}, {%4,%5,%6,%7}, {%8,%9}, {%0,%1,%2,%3};"
        : "+f"(c[0]), "+f"(c[1]), "+f"(c[2]), "+f"(c[3])
        : "r"(a[0]), "r"(a[1]), "r"(a[2]), "r"(a[3]), "r"(b[0]), "r"(b[1]));
}
__device__ __forceinline__ void ldsm4(uint32_t r[4], uint32_t addr) {
    asm volatile("ldmatrix.sync.aligned.m8n8.x4.shared.b16 {%0,%1,%2,%3}, [%4];"
        : "=r"(r[0]), "=r"(r[1]), "=r"(r[2]), "=r"(r[3]) : "r"(addr));
}
__device__ __forceinline__ void cpa16(void* dst, const void* src) {
    uint32_t d = (uint32_t)__cvta_generic_to_shared(dst);
    asm volatile("cp.async.cg.shared.global [%0], [%1], 16;" :: "r"(d), "l"(src) : "memory");
}
#define CP_COMMIT() asm volatile("cp.async.commit_group;" ::: "memory")
#define CP_WAIT1()  asm volatile("cp.async.wait_group 1;" ::: "memory")
#define CP_WAIT0()  asm volatile("cp.async.wait_group 0;" ::: "memory")

// ---------------- prep kernels ----------------
__global__ void rope_tables_kernel() {
    int idx = blockIdx.x * blockDim.x + threadIdx.x;
    if (idx >= SEQ * HALF) return;
    int s = idx / HALF;
    int j = idx % HALF;
    double inv = 0.61803398874989484820 / pow(10000.0, (double)j / 64.0);
    double ang = (double)s * inv;
    double si, co;
    sincos(ang, &si, &co);
    g_cos[idx] = (float)co;
    g_sin[idx] = (float)si;
}

__global__ void rope_apply_split() {
    int idx = blockIdx.x * blockDim.x + threadIdx.x;
    if (idx >= SEQ * NH * HALF) return;
    int s   = idx / (NH * HALF);
    int rem = idx % (NH * HALF);
    int h   = rem / HALF;
    int j   = rem % HALF;
    int base = s * DM + h * DH + j;
    float c  = g_cos[s * HALF + j];
    float sn = g_sin[s * HALF + j];

    float q1 = g_Q[base], q2 = g_Q[base + HALF];
    float qa = q1 * c - q2 * sn;
    float qb = q1 * sn + q2 * c;
    __nv_bfloat16 ha = __float2bfloat16(qa), hb = __float2bfloat16(qb);
    g_Qh[base] = ha;        g_Ql[base] = __float2bfloat16(qa - __bfloat162float(ha));
    g_Qh[base + HALF] = hb; g_Ql[base + HALF] = __float2bfloat16(qb - __bfloat162float(hb));

    float k1 = g_K[base], k2 = g_K[base + HALF];
    float ka = k1 * c - k2 * sn;
    float kb = k1 * sn + k2 * c;
    __nv_bfloat16 hc = __float2bfloat16(ka), hd = __float2bfloat16(kb);
    g_Kh[base] = hc;        g_Kl[base] = __float2bfloat16(ka - __bfloat162float(hc));
    g_Kh[base + HALF] = hd; g_Kl[base + HALF] = __float2bfloat16(kb - __bfloat162float(hd));
}

__global__ void split_f32(const float* __restrict__ s, __nv_bfloat16* __restrict__ h,
                          __nv_bfloat16* __restrict__ l, int n) {
    int i = blockIdx.x * blockDim.x + threadIdx.x;
    if (i >= n) return;
    float x = s[i];
    __nv_bfloat16 hh = __float2bfloat16(x);
    h[i] = hh;
    l[i] = __float2bfloat16(x - __bfloat162float(hh));
}

__global__ void transpose_split(const float* __restrict__ W, __nv_bfloat16* __restrict__ Th,
                                __nv_bfloat16* __restrict__ Tl) {
    __shared__ float tile[32][33];
    int bx = blockIdx.x * 32;
    int by = blockIdx.y * 32;
    int tx = threadIdx.x, ty = threadIdx.y;
    #pragma unroll
    for (int i = 0; i < 32; i += 8)
        tile[ty + i][tx] = W[(size_t)(by + ty + i) * DM + bx + tx];
    __syncthreads();
    #pragma unroll
    for (int i = 0; i < 32; i += 8) {
        float x = tile[tx][ty + i];
        __nv_bfloat16 hh = __float2bfloat16(x);
        size_t o = (size_t)(bx + ty + i) * DM + by + tx;
        Th[o] = hh;
        Tl[o] = __float2bfloat16(x - __bfloat162float(hh));
    }
}

__global__ void v_transpose_split(const float* __restrict__ V, __nv_bfloat16* __restrict__ Th,
                                  __nv_bfloat16* __restrict__ Tl) {
    __shared__ float tile[32][33];
    int bx = blockIdx.x * 32;
    int by = blockIdx.y * 32;
    int tx = threadIdx.x, ty = threadIdx.y;
    #pragma unroll
    for (int i = 0; i < 32; i += 8)
        tile[ty + i][tx] = V[(size_t)(by + ty + i) * DM + bx + tx];
    __syncthreads();
    #pragma unroll
    for (int i = 0; i < 32; i += 8) {
        float x = tile[tx][ty + i];
        __nv_bfloat16 hh = __float2bfloat16(x);
        size_t o = (size_t)(bx + ty + i) * SEQ + by + tx;
        Th[o] = hh;
        Tl[o] = __float2bfloat16(x - __bfloat162float(hh));
    }
}

// ---------------------------------------------------------------------------
// Split-bf16 GEMM, cp.async double-buffered, ldmatrix fragment loads.
// ---------------------------------------------------------------------------
#define AST 72
#define GBUF (2 * 128 * AST)

__global__ void __launch_bounds__(256, 2) gemm_mma(
    const __nv_bfloat16* __restrict__ Ah, const __nv_bfloat16* __restrict__ Al,
    const __nv_bfloat16* __restrict__ Bh, const __nv_bfloat16* __restrict__ Bl,
    float* __restrict__ C) {
    extern __shared__ __nv_bfloat16 dsm[];

    int t    = threadIdx.x;
    int wid  = t >> 5;
    int lane = t & 31;
    int wm   = (wid & 1) * 64;
    int wn   = (wid >> 1) * 32;
    int g    = lane >> 2;
    int q    = lane & 3;
    int m0 = blockIdx.y * 128;
    int n0 = blockIdx.x * 128;
    int lr = t >> 3;
    int lc = t & 7;

    // ldmatrix lane->address components
    int a_row = (lane & 7) + ((lane >> 3) & 1) * 8;   // 0..15
    int a_kof = (lane >> 4) * 8;                      // 0 or 8
    int b_row = (lane & 7) + (lane >> 4) * 8;         // 0..15
    int b_kof = ((lane >> 3) & 1) * 8;                // 0 or 8

    const __nv_bfloat16* APASS[3] = {Ah, Ah, Al};
    const __nv_bfloat16* BPASS[3] = {Bh, Bl, Bh};

    float acc[4][4][4];
    #pragma unroll
    for (int mt = 0; mt < 4; mt++)
        #pragma unroll
        for (int nt = 0; nt < 4; nt++)
            #pragma unroll
            for (int e = 0; e < 4; e++) acc[mt][nt][e] = 0.f;

    uint32_t sm0 = (uint32_t)__cvta_generic_to_shared(dsm);

    auto issue = [&](int ss) {
        int pass = ss >> 5;
        int k0   = (ss & 31) * 64;
        const __nv_bfloat16* Ag = APASS[pass];
        const __nv_bfloat16* Bg = BPASS[pass];
        __nv_bfloat16* As = dsm + (ss & 1) * GBUF;
        __nv_bfloat16* Bs = As + 128 * AST;
        #pragma unroll
        for (int i = 0; i < 4; i++) {
            int r = lr + i * 32;
            cpa16(As + r * AST + lc * 8, Ag + (size_t)(m0 + r) * DM + k0 + lc * 8);
            cpa16(Bs + r * AST + lc * 8, Bg + (size_t)(n0 + r) * DM + k0 + lc * 8);
        }
        CP_COMMIT();
    };

    issue(0);
    for (int ss = 0; ss < 96; ss++) {
        if (ss + 1 < 96) { issue(ss + 1); CP_WAIT1(); }
        else             { CP_WAIT0(); }
        __syncthreads();

        uint32_t asb = sm0 + (uint32_t)((ss & 1) * GBUF) * 2;
        uint32_t bsb = asb + 128 * AST * 2;
        uint32_t aaddr = asb + (uint32_t)((wm + a_row) * AST + a_kof) * 2;
        uint32_t baddr = bsb + (uint32_t)((wn + b_row) * AST + b_kof) * 2;

        #pragma unroll
        for (int kk = 0; kk < 64; kk += 16) {
            uint32_t a[4][4], b4[2][4];
            #pragma unroll
            for (int mt = 0; mt < 4; mt++)
                ldsm4(a[mt], aaddr + (uint32_t)(mt * 16 * AST + kk) * 2);
            #pragma unroll
            for (int np = 0; np < 2; np++)
                ldsm4(b4[np], baddr + (uint32_t)(np * 16 * AST + kk) * 2);
            #pragma unroll
            for (int mt = 0; mt < 4; mt++)
                #pragma unroll
                for (int nt = 0; nt < 4; nt++)
                    mma16816(acc[mt][nt], a[mt], &b4[nt >> 1][(nt & 1) * 2]);
        }
        __syncthreads();
    }

    #pragma unroll
    for (int mt = 0; mt < 4; mt++) {
        int row = m0 + wm + mt * 16 + g;
        #pragma unroll
        for (int nt = 0; nt < 4; nt++) {
            int col = n0 + wn + nt * 8 + q * 2;
            *(float2*)(C + (size_t)row * DM + col)       = make_float2(acc[mt][nt][0], acc[mt][nt][1]);
            *(float2*)(C + (size_t)(row + 8) * DM + col) = make_float2(acc[mt][nt][2], acc[mt][nt][3]);
        }
    }
}

// ---------------------------------------------------------------------------
// Flash attention, split-bf16 mma, cp.async double-buffered, ldmatrix loads.
// ---------------------------------------------------------------------------
#define QKSTR 136
#define VSTR  72
#define QSZ (128 * QKSTR)
#define KSZ (64 * QKSTR)
#define VSZ (128 * VSTR)
#define FBUF (2 * KSZ + 2 * VSZ)

__global__ void __launch_bounds__(256, 1) flash_mma(
    const __nv_bfloat16* __restrict__ Qh_, const __nv_bfloat16* __restrict__ Ql_,
    const __nv_bfloat16* __restrict__ Kh_, const __nv_bfloat16* __restrict__ Kl_,
    const __nv_bfloat16* __restrict__ Vh_, const __nv_bfloat16* __restrict__ Vl_,
    __nv_bfloat16* __restrict__ Oh_, __nv_bfloat16* __restrict__ Ol_) {
    extern __shared__ __nv_bfloat16 sb[];
    __nv_bfloat16* sQh = sb;
    __nv_bfloat16* sQl = sQh + QSZ;

    int t = threadIdx.x, wid = t >> 5, lane = t & 31;
    int g = lane >> 2, q = lane & 3;
    int h  = blockIdx.y;
    int qt = (int)gridDim.x - 1 - (int)blockIdx.x;
    int q0 = qt * 128;

    int a_row = (lane & 7) + ((lane >> 3) & 1) * 8;
    int a_kof = (lane >> 4) * 8;
    int b_row = (lane & 7) + (lane >> 4) * 8;
    int b_kof = ((lane >> 3) & 1) * 8;

    uint32_t sb0 = (uint32_t)__cvta_generic_to_shared(sb);

    // Q tile load
    #pragma unroll
    for (int i = 0; i < 8; i++) {
        int idx = t + i * 256;
        int r = idx >> 4, c = idx & 15;
        cpa16(sQh + r * QKSTR + c * 8, Qh_ + (size_t)(q0 + r) * DM + h * DH + c * 8);
        cpa16(sQl + r * QKSTR + c * 8, Ql_ + (size_t)(q0 + r) * DM + h * DH + c * 8);
    }
    CP_COMMIT();

    int nkt = 2 * qt + 2;

    auto issue_kv = [&](int kt) {
        int k0 = kt * 64;
        __nv_bfloat16* base = sb + 2 * QSZ + (kt & 1) * FBUF;
        #pragma unroll
        for (int i = 0; i < 4; i++) {
            int idx = t + i * 256;
            int rk = idx >> 4, ck = idx & 15;
            cpa16(base + rk * QKSTR + ck * 8,       Kh_ + (size_t)(k0 + rk) * DM + h * DH + ck * 8);
            cpa16(base + KSZ + rk * QKSTR + ck * 8, Kl_ + (size_t)(k0 + rk) * DM + h * DH + ck * 8);
            int rv = idx >> 3, cv = idx & 7;
            cpa16(base + 2 * KSZ + rv * VSTR + cv * 8,
                  Vh_ + (size_t)(h * DH + rv) * SEQ + k0 + cv * 8);
            cpa16(base + 2 * KSZ + VSZ + rv * VSTR + cv * 8,
                  Vl_ + (size_t)(h * DH + rv) * SEQ + k0 + cv * 8);
        }
        CP_COMMIT();
    };
    issue_kv(0);

    float o[16][4];
    #pragma unroll
    for (int nt = 0; nt < 16; nt++)
        #pragma unroll
        for (int e = 0; e < 4; e++) o[nt][e] = 0.f;
    float m0r = -1e30f, m1r = -1e30f, l0r = 0.f, l1r = 0.f;

    const float SC2 = 0.08838834764831845f * 1.4426950408889634f;
    int i0 = q0 + wid * 16 + g;

    // ldmatrix base addresses (lane-dependent, buffer-independent parts)
    uint32_t qa_h = sb0 + (uint32_t)(((wid * 16 + a_row) * QKSTR + a_kof) * 2);
    uint32_t qa_l = qa_h + (uint32_t)(QSZ * 2);

    for (int kt = 0; kt < nkt; kt++) {
        if (kt + 1 < nkt) { issue_kv(kt + 1); CP_WAIT1(); }
        else              { CP_WAIT0(); }
        __syncthreads();

        uint32_t kb_h = sb0 + (uint32_t)((2 * QSZ + (kt & 1) * FBUF) * 2)
                      + (uint32_t)((b_row * QKSTR + b_kof) * 2);
        uint32_t kb_l = kb_h + (uint32_t)(KSZ * 2);
        uint32_t vb_h = sb0 + (uint32_t)((2 * QSZ + (kt & 1) * FBUF + 2 * KSZ) * 2)
                      + (uint32_t)((b_row * VSTR + b_kof) * 2);
        uint32_t vb_l = vb_h + (uint32_t)(VSZ * 2);
        int k0 = kt * 64;

        // ---- S = Q K^T (3-pass split) ----
        float s[8][4];
        #pragma unroll
        for (int nt = 0; nt < 8; nt++)
            #pragma unroll
            for (int e = 0; e < 4; e++) s[nt][e] = 0.f;

        #pragma unroll
        for (int pass = 0; pass < 3; pass++) {
            uint32_t qa = (pass == 2) ? qa_l : qa_h;
            uint32_t kb = (pass == 1) ? kb_l : kb_h;
            #pragma unroll
            for (int kc = 0; kc < 8; kc++) {
                uint32_t a[4], b4[4][4];
                ldsm4(a, qa + (uint32_t)(kc * 16 * 2));
                #pragma unroll
                for (int np = 0; np < 4; np++)
                    ldsm4(b4[np], kb + (uint32_t)((np * 16 * QKSTR + kc * 16) * 2));
                #pragma unroll
                for (int nt = 0; nt < 8; nt++)
                    mma16816(s[nt], a, &b4[nt >> 1][(nt & 1) * 2]);
            }
        }

        // ---- scale + causal mask ----
        bool diag = (kt >= nkt - 2);
        #pragma unroll
        for (int nt = 0; nt < 8; nt++) {
            int j0 = k0 + nt * 8 + q * 2;
            #pragma unroll
            for (int e = 0; e < 4; e++) {
                float v = s[nt][e] * SC2;
                if (diag) {
                    int i = i0 + ((e >= 2) ? 8 : 0);
                    int j = j0 + (e & 1);
                    if (j > i) v = -1e30f;
                }
                s[nt][e] = v;
            }
        }

        // ---- online softmax ----
        float mt0 = -1e30f, mt1 = -1e30f;
        #pragma unroll
        for (int nt = 0; nt < 8; nt++) {
            mt0 = fmaxf(mt0, fmaxf(s[nt][0], s[nt][1]));
            mt1 = fmaxf(mt1, fmaxf(s[nt][2], s[nt][3]));
        }
        mt0 = fmaxf(mt0, __shfl_xor_sync(0xffffffffu, mt0, 1));
        mt0 = fmaxf(mt0, __shfl_xor_sync(0xffffffffu, mt0, 2));
        mt1 = fmaxf(mt1, __shfl_xor_sync(0xffffffffu, mt1, 1));
        mt1 = fmaxf(mt1, __shfl_xor_sync(0xffffffffu, mt1, 2));
        float mn0 = fmaxf(m0r, mt0), mn1 = fmaxf(m1r, mt1);
        float al0 = ex2f(m0r - mn0), al1 = ex2f(m1r - mn1);
        m0r = mn0; m1r = mn1;

        float sum0 = 0.f, sum1 = 0.f;
        #pragma unroll
        for (int nt = 0; nt < 8; nt++) {
            s[nt][0] = ex2f(s[nt][0] - mn0);
            s[nt][1] = ex2f(s[nt][1] - mn0);
            s[nt][2] = ex2f(s[nt][2] - mn1);
            s[nt][3] = ex2f(s[nt][3] - mn1);
            sum0 += s[nt][0] + s[nt][1];
            sum1 += s[nt][2] + s[nt][3];
        }
        sum0 += __shfl_xor_sync(0xffffffffu, sum0, 1);
        sum0 += __shfl_xor_sync(0xffffffffu, sum0, 2);
        sum1 += __shfl_xor_sync(0xffffffffu, sum1, 1);
        sum1 += __shfl_xor_sync(0xffffffffu, sum1, 2);
        l0r = l0r * al0 + sum0;
        l1r = l1r * al1 + sum1;

        #pragma unroll
        for (int nt = 0; nt < 16; nt++) {
            o[nt][0] *= al0; o[nt][1] *= al0;
            o[nt][2] *= al1; o[nt][3] *= al1;
        }

        // ---- pack P (hi/lo split) ----
        uint32_t Ph0[8], Ph1[8], Pl0[8], Pl1[8];
        #pragma unroll
        for (int nt = 0; nt < 8; nt++) {
            float p0 = s[nt][0], p1 = s[nt][1], p2 = s[nt][2], p3 = s[nt][3];
            __nv_bfloat16 b0 = __float2bfloat16(p0), b1 = __float2bfloat16(p1);
            __nv_bfloat16 b2 = __float2bfloat16(p2), b3 = __float2bfloat16(p3);
            Ph0[nt] = pack2(b0, b1);
            Ph1[nt] = pack2(b2, b3);
            Pl0[nt] = pack2(__float2bfloat16(p0 - __bfloat162float(b0)),
                            __float2bfloat16(p1 - __bfloat162float(b1)));
            Pl1[nt] = pack2(__float2bfloat16(p2 - __bfloat162float(b2)),
                            __float2bfloat16(p3 - __bfloat162float(b3)));
        }

        // ---- O += P V (3-pass split) ----
        #pragma unroll
        for (int pass = 0; pass < 3; pass++) {
            const uint32_t* A0 = (pass == 1) ? Pl0 : Ph0;
            const uint32_t* A1 = (pass == 1) ? Pl1 : Ph1;
            uint32_t vb = (pass == 2) ? vb_l : vb_h;
            #pragma unroll
            for (int kc = 0; kc < 4; kc++) {
                uint32_t a[4] = {A0[2 * kc], A1[2 * kc], A0[2 * kc + 1], A1[2 * kc + 1]};
                uint32_t b4[8][4];
                #pragma unroll
                for (int np = 0; np < 8; np++)
                    ldsm4(b4[np], vb + (uint32_t)((np * 16 * VSTR + kc * 16) * 2));
                #pragma unroll
                for (int nt = 0; nt < 16; nt++)
                    mma16816(o[nt], a, &b4[nt >> 1][(nt & 1) * 2]);
            }
        }
        __syncthreads();
    }

    // ---- epilogue ----
    float inv0 = 1.f / l0r, inv1 = 1.f / l1r;
    int row0 = q0 + wid * 16 + g;
    #pragma unroll
    for (int nt = 0; nt < 16; nt++) {
        int col = h * DH + nt * 8 + q * 2;
        float f0 = o[nt][0] * inv0, f1 = o[nt][1] * inv0;
        float f2 = o[nt][2] * inv1, f3 = o[nt][3] * inv1;
        __nv_bfloat16 b0 = __float2bfloat16(f0), b1 = __float2bfloat16(f1);
        __nv_bfloat16 b2 = __float2bfloat16(f2), b3 = __float2bfloat16(f3);
        *(uint32_t*)(Oh_ + (size_t)row0 * DM + col)       = pack2(b0, b1);
        *(uint32_t*)(Oh_ + (size_t)(row0 + 8) * DM + col) = pack2(b2, b3);
        *(uint32_t*)(Ol_ + (size_t)row0 * DM + col)       =
            pack2(__float2bfloat16(f0 - __bfloat162float(b0)),
                  __float2bfloat16(f1 - __bfloat162float(b1)));
        *(uint32_t*)(Ol_ + (size_t)(row0 + 8) * DM + col) =
            pack2(__float2bfloat16(f2 - __bfloat162float(b2)),
                  __float2bfloat16(f3 - __bfloat162float(b3)));
    }
}

// ---------------------------------------------------------------------------
extern "C" void kernel_launch(void* const* d_in, const int* in_sizes, int n_in,
                              void* d_out, int out_size) {
    const float* x  = (const float*)d_in[0];
    const float* Wq = (const float*)d_in[1];
    const float* Wk = (const float*)d_in[2];
    const float* Wv = (const float*)d_in[3];
    const float* Wo = (const float*)d_in[4];
    float* out = (float*)d_out;

    float *pQ, *pK, *pV;
    cudaGetSymbolAddress((void**)&pQ, g_Q);
    cudaGetSymbolAddress((void**)&pK, g_K);
    cudaGetSymbolAddress((void**)&pV, g_V);
    __nv_bfloat16 *xh, *xl, *wqh, *wql, *wkh, *wkl, *wvh, *wvl, *woh, *wol;
    __nv_bfloat16 *qh, *ql, *kh, *kl, *vth, *vtl;
    cudaGetSymbolAddress((void**)&xh, g_xh);
    cudaGetSymbolAddress((void**)&xl, g_xl);
    cudaGetSymbolAddress((void**)&wqh, g_Wqh);
    cudaGetSymbolAddress((void**)&wql, g_Wql);
    cudaGetSymbolAddress((void**)&wkh, g_Wkh);
    cudaGetSymbolAddress((void**)&wkl, g_Wkl);
    cudaGetSymbolAddress((void**)&wvh, g_Wvh);
    cudaGetSymbolAddress((void**)&wvl, g_Wvl);
    cudaGetSymbolAddress((void**)&woh, g_Woh);
    cudaGetSymbolAddress((void**)&wol, g_Wol);
    cudaGetSymbolAddress((void**)&qh, g_Qh);
    cudaGetSymbolAddress((void**)&ql, g_Ql);
    cudaGetSymbolAddress((void**)&kh, g_Kh);
    cudaGetSymbolAddress((void**)&kl, g_Kl);
    cudaGetSymbolAddress((void**)&vth, g_Vth);
    cudaGetSymbolAddress((void**)&vtl, g_Vtl);

    rope_tables_kernel<<<(SEQ * HALF + 255) / 256, 256>>>();

    split_f32<<<(SEQ * DM + 255) / 256, 256>>>(x, xh, xl, SEQ * DM);
    dim3 tgrid(DM / 32, DM / 32), tblk(32, 8);
    transpose_split<<<tgrid, tblk>>>(Wq, wqh, wql);
    transpose_split<<<tgrid, tblk>>>(Wk, wkh, wkl);
    transpose_split<<<tgrid, tblk>>>(Wv, wvh, wvl);
    transpose_split<<<tgrid, tblk>>>(Wo, woh, wol);

    size_t gsmem = (size_t)(2 * GBUF) * sizeof(__nv_bfloat16);
    cudaFuncSetAttribute(gemm_mma, cudaFuncAttributeMaxDynamicSharedMemorySize, (int)gsmem);
    dim3 ggrid(DM / 128, SEQ / 128);
    gemm_mma<<<ggrid, 256, gsmem>>>(xh, xl, wqh, wql, pQ);
    gemm_mma<<<ggrid, 256, gsmem>>>(xh, xl, wkh, wkl, pK);
    gemm_mma<<<ggrid, 256, gsmem>>>(xh, xl, wvh, wvl, pV);

    rope_apply_split<<<(SEQ * NH * HALF) / 256, 256>>>();
    v_transpose_split<<<tgrid, tblk>>>(pV, vth, vtl);

    size_t fsmem = (size_t)(2 * QSZ + 2 * FBUF) * sizeof(__nv_bfloat16);
    cudaFuncSetAttribute(flash_mma, cudaFuncAttributeMaxDynamicSharedMemorySize, (int)fsmem);
    flash_mma<<<dim3(SEQ / 128, NH), 256, fsmem>>>(qh, ql, kh, kl, vth, vtl, xh, xl);

    gemm_mma<<<ggrid, 256, gsmem>>>(xh, xl, woh, wol, out);
}

// round 8
// speedup vs baseline: 4.2662x; 1.5483x over previous
#include <cuda_runtime.h>
#include <cuda_fp16.h>
#include <math.h>
#include <stdint.h>

#define SEQ 2048
#define DM  2048
#define NH  16
#define DH  128
#define HALF 64

// ---------------- scratch (device globals; allocation-free) ----------------
__device__ float g_Q[SEQ * DM];
__device__ float g_K[SEQ * DM];
__device__ float g_V[SEQ * DM];
__device__ float g_cos[SEQ * HALF];
__device__ float g_sin[SEQ * HALF];
__device__ __half g_xh[SEQ * DM];
__device__ __half g_xl[SEQ * DM];
__device__ __half g_Wqh[DM * DM];
__device__ __half g_Wkh[DM * DM];
__device__ __half g_Wvh[DM * DM];
__device__ __half g_Woh[DM * DM];
__device__ __half g_Qh[SEQ * DM];
__device__ __half g_Ql[SEQ * DM];
__device__ __half g_Kh[SEQ * DM];
__device__ __half g_Vth[DM * SEQ];   // V transposed hi: [col][seq]

// ---------------- helpers ----------------
__device__ __forceinline__ float ex2f(float x) {
    float y;
    asm("ex2.approx.ftz.f32 %0, %1;" : "=f"(y) : "f"(x));
    return y;
}
__device__ __forceinline__ uint32_t pack2h(__half lo, __half hi) {
    __half2 v; v.x = lo; v.y = hi;
    return *(uint32_t*)&v;
}
__device__ __forceinline__ void mma16816(float c[4], const uint32_t a[4], const uint32_t b[2]) {
    asm volatile(
        "mma.sync.aligned.m16n8k16.row.col.f32.f16.f16.f32 "
        "{%0,%1,%2,%3}, {%4,%5,%6,%7}, {%8,%9}, {%0,%1,%2,%3};"
        : "+f"(c[0]), "+f"(c[1]), "+f"(c[2]), "+f"(c[3])
        : "r"(a[0]), "r"(a[1]), "r"(a[2]), "r"(a[3]), "r"(b[0]), "r"(b[1]));
}
__device__ __forceinline__ void ldsm4(uint32_t r[4], uint32_t addr) {
    asm volatile("ldmatrix.sync.aligned.m8n8.x4.shared.b16 {%0,%1,%2,%3}, [%4];"
        : "=r"(r[0]), "=r"(r[1]), "=r"(r[2]), "=r"(r[3]) : "r"(addr));
}
__device__ __forceinline__ void cpa16(void* dst, const void* src) {
    uint32_t d = (uint32_t)__cvta_generic_to_shared(dst);
    asm volatile("cp.async.cg.shared.global [%0], [%1], 16;" :: "r"(d), "l"(src) : "memory");
}
#define CP_COMMIT() asm volatile("cp.async.commit_group;" ::: "memory")
#define CP_WAIT1()  asm volatile("cp.async.wait_group 1;" ::: "memory")
#define CP_WAIT0()  asm volatile("cp.async.wait_group 0;" ::: "memory")

// ---------------- prep kernels ----------------
__global__ void rope_tables_kernel() {
    int idx = blockIdx.x * blockDim.x + threadIdx.x;
    if (idx >= SEQ * HALF) return;
    int s = idx / HALF;
    int j = idx % HALF;
    double inv = 0.61803398874989484820 / pow(10000.0, (double)j / 64.0);
    double ang = (double)s * inv;
    double si, co;
    sincos(ang, &si, &co);
    g_cos[idx] = (float)co;
    g_sin[idx] = (float)si;
}

// RoPE -> Q hi/lo fp16, K hi fp16 only
__global__ void rope_apply_split() {
    int idx = blockIdx.x * blockDim.x + threadIdx.x;
    if (idx >= SEQ * NH * HALF) return;
    int s   = idx / (NH * HALF);
    int rem = idx % (NH * HALF);
    int h   = rem / HALF;
    int j   = rem % HALF;
    int base = s * DM + h * DH + j;
    float c  = g_cos[s * HALF + j];
    float sn = g_sin[s * HALF + j];

    float q1 = g_Q[base], q2 = g_Q[base + HALF];
    float qa = q1 * c - q2 * sn;
    float qb = q1 * sn + q2 * c;
    __half ha = __float2half(qa), hb = __float2half(qb);
    g_Qh[base] = ha;        g_Ql[base] = __float2half(qa - __half2float(ha));
    g_Qh[base + HALF] = hb; g_Ql[base + HALF] = __float2half(qb - __half2float(hb));

    float k1 = g_K[base], k2 = g_K[base + HALF];
    g_Kh[base]        = __float2half(k1 * c - k2 * sn);
    g_Kh[base + HALF] = __float2half(k1 * sn + k2 * c);
}

__global__ void split_f32(const float* __restrict__ s, __half* __restrict__ h,
                          __half* __restrict__ l, int n) {
    int i = blockIdx.x * blockDim.x + threadIdx.x;
    if (i >= n) return;
    float x = s[i];
    __half hh = __float2half(x);
    h[i] = hh;
    l[i] = __float2half(x - __half2float(hh));
}

// W[K][N] -> Wt hi [N][K] fp16 (transpose, hi only)
__global__ void transpose_split(const float* __restrict__ W, __half* __restrict__ Th) {
    __shared__ float tile[32][33];
    int bx = blockIdx.x * 32;
    int by = blockIdx.y * 32;
    int tx = threadIdx.x, ty = threadIdx.y;
    #pragma unroll
    for (int i = 0; i < 32; i += 8)
        tile[ty + i][tx] = W[(size_t)(by + ty + i) * DM + bx + tx];
    __syncthreads();
    #pragma unroll
    for (int i = 0; i < 32; i += 8)
        Th[(size_t)(bx + ty + i) * DM + by + tx] = __float2half(tile[tx][ty + i]);
}

// V [s][c] -> Vt hi [c][s] fp16
__global__ void v_transpose_split(const float* __restrict__ V, __half* __restrict__ Th) {
    __shared__ float tile[32][33];
    int bx = blockIdx.x * 32;
    int by = blockIdx.y * 32;
    int tx = threadIdx.x, ty = threadIdx.y;
    #pragma unroll
    for (int i = 0; i < 32; i += 8)
        tile[ty + i][tx] = V[(size_t)(by + ty + i) * DM + bx + tx];
    __syncthreads();
    #pragma unroll
    for (int i = 0; i < 32; i += 8)
        Th[(size_t)(bx + ty + i) * SEQ + by + tx] = __float2half(tile[tx][ty + i]);
}

// ---------------------------------------------------------------------------
// 2-pass fp16 split GEMM: C = Ah@Bh^T + Al@Bh^T.
// cp.async double-buffered, ldmatrix fragments. 64 stages.
// ---------------------------------------------------------------------------
#define AST 72
#define GBUF (2 * 128 * AST)

__global__ void __launch_bounds__(256, 2) gemm_mma(
    const __half* __restrict__ Ah, const __half* __restrict__ Al,
    const __half* __restrict__ Bh, float* __restrict__ C) {
    extern __shared__ __half dsm[];

    int t    = threadIdx.x;
    int wid  = t >> 5;
    int lane = t & 31;
    int wm   = (wid & 1) * 64;
    int wn   = (wid >> 1) * 32;
    int g    = lane >> 2;
    int q    = lane & 3;
    int m0 = blockIdx.y * 128;
    int n0 = blockIdx.x * 128;
    int lr = t >> 3;
    int lc = t & 7;

    int a_row = (lane & 7) + ((lane >> 3) & 1) * 8;
    int a_kof = (lane >> 4) * 8;
    int b_row = (lane & 7) + (lane >> 4) * 8;
    int b_kof = ((lane >> 3) & 1) * 8;

    const __half* APASS[2] = {Ah, Al};

    float acc[4][4][4];
    #pragma unroll
    for (int mt = 0; mt < 4; mt++)
        #pragma unroll
        for (int nt = 0; nt < 4; nt++)
            #pragma unroll
            for (int e = 0; e < 4; e++) acc[mt][nt][e] = 0.f;

    uint32_t sm0 = (uint32_t)__cvta_generic_to_shared(dsm);

    auto issue = [&](int ss) {
        int pass = ss >> 5;
        int k0   = (ss & 31) * 64;
        const __half* Ag = APASS[pass];
        __half* As = dsm + (ss & 1) * GBUF;
        __half* Bs = As + 128 * AST;
        #pragma unroll
        for (int i = 0; i < 4; i++) {
            int r = lr + i * 32;
            cpa16(As + r * AST + lc * 8, Ag + (size_t)(m0 + r) * DM + k0 + lc * 8);
            cpa16(Bs + r * AST + lc * 8, Bh + (size_t)(n0 + r) * DM + k0 + lc * 8);
        }
        CP_COMMIT();
    };

    issue(0);
    for (int ss = 0; ss < 64; ss++) {
        if (ss + 1 < 64) { issue(ss + 1); CP_WAIT1(); }
        else             { CP_WAIT0(); }
        __syncthreads();

        uint32_t asb = sm0 + (uint32_t)((ss & 1) * GBUF) * 2;
        uint32_t bsb = asb + 128 * AST * 2;
        uint32_t aaddr = asb + (uint32_t)((wm + a_row) * AST + a_kof) * 2;
        uint32_t baddr = bsb + (uint32_t)((wn + b_row) * AST + b_kof) * 2;

        #pragma unroll
        for (int kk = 0; kk < 64; kk += 16) {
            uint32_t a[4][4], b4[2][4];
            #pragma unroll
            for (int mt = 0; mt < 4; mt++)
                ldsm4(a[mt], aaddr + (uint32_t)(mt * 16 * AST + kk) * 2);
            #pragma unroll
            for (int np = 0; np < 2; np++)
                ldsm4(b4[np], baddr + (uint32_t)(np * 16 * AST + kk) * 2);
            #pragma unroll
            for (int mt = 0; mt < 4; mt++)
                #pragma unroll
                for (int nt = 0; nt < 4; nt++)
                    mma16816(acc[mt][nt], a[mt], &b4[nt >> 1][(nt & 1) * 2]);
        }
        __syncthreads();
    }

    #pragma unroll
    for (int mt = 0; mt < 4; mt++) {
        int row = m0 + wm + mt * 16 + g;
        #pragma unroll
        for (int nt = 0; nt < 4; nt++) {
            int col = n0 + wn + nt * 8 + q * 2;
            *(float2*)(C + (size_t)row * DM + col)       = make_float2(acc[mt][nt][0], acc[mt][nt][1]);
            *(float2*)(C + (size_t)(row + 8) * DM + col) = make_float2(acc[mt][nt][2], acc[mt][nt][3]);
        }
    }
}

// ---------------------------------------------------------------------------
// Flash attention, 2-pass fp16 split: S = Qh Kh^T + Ql Kh^T; O = Ph V + Pl V.
// ---------------------------------------------------------------------------
#define QKSTR 136
#define VSTR  72
#define QSZ (128 * QKSTR)
#define KSZ (64 * QKSTR)
#define VSZ (128 * VSTR)
#define FBUF (KSZ + VSZ)

__global__ void __launch_bounds__(256, 1) flash_mma(
    const __half* __restrict__ Qh_, const __half* __restrict__ Ql_,
    const __half* __restrict__ Kh_, const __half* __restrict__ Vh_,
    __half* __restrict__ Oh_, __half* __restrict__ Ol_) {
    extern __shared__ __half sb[];
    __half* sQh = sb;
    __half* sQl = sQh + QSZ;

    int t = threadIdx.x, wid = t >> 5, lane = t & 31;
    int g = lane >> 2, q = lane & 3;
    int h  = blockIdx.y;
    int qt = (int)gridDim.x - 1 - (int)blockIdx.x;
    int q0 = qt * 128;

    int a_row = (lane & 7) + ((lane >> 3) & 1) * 8;
    int a_kof = (lane >> 4) * 8;
    int b_row = (lane & 7) + (lane >> 4) * 8;
    int b_kof = ((lane >> 3) & 1) * 8;

    uint32_t sb0 = (uint32_t)__cvta_generic_to_shared(sb);

    // Q tile load (hi + lo)
    #pragma unroll
    for (int i = 0; i < 8; i++) {
        int idx = t + i * 256;
        int r = idx >> 4, c = idx & 15;
        cpa16(sQh + r * QKSTR + c * 8, Qh_ + (size_t)(q0 + r) * DM + h * DH + c * 8);
        cpa16(sQl + r * QKSTR + c * 8, Ql_ + (size_t)(q0 + r) * DM + h * DH + c * 8);
    }
    CP_COMMIT();

    int nkt = 2 * qt + 2;

    auto issue_kv = [&](int kt) {
        int k0 = kt * 64;
        __half* base = sb + 2 * QSZ + (kt & 1) * FBUF;
        #pragma unroll
        for (int i = 0; i < 4; i++) {
            int idx = t + i * 256;
            int rk = idx >> 4, ck = idx & 15;
            cpa16(base + rk * QKSTR + ck * 8, Kh_ + (size_t)(k0 + rk) * DM + h * DH + ck * 8);
            int rv = idx >> 3, cv = idx & 7;
            cpa16(base + KSZ + rv * VSTR + cv * 8,
                  Vh_ + (size_t)(h * DH + rv) * SEQ + k0 + cv * 8);
        }
        CP_COMMIT();
    };
    issue_kv(0);

    float o[16][4];
    #pragma unroll
    for (int nt = 0; nt < 16; nt++)
        #pragma unroll
        for (int e = 0; e < 4; e++) o[nt][e] = 0.f;
    float m0r = -1e30f, m1r = -1e30f, l0r = 0.f, l1r = 0.f;

    const float SC2 = 0.08838834764831845f * 1.4426950408889634f;
    int i0 = q0 + wid * 16 + g;

    uint32_t qa_h = sb0 + (uint32_t)(((wid * 16 + a_row) * QKSTR + a_kof) * 2);
    uint32_t qa_l = qa_h + (uint32_t)(QSZ * 2);

    for (int kt = 0; kt < nkt; kt++) {
        if (kt + 1 < nkt) { issue_kv(kt + 1); CP_WAIT1(); }
        else              { CP_WAIT0(); }
        __syncthreads();

        uint32_t kb = sb0 + (uint32_t)((2 * QSZ + (kt & 1) * FBUF) * 2)
                    + (uint32_t)((b_row * QKSTR + b_kof) * 2);
        uint32_t vb = sb0 + (uint32_t)((2 * QSZ + (kt & 1) * FBUF + KSZ) * 2)
                    + (uint32_t)((b_row * VSTR + b_kof) * 2);
        int k0 = kt * 64;

        // ---- S = Q K^T (2-pass fp16 split) ----
        float s[8][4];
        #pragma unroll
        for (int nt = 0; nt < 8; nt++)
            #pragma unroll
            for (int e = 0; e < 4; e++) s[nt][e] = 0.f;

        #pragma unroll
        for (int pass = 0; pass < 2; pass++) {
            uint32_t qa = (pass == 1) ? qa_l : qa_h;
            #pragma unroll
            for (int kc = 0; kc < 8; kc++) {
                uint32_t a[4], b4[4][4];
                ldsm4(a, qa + (uint32_t)(kc * 16 * 2));
                #pragma unroll
                for (int np = 0; np < 4; np++)
                    ldsm4(b4[np], kb + (uint32_t)((np * 16 * QKSTR + kc * 16) * 2));
                #pragma unroll
                for (int nt = 0; nt < 8; nt++)
                    mma16816(s[nt], a, &b4[nt >> 1][(nt & 1) * 2]);
            }
        }

        // ---- scale + causal mask ----
        bool diag = (kt >= nkt - 2);
        #pragma unroll
        for (int nt = 0; nt < 8; nt++) {
            int j0 = k0 + nt * 8 + q * 2;
            #pragma unroll
            for (int e = 0; e < 4; e++) {
                float v = s[nt][e] * SC2;
                if (diag) {
                    int i = i0 + ((e >= 2) ? 8 : 0);
                    int j = j0 + (e & 1);
                    if (j > i) v = -1e30f;
                }
                s[nt][e] = v;
            }
        }

        // ---- online softmax ----
        float mt0 = -1e30f, mt1 = -1e30f;
        #pragma unroll
        for (int nt = 0; nt < 8; nt++) {
            mt0 = fmaxf(mt0, fmaxf(s[nt][0], s[nt][1]));
            mt1 = fmaxf(mt1, fmaxf(s[nt][2], s[nt][3]));
        }
        mt0 = fmaxf(mt0, __shfl_xor_sync(0xffffffffu, mt0, 1));
        mt0 = fmaxf(mt0, __shfl_xor_sync(0xffffffffu, mt0, 2));
        mt1 = fmaxf(mt1, __shfl_xor_sync(0xffffffffu, mt1, 1));
        mt1 = fmaxf(mt1, __shfl_xor_sync(0xffffffffu, mt1, 2));
        float mn0 = fmaxf(m0r, mt0), mn1 = fmaxf(m1r, mt1);
        float al0 = ex2f(m0r - mn0), al1 = ex2f(m1r - mn1);
        m0r = mn0; m1r = mn1;

        float sum0 = 0.f, sum1 = 0.f;
        #pragma unroll
        for (int nt = 0; nt < 8; nt++) {
            s[nt][0] = ex2f(s[nt][0] - mn0);
            s[nt][1] = ex2f(s[nt][1] - mn0);
            s[nt][2] = ex2f(s[nt][2] - mn1);
            s[nt][3] = ex2f(s[nt][3] - mn1);
            sum0 += s[nt][0] + s[nt][1];
            sum1 += s[nt][2] + s[nt][3];
        }
        sum0 += __shfl_xor_sync(0xffffffffu, sum0, 1);
        sum0 += __shfl_xor_sync(0xffffffffu, sum0, 2);
        sum1 += __shfl_xor_sync(0xffffffffu, sum1, 1);
        sum1 += __shfl_xor_sync(0xffffffffu, sum1, 2);
        l0r = l0r * al0 + sum0;
        l1r = l1r * al1 + sum1;

        #pragma unroll
        for (int nt = 0; nt < 16; nt++) {
            o[nt][0] *= al0; o[nt][1] *= al0;
            o[nt][2] *= al1; o[nt][3] *= al1;
        }

        // ---- pack P (fp16 hi/lo split) ----
        uint32_t Ph0[8], Ph1[8], Pl0[8], Pl1[8];
        #pragma unroll
        for (int nt = 0; nt < 8; nt++) {
            float p0 = s[nt][0], p1 = s[nt][1], p2 = s[nt][2], p3 = s[nt][3];
            __half b0 = __float2half(p0), b1 = __float2half(p1);
            __half b2 = __float2half(p2), b3 = __float2half(p3);
            Ph0[nt] = pack2h(b0, b1);
            Ph1[nt] = pack2h(b2, b3);
            Pl0[nt] = pack2h(__float2half(p0 - __half2float(b0)),
                             __float2half(p1 - __half2float(b1)));
            Pl1[nt] = pack2h(__float2half(p2 - __half2float(b2)),
                             __float2half(p3 - __half2float(b3)));
        }

        // ---- O += P V (2-pass fp16 split) ----
        #pragma unroll
        for (int pass = 0; pass < 2; pass++) {
            const uint32_t* A0 = (pass == 1) ? Pl0 : Ph0;
            const uint32_t* A1 = (pass == 1) ? Pl1 : Ph1;
            #pragma unroll
            for (int kc = 0; kc < 4; kc++) {
                uint32_t a[4] = {A0[2 * kc], A1[2 * kc], A0[2 * kc + 1], A1[2 * kc + 1]};
                uint32_t b4[8][4];
                #pragma unroll
                for (int np = 0; np < 8; np++)
                    ldsm4(b4[np], vb + (uint32_t)((np * 16 * VSTR + kc * 16) * 2));
                #pragma unroll
                for (int nt = 0; nt < 16; nt++)
                    mma16816(o[nt], a, &b4[nt >> 1][(nt & 1) * 2]);
            }
        }
        __syncthreads();
    }

    // ---- epilogue ----
    float inv0 = 1.f / l0r, inv1 = 1.f / l1r;
    int row0 = q0 + wid * 16 + g;
    #pragma unroll
    for (int nt = 0; nt < 16; nt++) {
        int col = h * DH + nt * 8 + q * 2;
        float f0 = o[nt][0] * inv0, f1 = o[nt][1] * inv0;
        float f2 = o[nt][2] * inv1, f3 = o[nt][3] * inv1;
        __half b0 = __float2half(f0), b1 = __float2half(f1);
        __half b2 = __float2half(f2), b3 = __float2half(f3);
        *(uint32_t*)(Oh_ + (size_t)row0 * DM + col)       = pack2h(b0, b1);
        *(uint32_t*)(Oh_ + (size_t)(row0 + 8) * DM + col) = pack2h(b2, b3);
        *(uint32_t*)(Ol_ + (size_t)row0 * DM + col)       =
            pack2h(__float2half(f0 - __half2float(b0)),
                   __float2half(f1 - __half2float(b1)));
        *(uint32_t*)(Ol_ + (size_t)(row0 + 8) * DM + col) =
            pack2h(__float2half(f2 - __half2float(b2)),
                   __float2half(f3 - __half2float(b3)));
    }
}

// ---------------------------------------------------------------------------
extern "C" void kernel_launch(void* const* d_in, const int* in_sizes, int n_in,
                              void* d_out, int out_size) {
    const float* x  = (const float*)d_in[0];
    const float* Wq = (const float*)d_in[1];
    const float* Wk = (const float*)d_in[2];
    const float* Wv = (const float*)d_in[3];
    const float* Wo = (const float*)d_in[4];
    float* out = (float*)d_out;

    float *pQ, *pK, *pV;
    cudaGetSymbolAddress((void**)&pQ, g_Q);
    cudaGetSymbolAddress((void**)&pK, g_K);
    cudaGetSymbolAddress((void**)&pV, g_V);
    __half *xh, *xl, *wqh, *wkh, *wvh, *woh, *qh, *ql, *kh, *vth;
    cudaGetSymbolAddress((void**)&xh, g_xh);
    cudaGetSymbolAddress((void**)&xl, g_xl);
    cudaGetSymbolAddress((void**)&wqh, g_Wqh);
    cudaGetSymbolAddress((void**)&wkh, g_Wkh);
    cudaGetSymbolAddress((void**)&wvh, g_Wvh);
    cudaGetSymbolAddress((void**)&woh, g_Woh);
    cudaGetSymbolAddress((void**)&qh, g_Qh);
    cudaGetSymbolAddress((void**)&ql, g_Ql);
    cudaGetSymbolAddress((void**)&kh, g_Kh);
    cudaGetSymbolAddress((void**)&vth, g_Vth);

    size_t gsmem = (size_t)(2 * GBUF) * sizeof(__half);
    cudaFuncSetAttribute(gemm_mma, cudaFuncAttributeMaxDynamicSharedMemorySize, (int)gsmem);
    size_t fsmem = (size_t)(2 * QSZ + 2 * FBUF) * sizeof(__half);
    cudaFuncSetAttribute(flash_mma, cudaFuncAttributeMaxDynamicSharedMemorySize, (int)fsmem);

    dim3 tgrid(DM / 32, DM / 32), tblk(32, 8);
    dim3 ggrid(DM / 128, SEQ / 128);

    // Launch order arranged so ncu (-s 5 -c 1) captures gemm_mma (launch #5).
    rope_tables_kernel<<<(SEQ * HALF + 255) / 256, 256>>>();        // 0
    split_f32<<<(SEQ * DM + 255) / 256, 256>>>(x, xh, xl, SEQ * DM); // 1
    transpose_split<<<tgrid, tblk>>>(Wq, wqh);                       // 2
    transpose_split<<<tgrid, tblk>>>(Wk, wkh);                       // 3
    transpose_split<<<tgrid, tblk>>>(Wv, wvh);                       // 4
    gemm_mma<<<ggrid, 256, gsmem>>>(xh, xl, wqh, pQ);                // 5  <- profiled
    gemm_mma<<<ggrid, 256, gsmem>>>(xh, xl, wkh, pK);                // 6
    gemm_mma<<<ggrid, 256, gsmem>>>(xh, xl, wvh, pV);                // 7
    rope_apply_split<<<(SEQ * NH * HALF) / 256, 256>>>();            // 8
    v_transpose_split<<<tgrid, tblk>>>(pV, vth);                     // 9
    transpose_split<<<tgrid, tblk>>>(Wo, woh);                       // 10
    flash_mma<<<dim3(SEQ / 128, NH), 256, fsmem>>>(qh, ql, kh, vth, xh, xl); // 11
    gemm_mma<<<ggrid, 256, gsmem>>>(xh, xl, woh, out);               // 12
}

// round 9
// speedup vs baseline: 5.9897x; 1.4040x over previous
#include <cuda_runtime.h>
#include <cuda_fp16.h>
#include <math.h>
#include <stdint.h>

#define SEQ 2048
#define DM  2048
#define NH  16
#define DH  128
#define HALF 64

// ---------------- scratch (device globals; allocation-free) ----------------
__device__ float g_Q[SEQ * DM];
__device__ float g_K[SEQ * DM];
__device__ float g_V[SEQ * DM];
__device__ float g_cos[SEQ * HALF];
__device__ float g_sin[SEQ * HALF];
__device__ __half g_xh[SEQ * DM];
__device__ __half g_xl[SEQ * DM];
__device__ __half g_Wqh[DM * DM];
__device__ __half g_Wkh[DM * DM];
__device__ __half g_Wvh[DM * DM];
__device__ __half g_Woh[DM * DM];
__device__ __half g_Qh[SEQ * DM];
__device__ __half g_Kh[SEQ * DM];
__device__ __half g_Vth[DM * SEQ];   // V transposed hi: [col][seq]

// ---------------- helpers ----------------
__device__ __forceinline__ float ex2f(float x) {
    float y;
    asm("ex2.approx.ftz.f32 %0, %1;" : "=f"(y) : "f"(x));
    return y;
}
__device__ __forceinline__ uint32_t pack2h(__half lo, __half hi) {
    __half2 v; v.x = lo; v.y = hi;
    return *(uint32_t*)&v;
}
__device__ __forceinline__ void mma16816(float c[4], const uint32_t a[4], const uint32_t b[2]) {
    asm volatile(
        "mma.sync.aligned.m16n8k16.row.col.f32.f16.f16.f32 "
        "{%0,%1,%2,%3}, {%4,%5,%6,%7}, {%8,%9}, {%0,%1,%2,%3};"
        : "+f"(c[0]), "+f"(c[1]), "+f"(c[2]), "+f"(c[3])
        : "r"(a[0]), "r"(a[1]), "r"(a[2]), "r"(a[3]), "r"(b[0]), "r"(b[1]));
}
__device__ __forceinline__ void ldsm4(uint32_t r[4], uint32_t addr) {
    asm volatile("ldmatrix.sync.aligned.m8n8.x4.shared.b16 {%0,%1,%2,%3}, [%4];"
        : "=r"(r[0]), "=r"(r[1]), "=r"(r[2]), "=r"(r[3]) : "r"(addr));
}
__device__ __forceinline__ void cpa16(void* dst, const void* src) {
    uint32_t d = (uint32_t)__cvta_generic_to_shared(dst);
    asm volatile("cp.async.cg.shared.global [%0], [%1], 16;" :: "r"(d), "l"(src) : "memory");
}
#define CP_COMMIT() asm volatile("cp.async.commit_group;" ::: "memory")
#define CP_WAIT1()  asm volatile("cp.async.wait_group 1;" ::: "memory")
#define CP_WAIT0()  asm volatile("cp.async.wait_group 0;" ::: "memory")

// ---------------- prep kernels ----------------
__global__ void rope_tables_kernel() {
    int idx = blockIdx.x * blockDim.x + threadIdx.x;
    if (idx >= SEQ * HALF) return;
    int s = idx / HALF;
    int j = idx % HALF;
    double inv = 0.61803398874989484820 / pow(10000.0, (double)j / 64.0);
    double ang = (double)s * inv;
    double si, co;
    sincos(ang, &si, &co);
    g_cos[idx] = (float)co;
    g_sin[idx] = (float)si;
}

// RoPE -> Qh, Kh fp16 (hi only; score precision bounded by fp16 truncation anyway)
__global__ void rope_apply_split() {
    int idx = blockIdx.x * blockDim.x + threadIdx.x;
    if (idx >= SEQ * NH * HALF) return;
    int s   = idx / (NH * HALF);
    int rem = idx % (NH * HALF);
    int h   = rem / HALF;
    int j   = rem % HALF;
    int base = s * DM + h * DH + j;
    float c  = g_cos[s * HALF + j];
    float sn = g_sin[s * HALF + j];

    float q1 = g_Q[base], q2 = g_Q[base + HALF];
    g_Qh[base]        = __float2half(q1 * c - q2 * sn);
    g_Qh[base + HALF] = __float2half(q1 * sn + q2 * c);

    float k1 = g_K[base], k2 = g_K[base + HALF];
    g_Kh[base]        = __float2half(k1 * c - k2 * sn);
    g_Kh[base + HALF] = __float2half(k1 * sn + k2 * c);
}

__global__ void split_f32(const float* __restrict__ s, __half* __restrict__ h,
                          __half* __restrict__ l, int n) {
    int i = blockIdx.x * blockDim.x + threadIdx.x;
    if (i >= n) return;
    float x = s[i];
    __half hh = __float2half(x);
    h[i] = hh;
    l[i] = __float2half(x - __half2float(hh));
}

// W[K][N] -> Wt hi [N][K] fp16
__global__ void transpose_split(const float* __restrict__ W, __half* __restrict__ Th) {
    __shared__ float tile[32][33];
    int bx = blockIdx.x * 32;
    int by = blockIdx.y * 32;
    int tx = threadIdx.x, ty = threadIdx.y;
    #pragma unroll
    for (int i = 0; i < 32; i += 8)
        tile[ty + i][tx] = W[(size_t)(by + ty + i) * DM + bx + tx];
    __syncthreads();
    #pragma unroll
    for (int i = 0; i < 32; i += 8)
        Th[(size_t)(bx + ty + i) * DM + by + tx] = __float2half(tile[tx][ty + i]);
}

// V [s][c] -> Vt hi [c][s] fp16
__global__ void v_transpose_split(const float* __restrict__ V, __half* __restrict__ Th) {
    __shared__ float tile[32][33];
    int bx = blockIdx.x * 32;
    int by = blockIdx.y * 32;
    int tx = threadIdx.x, ty = threadIdx.y;
    #pragma unroll
    for (int i = 0; i < 32; i += 8)
        tile[ty + i][tx] = V[(size_t)(by + ty + i) * DM + bx + tx];
    __syncthreads();
    #pragma unroll
    for (int i = 0; i < 32; i += 8)
        Th[(size_t)(bx + ty + i) * SEQ + by + tx] = __float2half(tile[tx][ty + i]);
}

// ---------------------------------------------------------------------------
// fp16 split GEMM with runtime pass count (1 or 2): C = sum_p APASS[p] @ Bh^T.
// cp.async double-buffered, ldmatrix fragments.
// ---------------------------------------------------------------------------
#define AST 72
#define GBUF (2 * 128 * AST)

__global__ void __launch_bounds__(256, 2) gemm_mma(
    const __half* __restrict__ Ah, const __half* __restrict__ Al,
    const __half* __restrict__ Bh, float* __restrict__ C, int npass) {
    extern __shared__ __half dsm[];

    int t    = threadIdx.x;
    int wid  = t >> 5;
    int lane = t & 31;
    int wm   = (wid & 1) * 64;
    int wn   = (wid >> 1) * 32;
    int g    = lane >> 2;
    int q    = lane & 3;
    int m0 = blockIdx.y * 128;
    int n0 = blockIdx.x * 128;
    int lr = t >> 3;
    int lc = t & 7;

    int a_row = (lane & 7) + ((lane >> 3) & 1) * 8;
    int a_kof = (lane >> 4) * 8;
    int b_row = (lane & 7) + (lane >> 4) * 8;
    int b_kof = ((lane >> 3) & 1) * 8;

    const __half* APASS[2] = {Ah, Al};

    float acc[4][4][4];
    #pragma unroll
    for (int mt = 0; mt < 4; mt++)
        #pragma unroll
        for (int nt = 0; nt < 4; nt++)
            #pragma unroll
            for (int e = 0; e < 4; e++) acc[mt][nt][e] = 0.f;

    uint32_t sm0 = (uint32_t)__cvta_generic_to_shared(dsm);
    int NS = npass << 5;

    auto issue = [&](int ss) {
        int pass = ss >> 5;
        int k0   = (ss & 31) * 64;
        const __half* Ag = APASS[pass];
        __half* As = dsm + (ss & 1) * GBUF;
        __half* Bs = As + 128 * AST;
        #pragma unroll
        for (int i = 0; i < 4; i++) {
            int r = lr + i * 32;
            cpa16(As + r * AST + lc * 8, Ag + (size_t)(m0 + r) * DM + k0 + lc * 8);
            cpa16(Bs + r * AST + lc * 8, Bh + (size_t)(n0 + r) * DM + k0 + lc * 8);
        }
        CP_COMMIT();
    };

    issue(0);
    for (int ss = 0; ss < NS; ss++) {
        if (ss + 1 < NS) { issue(ss + 1); CP_WAIT1(); }
        else             { CP_WAIT0(); }
        __syncthreads();

        uint32_t asb = sm0 + (uint32_t)((ss & 1) * GBUF) * 2;
        uint32_t bsb = asb + 128 * AST * 2;
        uint32_t aaddr = asb + (uint32_t)((wm + a_row) * AST + a_kof) * 2;
        uint32_t baddr = bsb + (uint32_t)((wn + b_row) * AST + b_kof) * 2;

        #pragma unroll
        for (int kk = 0; kk < 64; kk += 16) {
            uint32_t a[4][4], b4[2][4];
            #pragma unroll
            for (int mt = 0; mt < 4; mt++)
                ldsm4(a[mt], aaddr + (uint32_t)(mt * 16 * AST + kk) * 2);
            #pragma unroll
            for (int np = 0; np < 2; np++)
                ldsm4(b4[np], baddr + (uint32_t)(np * 16 * AST + kk) * 2);
            #pragma unroll
            for (int mt = 0; mt < 4; mt++)
                #pragma unroll
                for (int nt = 0; nt < 4; nt++)
                    mma16816(acc[mt][nt], a[mt], &b4[nt >> 1][(nt & 1) * 2]);
        }
        __syncthreads();
    }

    #pragma unroll
    for (int mt = 0; mt < 4; mt++) {
        int row = m0 + wm + mt * 16 + g;
        #pragma unroll
        for (int nt = 0; nt < 4; nt++) {
            int col = n0 + wn + nt * 8 + q * 2;
            *(float2*)(C + (size_t)row * DM + col)       = make_float2(acc[mt][nt][0], acc[mt][nt][1]);
            *(float2*)(C + (size_t)(row + 8) * DM + col) = make_float2(acc[mt][nt][2], acc[mt][nt][3]);
        }
    }
}

// ---------------------------------------------------------------------------
// Flash attention: S = Qh Kh^T (1-pass); O = (Ph + Pl) V (2-pass on P).
// cp.async double-buffered K/V, ldmatrix fragments.
// ---------------------------------------------------------------------------
#define QKSTR 136
#define VSTR  72
#define QSZ (128 * QKSTR)
#define KSZ (64 * QKSTR)
#define VSZ (128 * VSTR)
#define FBUF (KSZ + VSZ)

__global__ void __launch_bounds__(256, 1) flash_mma(
    const __half* __restrict__ Qh_, const __half* __restrict__ Kh_,
    const __half* __restrict__ Vh_,
    __half* __restrict__ Oh_, __half* __restrict__ Ol_) {
    extern __shared__ __half sb[];
    __half* sQh = sb;

    int t = threadIdx.x, wid = t >> 5, lane = t & 31;
    int g = lane >> 2, q = lane & 3;
    int h  = blockIdx.y;
    int qt = (int)gridDim.x - 1 - (int)blockIdx.x;
    int q0 = qt * 128;

    int a_row = (lane & 7) + ((lane >> 3) & 1) * 8;
    int a_kof = (lane >> 4) * 8;
    int b_row = (lane & 7) + (lane >> 4) * 8;
    int b_kof = ((lane >> 3) & 1) * 8;

    uint32_t sb0 = (uint32_t)__cvta_generic_to_shared(sb);

    // Q tile load (hi only)
    #pragma unroll
    for (int i = 0; i < 8; i++) {
        int idx = t + i * 256;
        int r = idx >> 4, c = idx & 15;
        cpa16(sQh + r * QKSTR + c * 8, Qh_ + (size_t)(q0 + r) * DM + h * DH + c * 8);
    }
    CP_COMMIT();

    int nkt = 2 * qt + 2;

    auto issue_kv = [&](int kt) {
        int k0 = kt * 64;
        __half* base = sb + QSZ + (kt & 1) * FBUF;
        #pragma unroll
        for (int i = 0; i < 4; i++) {
            int idx = t + i * 256;
            int rk = idx >> 4, ck = idx & 15;
            cpa16(base + rk * QKSTR + ck * 8, Kh_ + (size_t)(k0 + rk) * DM + h * DH + ck * 8);
            int rv = idx >> 3, cv = idx & 7;
            cpa16(base + KSZ + rv * VSTR + cv * 8,
                  Vh_ + (size_t)(h * DH + rv) * SEQ + k0 + cv * 8);
        }
        CP_COMMIT();
    };
    issue_kv(0);

    float o[16][4];
    #pragma unroll
    for (int nt = 0; nt < 16; nt++)
        #pragma unroll
        for (int e = 0; e < 4; e++) o[nt][e] = 0.f;
    float m0r = -1e30f, m1r = -1e30f, l0r = 0.f, l1r = 0.f;

    const float SC2 = 0.08838834764831845f * 1.4426950408889634f;
    int i0 = q0 + wid * 16 + g;

    uint32_t qa_h = sb0 + (uint32_t)(((wid * 16 + a_row) * QKSTR + a_kof) * 2);

    for (int kt = 0; kt < nkt; kt++) {
        if (kt + 1 < nkt) { issue_kv(kt + 1); CP_WAIT1(); }
        else              { CP_WAIT0(); }
        __syncthreads();

        uint32_t kb = sb0 + (uint32_t)((QSZ + (kt & 1) * FBUF) * 2)
                    + (uint32_t)((b_row * QKSTR + b_kof) * 2);
        uint32_t vb = sb0 + (uint32_t)((QSZ + (kt & 1) * FBUF + KSZ) * 2)
                    + (uint32_t)((b_row * VSTR + b_kof) * 2);
        int k0 = kt * 64;

        // ---- S = Qh Kh^T (1 pass) ----
        float s[8][4];
        #pragma unroll
        for (int nt = 0; nt < 8; nt++)
            #pragma unroll
            for (int e = 0; e < 4; e++) s[nt][e] = 0.f;

        #pragma unroll
        for (int kc = 0; kc < 8; kc++) {
            uint32_t a[4], b4[4][4];
            ldsm4(a, qa_h + (uint32_t)(kc * 16 * 2));
            #pragma unroll
            for (int np = 0; np < 4; np++)
                ldsm4(b4[np], kb + (uint32_t)((np * 16 * QKSTR + kc * 16) * 2));
            #pragma unroll
            for (int nt = 0; nt < 8; nt++)
                mma16816(s[nt], a, &b4[nt >> 1][(nt & 1) * 2]);
        }

        // ---- scale + causal mask ----
        bool diag = (kt >= nkt - 2);
        #pragma unroll
        for (int nt = 0; nt < 8; nt++) {
            int j0 = k0 + nt * 8 + q * 2;
            #pragma unroll
            for (int e = 0; e < 4; e++) {
                float v = s[nt][e] * SC2;
                if (diag) {
                    int i = i0 + ((e >= 2) ? 8 : 0);
                    int j = j0 + (e & 1);
                    if (j > i) v = -1e30f;
                }
                s[nt][e] = v;
            }
        }

        // ---- online softmax ----
        float mt0 = -1e30f, mt1 = -1e30f;
        #pragma unroll
        for (int nt = 0; nt < 8; nt++) {
            mt0 = fmaxf(mt0, fmaxf(s[nt][0], s[nt][1]));
            mt1 = fmaxf(mt1, fmaxf(s[nt][2], s[nt][3]));
        }
        mt0 = fmaxf(mt0, __shfl_xor_sync(0xffffffffu, mt0, 1));
        mt0 = fmaxf(mt0, __shfl_xor_sync(0xffffffffu, mt0, 2));
        mt1 = fmaxf(mt1, __shfl_xor_sync(0xffffffffu, mt1, 1));
        mt1 = fmaxf(mt1, __shfl_xor_sync(0xffffffffu, mt1, 2));
        float mn0 = fmaxf(m0r, mt0), mn1 = fmaxf(m1r, mt1);
        float al0 = ex2f(m0r - mn0), al1 = ex2f(m1r - mn1);
        m0r = mn0; m1r = mn1;

        float sum0 = 0.f, sum1 = 0.f;
        #pragma unroll
        for (int nt = 0; nt < 8; nt++) {
            s[nt][0] = ex2f(s[nt][0] - mn0);
            s[nt][1] = ex2f(s[nt][1] - mn0);
            s[nt][2] = ex2f(s[nt][2] - mn1);
            s[nt][3] = ex2f(s[nt][3] - mn1);
            sum0 += s[nt][0] + s[nt][1];
            sum1 += s[nt][2] + s[nt][3];
        }
        sum0 += __shfl_xor_sync(0xffffffffu, sum0, 1);
        sum0 += __shfl_xor_sync(0xffffffffu, sum0, 2);
        sum1 += __shfl_xor_sync(0xffffffffu, sum1, 1);
        sum1 += __shfl_xor_sync(0xffffffffu, sum1, 2);
        l0r = l0r * al0 + sum0;
        l1r = l1r * al1 + sum1;

        #pragma unroll
        for (int nt = 0; nt < 16; nt++) {
            o[nt][0] *= al0; o[nt][1] *= al0;
            o[nt][2] *= al1; o[nt][3] *= al1;
        }

        // ---- pack P (fp16 hi/lo split; output path keeps 2-pass precision) ----
        uint32_t Ph0[8], Ph1[8], Pl0[8], Pl1[8];
        #pragma unroll
        for (int nt = 0; nt < 8; nt++) {
            float p0 = s[nt][0], p1 = s[nt][1], p2 = s[nt][2], p3 = s[nt][3];
            __half b0 = __float2half(p0), b1 = __float2half(p1);
            __half b2 = __float2half(p2), b3 = __float2half(p3);
            Ph0[nt] = pack2h(b0, b1);
            Ph1[nt] = pack2h(b2, b3);
            Pl0[nt] = pack2h(__float2half(p0 - __half2float(b0)),
                             __float2half(p1 - __half2float(b1)));
            Pl1[nt] = pack2h(__float2half(p2 - __half2float(b2)),
                             __float2half(p3 - __half2float(b3)));
        }

        // ---- O += P V (2-pass on P) ----
        #pragma unroll
        for (int pass = 0; pass < 2; pass++) {
            const uint32_t* A0 = (pass == 1) ? Pl0 : Ph0;
            const uint32_t* A1 = (pass == 1) ? Pl1 : Ph1;
            #pragma unroll
            for (int kc = 0; kc < 4; kc++) {
                uint32_t a[4] = {A0[2 * kc], A1[2 * kc], A0[2 * kc + 1], A1[2 * kc + 1]};
                uint32_t b4[8][4];
                #pragma unroll
                for (int np = 0; np < 8; np++)
                    ldsm4(b4[np], vb + (uint32_t)((np * 16 * VSTR + kc * 16) * 2));
                #pragma unroll
                for (int nt = 0; nt < 16; nt++)
                    mma16816(o[nt], a, &b4[nt >> 1][(nt & 1) * 2]);
            }
        }
        __syncthreads();
    }

    // ---- epilogue: normalize, split hi/lo for the 2-pass Wo GEMM ----
    float inv0 = 1.f / l0r, inv1 = 1.f / l1r;
    int row0 = q0 + wid * 16 + g;
    #pragma unroll
    for (int nt = 0; nt < 16; nt++) {
        int col = h * DH + nt * 8 + q * 2;
        float f0 = o[nt][0] * inv0, f1 = o[nt][1] * inv0;
        float f2 = o[nt][2] * inv1, f3 = o[nt][3] * inv1;
        __half b0 = __float2half(f0), b1 = __float2half(f1);
        __half b2 = __float2half(f2), b3 = __float2half(f3);
        *(uint32_t*)(Oh_ + (size_t)row0 * DM + col)       = pack2h(b0, b1);
        *(uint32_t*)(Oh_ + (size_t)(row0 + 8) * DM + col) = pack2h(b2, b3);
        *(uint32_t*)(Ol_ + (size_t)row0 * DM + col)       =
            pack2h(__float2half(f0 - __half2float(b0)),
                   __float2half(f1 - __half2float(b1)));
        *(uint32_t*)(Ol_ + (size_t)(row0 + 8) * DM + col) =
            pack2h(__float2half(f2 - __half2float(b2)),
                   __float2half(f3 - __half2float(b3)));
    }
}

// ---------------------------------------------------------------------------
extern "C" void kernel_launch(void* const* d_in, const int* in_sizes, int n_in,
                              void* d_out, int out_size) {
    const float* x  = (const float*)d_in[0];
    const float* Wq = (const float*)d_in[1];
    const float* Wk = (const float*)d_in[2];
    const float* Wv = (const float*)d_in[3];
    const float* Wo = (const float*)d_in[4];
    float* out = (float*)d_out;

    float *pQ, *pK, *pV;
    cudaGetSymbolAddress((void**)&pQ, g_Q);
    cudaGetSymbolAddress((void**)&pK, g_K);
    cudaGetSymbolAddress((void**)&pV, g_V);
    __half *xh, *xl, *wqh, *wkh, *wvh, *woh, *qh, *kh, *vth;
    cudaGetSymbolAddress((void**)&xh, g_xh);
    cudaGetSymbolAddress((void**)&xl, g_xl);
    cudaGetSymbolAddress((void**)&wqh, g_Wqh);
    cudaGetSymbolAddress((void**)&wkh, g_Wkh);
    cudaGetSymbolAddress((void**)&wvh, g_Wvh);
    cudaGetSymbolAddress((void**)&woh, g_Woh);
    cudaGetSymbolAddress((void**)&qh, g_Qh);
    cudaGetSymbolAddress((void**)&kh, g_Kh);
    cudaGetSymbolAddress((void**)&vth, g_Vth);

    size_t gsmem = (size_t)(2 * GBUF) * sizeof(__half);
    cudaFuncSetAttribute(gemm_mma, cudaFuncAttributeMaxDynamicSharedMemorySize, (int)gsmem);
    size_t fsmem = (size_t)(QSZ + 2 * FBUF) * sizeof(__half);
    cudaFuncSetAttribute(flash_mma, cudaFuncAttributeMaxDynamicSharedMemorySize, (int)fsmem);

    dim3 tgrid(DM / 32, DM / 32), tblk(32, 8);
    dim3 ggrid(DM / 128, SEQ / 128);

    // Launch order arranged so ncu (-s 5 -c 1) captures gemm_mma (launch #5).
    rope_tables_kernel<<<(SEQ * HALF + 255) / 256, 256>>>();         // 0
    split_f32<<<(SEQ * DM + 255) / 256, 256>>>(x, xh, xl, SEQ * DM); // 1
    transpose_split<<<tgrid, tblk>>>(Wq, wqh);                       // 2
    transpose_split<<<tgrid, tblk>>>(Wk, wkh);                       // 3
    transpose_split<<<tgrid, tblk>>>(Wv, wvh);                       // 4
    gemm_mma<<<ggrid, 256, gsmem>>>(xh, xl, wqh, pQ, 1);             // 5  <- profiled
    gemm_mma<<<ggrid, 256, gsmem>>>(xh, xl, wkh, pK, 1);             // 6
    gemm_mma<<<ggrid, 256, gsmem>>>(xh, xl, wvh, pV, 1);             // 7
    rope_apply_split<<<(SEQ * NH * HALF) / 256, 256>>>();            // 8
    v_transpose_split<<<tgrid, tblk>>>(pV, vth);                     // 9
    transpose_split<<<tgrid, tblk>>>(Wo, woh);                       // 10
    flash_mma<<<dim3(SEQ / 128, NH), 256, fsmem>>>(qh, kh, vth, xh, xl); // 11
    gemm_mma<<<ggrid, 256, gsmem>>>(xh, xl, woh, out, 2);            // 12
}

// round 10
// speedup vs baseline: 6.8275x; 1.1399x over previous
#include <cuda_runtime.h>
#include <cuda_fp16.h>
#include <math.h>
#include <stdint.h>

#define SEQ 2048
#define DM  2048
#define NH  16
#define DH  128
#define HALF 64

// ---------------- scratch (device globals; allocation-free) ----------------
__device__ float g_Q[SEQ * DM];
__device__ float g_K[SEQ * DM];
__device__ float g_V[SEQ * DM];
__device__ float g_cos[SEQ * HALF];
__device__ float g_sin[SEQ * HALF];
__device__ __half g_xh[SEQ * DM];
__device__ __half g_Wqh[DM * DM];
__device__ __half g_Wkh[DM * DM];
__device__ __half g_Wvh[DM * DM];
__device__ __half g_Woh[DM * DM];
__device__ __half g_Qh[SEQ * DM];
__device__ __half g_Kh[SEQ * DM];
__device__ __half g_Vth[DM * SEQ];   // V transposed: [col][seq]

// ---------------- helpers ----------------
__device__ __forceinline__ float ex2f(float x) {
    float y;
    asm("ex2.approx.ftz.f32 %0, %1;" : "=f"(y) : "f"(x));
    return y;
}
__device__ __forceinline__ uint32_t pack2h(__half lo, __half hi) {
    __half2 v; v.x = lo; v.y = hi;
    return *(uint32_t*)&v;
}
__device__ __forceinline__ void mma16816(float c[4], const uint32_t a[4], const uint32_t b[2]) {
    asm volatile(
        "mma.sync.aligned.m16n8k16.row.col.f32.f16.f16.f32 "
        "{%0,%1,%2,%3}, {%4,%5,%6,%7}, {%8,%9}, {%0,%1,%2,%3};"
        : "+f"(c[0]), "+f"(c[1]), "+f"(c[2]), "+f"(c[3])
        : "r"(a[0]), "r"(a[1]), "r"(a[2]), "r"(a[3]), "r"(b[0]), "r"(b[1]));
}
__device__ __forceinline__ void ldsm4(uint32_t r[4], uint32_t addr) {
    asm volatile("ldmatrix.sync.aligned.m8n8.x4.shared.b16 {%0,%1,%2,%3}, [%4];"
        : "=r"(r[0]), "=r"(r[1]), "=r"(r[2]), "=r"(r[3]) : "r"(addr));
}
__device__ __forceinline__ void cpa16(void* dst, const void* src) {
    uint32_t d = (uint32_t)__cvta_generic_to_shared(dst);
    asm volatile("cp.async.cg.shared.global [%0], [%1], 16;" :: "r"(d), "l"(src) : "memory");
}
#define CP_COMMIT() asm volatile("cp.async.commit_group;" ::: "memory")
#define CP_WAIT1()  asm volatile("cp.async.wait_group 1;" ::: "memory")
#define CP_WAIT0()  asm volatile("cp.async.wait_group 0;" ::: "memory")

// ---------------- prep kernels ----------------
__global__ void rope_tables_kernel() {
    int idx = blockIdx.x * blockDim.x + threadIdx.x;
    if (idx >= SEQ * HALF) return;
    int s = idx / HALF;
    int j = idx % HALF;
    double inv = 0.61803398874989484820 / pow(10000.0, (double)j / 64.0);
    double ang = (double)s * inv;
    double si, co;
    sincos(ang, &si, &co);
    g_cos[idx] = (float)co;
    g_sin[idx] = (float)si;
}

// RoPE -> Qh, Kh fp16
__global__ void rope_apply_split() {
    int idx = blockIdx.x * blockDim.x + threadIdx.x;
    if (idx >= SEQ * NH * HALF) return;
    int s   = idx / (NH * HALF);
    int rem = idx % (NH * HALF);
    int h   = rem / HALF;
    int j   = rem % HALF;
    int base = s * DM + h * DH + j;
    float c  = g_cos[s * HALF + j];
    float sn = g_sin[s * HALF + j];

    float q1 = g_Q[base], q2 = g_Q[base + HALF];
    g_Qh[base]        = __float2half(q1 * c - q2 * sn);
    g_Qh[base + HALF] = __float2half(q1 * sn + q2 * c);

    float k1 = g_K[base], k2 = g_K[base + HALF];
    g_Kh[base]        = __float2half(k1 * c - k2 * sn);
    g_Kh[base + HALF] = __float2half(k1 * sn + k2 * c);
}

// plain f32 -> f16 convert
__global__ void conv_f16(const float* __restrict__ s, __half* __restrict__ h, int n) {
    int i = blockIdx.x * blockDim.x + threadIdx.x;
    if (i >= n) return;
    h[i] = __float2half(s[i]);
}

// W[K][N] -> Wt [N][K] fp16
__global__ void transpose_h(const float* __restrict__ W, __half* __restrict__ Th) {
    __shared__ float tile[32][33];
    int bx = blockIdx.x * 32;
    int by = blockIdx.y * 32;
    int tx = threadIdx.x, ty = threadIdx.y;
    #pragma unroll
    for (int i = 0; i < 32; i += 8)
        tile[ty + i][tx] = W[(size_t)(by + ty + i) * DM + bx + tx];
    __syncthreads();
    #pragma unroll
    for (int i = 0; i < 32; i += 8)
        Th[(size_t)(bx + ty + i) * DM + by + tx] = __float2half(tile[tx][ty + i]);
}

// V [s][c] -> Vt [c][s] fp16
__global__ void v_transpose_h(const float* __restrict__ V, __half* __restrict__ Th) {
    __shared__ float tile[32][33];
    int bx = blockIdx.x * 32;
    int by = blockIdx.y * 32;
    int tx = threadIdx.x, ty = threadIdx.y;
    #pragma unroll
    for (int i = 0; i < 32; i += 8)
        tile[ty + i][tx] = V[(size_t)(by + ty + i) * DM + bx + tx];
    __syncthreads();
    #pragma unroll
    for (int i = 0; i < 32; i += 8)
        Th[(size_t)(bx + ty + i) * SEQ + by + tx] = __float2half(tile[tx][ty + i]);
}

// ---------------------------------------------------------------------------
// fp16 GEMM (1 pass): C = A @ B^T. cp.async double-buffered, ldmatrix.
// ---------------------------------------------------------------------------
#define AST 72
#define GBUF (2 * 128 * AST)

__global__ void __launch_bounds__(256, 2) gemm_mma(
    const __half* __restrict__ Ah, const __half* __restrict__ Bh,
    float* __restrict__ C) {
    extern __shared__ __half dsm[];

    int t    = threadIdx.x;
    int wid  = t >> 5;
    int lane = t & 31;
    int wm   = (wid & 1) * 64;
    int wn   = (wid >> 1) * 32;
    int g    = lane >> 2;
    int q    = lane & 3;
    int m0 = blockIdx.y * 128;
    int n0 = blockIdx.x * 128;
    int lr = t >> 3;
    int lc = t & 7;

    int a_row = (lane & 7) + ((lane >> 3) & 1) * 8;
    int a_kof = (lane >> 4) * 8;
    int b_row = (lane & 7) + (lane >> 4) * 8;
    int b_kof = ((lane >> 3) & 1) * 8;

    float acc[4][4][4];
    #pragma unroll
    for (int mt = 0; mt < 4; mt++)
        #pragma unroll
        for (int nt = 0; nt < 4; nt++)
            #pragma unroll
            for (int e = 0; e < 4; e++) acc[mt][nt][e] = 0.f;

    uint32_t sm0 = (uint32_t)__cvta_generic_to_shared(dsm);

    auto issue = [&](int ss) {
        int k0 = ss * 64;
        __half* As = dsm + (ss & 1) * GBUF;
        __half* Bs = As + 128 * AST;
        #pragma unroll
        for (int i = 0; i < 4; i++) {
            int r = lr + i * 32;
            cpa16(As + r * AST + lc * 8, Ah + (size_t)(m0 + r) * DM + k0 + lc * 8);
            cpa16(Bs + r * AST + lc * 8, Bh + (size_t)(n0 + r) * DM + k0 + lc * 8);
        }
        CP_COMMIT();
    };

    issue(0);
    for (int ss = 0; ss < 32; ss++) {
        if (ss + 1 < 32) { issue(ss + 1); CP_WAIT1(); }
        else             { CP_WAIT0(); }
        __syncthreads();

        uint32_t asb = sm0 + (uint32_t)((ss & 1) * GBUF) * 2;
        uint32_t bsb = asb + 128 * AST * 2;
        uint32_t aaddr = asb + (uint32_t)((wm + a_row) * AST + a_kof) * 2;
        uint32_t baddr = bsb + (uint32_t)((wn + b_row) * AST + b_kof) * 2;

        #pragma unroll
        for (int kk = 0; kk < 64; kk += 16) {
            uint32_t a[4][4], b4[2][4];
            #pragma unroll
            for (int mt = 0; mt < 4; mt++)
                ldsm4(a[mt], aaddr + (uint32_t)(mt * 16 * AST + kk) * 2);
            #pragma unroll
            for (int np = 0; np < 2; np++)
                ldsm4(b4[np], baddr + (uint32_t)(np * 16 * AST + kk) * 2);
            #pragma unroll
            for (int mt = 0; mt < 4; mt++)
                #pragma unroll
                for (int nt = 0; nt < 4; nt++)
                    mma16816(acc[mt][nt], a[mt], &b4[nt >> 1][(nt & 1) * 2]);
        }
        __syncthreads();
    }

    #pragma unroll
    for (int mt = 0; mt < 4; mt++) {
        int row = m0 + wm + mt * 16 + g;
        #pragma unroll
        for (int nt = 0; nt < 4; nt++) {
            int col = n0 + wn + nt * 8 + q * 2;
            *(float2*)(C + (size_t)row * DM + col)       = make_float2(acc[mt][nt][0], acc[mt][nt][1]);
            *(float2*)(C + (size_t)(row + 8) * DM + col) = make_float2(acc[mt][nt][2], acc[mt][nt][3]);
        }
    }
}

// ---------------------------------------------------------------------------
// Flash attention: S = Qh Kh^T (1-pass); O = (Ph + Pl) V (2-pass on P).
// ---------------------------------------------------------------------------
#define QKSTR 136
#define VSTR  72
#define QSZ (128 * QKSTR)
#define KSZ (64 * QKSTR)
#define VSZ (128 * VSTR)
#define FBUF (KSZ + VSZ)

__global__ void __launch_bounds__(256, 1) flash_mma(
    const __half* __restrict__ Qh_, const __half* __restrict__ Kh_,
    const __half* __restrict__ Vh_, __half* __restrict__ Oh_) {
    extern __shared__ __half sb[];
    __half* sQh = sb;

    int t = threadIdx.x, wid = t >> 5, lane = t & 31;
    int g = lane >> 2, q = lane & 3;
    int h  = blockIdx.y;
    int qt = (int)gridDim.x - 1 - (int)blockIdx.x;
    int q0 = qt * 128;

    int a_row = (lane & 7) + ((lane >> 3) & 1) * 8;
    int a_kof = (lane >> 4) * 8;
    int b_row = (lane & 7) + (lane >> 4) * 8;
    int b_kof = ((lane >> 3) & 1) * 8;

    uint32_t sb0 = (uint32_t)__cvta_generic_to_shared(sb);

    // Q tile load
    #pragma unroll
    for (int i = 0; i < 8; i++) {
        int idx = t + i * 256;
        int r = idx >> 4, c = idx & 15;
        cpa16(sQh + r * QKSTR + c * 8, Qh_ + (size_t)(q0 + r) * DM + h * DH + c * 8);
    }
    CP_COMMIT();

    int nkt = 2 * qt + 2;

    auto issue_kv = [&](int kt) {
        int k0 = kt * 64;
        __half* base = sb + QSZ + (kt & 1) * FBUF;
        #pragma unroll
        for (int i = 0; i < 4; i++) {
            int idx = t + i * 256;
            int rk = idx >> 4, ck = idx & 15;
            cpa16(base + rk * QKSTR + ck * 8, Kh_ + (size_t)(k0 + rk) * DM + h * DH + ck * 8);
            int rv = idx >> 3, cv = idx & 7;
            cpa16(base + KSZ + rv * VSTR + cv * 8,
                  Vh_ + (size_t)(h * DH + rv) * SEQ + k0 + cv * 8);
        }
        CP_COMMIT();
    };
    issue_kv(0);

    float o[16][4];
    #pragma unroll
    for (int nt = 0; nt < 16; nt++)
        #pragma unroll
        for (int e = 0; e < 4; e++) o[nt][e] = 0.f;
    float m0r = -1e30f, m1r = -1e30f, l0r = 0.f, l1r = 0.f;

    const float SC2 = 0.08838834764831845f * 1.4426950408889634f;
    int i0 = q0 + wid * 16 + g;

    uint32_t qa_h = sb0 + (uint32_t)(((wid * 16 + a_row) * QKSTR + a_kof) * 2);

    for (int kt = 0; kt < nkt; kt++) {
        if (kt + 1 < nkt) { issue_kv(kt + 1); CP_WAIT1(); }
        else              { CP_WAIT0(); }
        __syncthreads();

        uint32_t kb = sb0 + (uint32_t)((QSZ + (kt & 1) * FBUF) * 2)
                    + (uint32_t)((b_row * QKSTR + b_kof) * 2);
        uint32_t vb = sb0 + (uint32_t)((QSZ + (kt & 1) * FBUF + KSZ) * 2)
                    + (uint32_t)((b_row * VSTR + b_kof) * 2);
        int k0 = kt * 64;

        // ---- S = Qh Kh^T ----
        float s[8][4];
        #pragma unroll
        for (int nt = 0; nt < 8; nt++)
            #pragma unroll
            for (int e = 0; e < 4; e++) s[nt][e] = 0.f;

        #pragma unroll
        for (int kc = 0; kc < 8; kc++) {
            uint32_t a[4], b4[4][4];
            ldsm4(a, qa_h + (uint32_t)(kc * 16 * 2));
            #pragma unroll
            for (int np = 0; np < 4; np++)
                ldsm4(b4[np], kb + (uint32_t)((np * 16 * QKSTR + kc * 16) * 2));
            #pragma unroll
            for (int nt = 0; nt < 8; nt++)
                mma16816(s[nt], a, &b4[nt >> 1][(nt & 1) * 2]);
        }

        // ---- scale + causal mask ----
        bool diag = (kt >= nkt - 2);
        #pragma unroll
        for (int nt = 0; nt < 8; nt++) {
            int j0 = k0 + nt * 8 + q * 2;
            #pragma unroll
            for (int e = 0; e < 4; e++) {
                float v = s[nt][e] * SC2;
                if (diag) {
                    int i = i0 + ((e >= 2) ? 8 : 0);
                    int j = j0 + (e & 1);
                    if (j > i) v = -1e30f;
                }
                s[nt][e] = v;
            }
        }

        // ---- online softmax ----
        float mt0 = -1e30f, mt1 = -1e30f;
        #pragma unroll
        for (int nt = 0; nt < 8; nt++) {
            mt0 = fmaxf(mt0, fmaxf(s[nt][0], s[nt][1]));
            mt1 = fmaxf(mt1, fmaxf(s[nt][2], s[nt][3]));
        }
        mt0 = fmaxf(mt0, __shfl_xor_sync(0xffffffffu, mt0, 1));
        mt0 = fmaxf(mt0, __shfl_xor_sync(0xffffffffu, mt0, 2));
        mt1 = fmaxf(mt1, __shfl_xor_sync(0xffffffffu, mt1, 1));
        mt1 = fmaxf(mt1, __shfl_xor_sync(0xffffffffu, mt1, 2));
        float mn0 = fmaxf(m0r, mt0), mn1 = fmaxf(m1r, mt1);
        float al0 = ex2f(m0r - mn0), al1 = ex2f(m1r - mn1);
        m0r = mn0; m1r = mn1;

        float sum0 = 0.f, sum1 = 0.f;
        #pragma unroll
        for (int nt = 0; nt < 8; nt++) {
            s[nt][0] = ex2f(s[nt][0] - mn0);
            s[nt][1] = ex2f(s[nt][1] - mn0);
            s[nt][2] = ex2f(s[nt][2] - mn1);
            s[nt][3] = ex2f(s[nt][3] - mn1);
            sum0 += s[nt][0] + s[nt][1];
            sum1 += s[nt][2] + s[nt][3];
        }
        sum0 += __shfl_xor_sync(0xffffffffu, sum0, 1);
        sum0 += __shfl_xor_sync(0xffffffffu, sum0, 2);
        sum1 += __shfl_xor_sync(0xffffffffu, sum1, 1);
        sum1 += __shfl_xor_sync(0xffffffffu, sum1, 2);
        l0r = l0r * al0 + sum0;
        l1r = l1r * al1 + sum1;

        #pragma unroll
        for (int nt = 0; nt < 16; nt++) {
            o[nt][0] *= al0; o[nt][1] *= al0;
            o[nt][2] *= al1; o[nt][3] *= al1;
        }

        // ---- pack P (fp16 hi/lo; output path keeps 2-pass precision) ----
        uint32_t Ph0[8], Ph1[8], Pl0[8], Pl1[8];
        #pragma unroll
        for (int nt = 0; nt < 8; nt++) {
            float p0 = s[nt][0], p1 = s[nt][1], p2 = s[nt][2], p3 = s[nt][3];
            __half b0 = __float2half(p0), b1 = __float2half(p1);
            __half b2 = __float2half(p2), b3 = __float2half(p3);
            Ph0[nt] = pack2h(b0, b1);
            Ph1[nt] = pack2h(b2, b3);
            Pl0[nt] = pack2h(__float2half(p0 - __half2float(b0)),
                             __float2half(p1 - __half2float(b1)));
            Pl1[nt] = pack2h(__float2half(p2 - __half2float(b2)),
                             __float2half(p3 - __half2float(b3)));
        }

        // ---- O += P V (2-pass on P) ----
        #pragma unroll
        for (int pass = 0; pass < 2; pass++) {
            const uint32_t* A0 = (pass == 1) ? Pl0 : Ph0;
            const uint32_t* A1 = (pass == 1) ? Pl1 : Ph1;
            #pragma unroll
            for (int kc = 0; kc < 4; kc++) {
                uint32_t a[4] = {A0[2 * kc], A1[2 * kc], A0[2 * kc + 1], A1[2 * kc + 1]};
                uint32_t b4[8][4];
                #pragma unroll
                for (int np = 0; np < 8; np++)
                    ldsm4(b4[np], vb + (uint32_t)((np * 16 * VSTR + kc * 16) * 2));
                #pragma unroll
                for (int nt = 0; nt < 16; nt++)
                    mma16816(o[nt], a, &b4[nt >> 1][(nt & 1) * 2]);
            }
        }
        __syncthreads();
    }

    // ---- epilogue: normalize, convert to fp16 ----
    float inv0 = 1.f / l0r, inv1 = 1.f / l1r;
    int row0 = q0 + wid * 16 + g;
    #pragma unroll
    for (int nt = 0; nt < 16; nt++) {
        int col = h * DH + nt * 8 + q * 2;
        *(uint32_t*)(Oh_ + (size_t)row0 * DM + col) =
            pack2h(__float2half(o[nt][0] * inv0), __float2half(o[nt][1] * inv0));
        *(uint32_t*)(Oh_ + (size_t)(row0 + 8) * DM + col) =
            pack2h(__float2half(o[nt][2] * inv1), __float2half(o[nt][3] * inv1));
    }
}

// ---------------------------------------------------------------------------
extern "C" void kernel_launch(void* const* d_in, const int* in_sizes, int n_in,
                              void* d_out, int out_size) {
    const float* x  = (const float*)d_in[0];
    const float* Wq = (const float*)d_in[1];
    const float* Wk = (const float*)d_in[2];
    const float* Wv = (const float*)d_in[3];
    const float* Wo = (const float*)d_in[4];
    float* out = (float*)d_out;

    float *pQ, *pK, *pV;
    cudaGetSymbolAddress((void**)&pQ, g_Q);
    cudaGetSymbolAddress((void**)&pK, g_K);
    cudaGetSymbolAddress((void**)&pV, g_V);
    __half *xh, *wqh, *wkh, *wvh, *woh, *qh, *kh, *vth;
    cudaGetSymbolAddress((void**)&xh, g_xh);
    cudaGetSymbolAddress((void**)&wqh, g_Wqh);
    cudaGetSymbolAddress((void**)&wkh, g_Wkh);
    cudaGetSymbolAddress((void**)&wvh, g_Wvh);
    cudaGetSymbolAddress((void**)&woh, g_Woh);
    cudaGetSymbolAddress((void**)&qh, g_Qh);
    cudaGetSymbolAddress((void**)&kh, g_Kh);
    cudaGetSymbolAddress((void**)&vth, g_Vth);

    size_t gsmem = (size_t)(2 * GBUF) * sizeof(__half);
    cudaFuncSetAttribute(gemm_mma, cudaFuncAttributeMaxDynamicSharedMemorySize, (int)gsmem);
    size_t fsmem = (size_t)(QSZ + 2 * FBUF) * sizeof(__half);
    cudaFuncSetAttribute(flash_mma, cudaFuncAttributeMaxDynamicSharedMemorySize, (int)fsmem);

    dim3 tgrid(DM / 32, DM / 32), tblk(32, 8);
    dim3 ggrid(DM / 128, SEQ / 128);

    // Launch order arranged so ncu (-s 5 -c 1) captures gemm_mma (launch #5).
    rope_tables_kernel<<<(SEQ * HALF + 255) / 256, 256>>>();         // 0
    conv_f16<<<(SEQ * DM + 255) / 256, 256>>>(x, xh, SEQ * DM);      // 1
    transpose_h<<<tgrid, tblk>>>(Wq, wqh);                           // 2
    transpose_h<<<tgrid, tblk>>>(Wk, wkh);                           // 3
    transpose_h<<<tgrid, tblk>>>(Wv, wvh);                           // 4
    gemm_mma<<<ggrid, 256, gsmem>>>(xh, wqh, pQ);                    // 5  <- profiled
    gemm_mma<<<ggrid, 256, gsmem>>>(xh, wkh, pK);                    // 6
    gemm_mma<<<ggrid, 256, gsmem>>>(xh, wvh, pV);                    // 7
    rope_apply_split<<<(SEQ * NH * HALF) / 256, 256>>>();            // 8
    v_transpose_h<<<tgrid, tblk>>>(pV, vth);                         // 9
    transpose_h<<<tgrid, tblk>>>(Wo, woh);                           // 10
    flash_mma<<<dim3(SEQ / 128, NH), 256, fsmem>>>(qh, kh, vth, xh); // 11
    gemm_mma<<<ggrid, 256, gsmem>>>(xh, woh, out);                   // 12
}

// round 12
// speedup vs baseline: 6.8891x; 1.0090x over previous
#include <cuda_runtime.h>
#include <cuda_fp16.h>
#include <math.h>
#include <stdint.h>

#define SEQ 2048
#define DM  2048
#define NH  16
#define DH  128
#define HALF 64

// ---------------- scratch (device globals; allocation-free) ----------------
__device__ float g_Q[SEQ * DM];
__device__ float g_K[SEQ * DM];
__device__ float g_cos[SEQ * HALF];
__device__ float g_sin[SEQ * HALF];
__device__ __half g_xh[SEQ * DM];
__device__ __half g_Wqh[DM * DM];
__device__ __half g_Wkh[DM * DM];
__device__ __half g_Wvh[DM * DM];
__device__ __half g_Woh[DM * DM];
__device__ __half g_Qh[SEQ * DM];
__device__ __half g_Kh[SEQ * DM];
__device__ __half g_Vth[DM * SEQ];   // V transposed: [col][seq]

// ---------------- helpers ----------------
__device__ __forceinline__ float ex2f(float x) {
    float y;
    asm("ex2.approx.ftz.f32 %0, %1;" : "=f"(y) : "f"(x));
    return y;
}
__device__ __forceinline__ uint32_t pack2h(__half lo, __half hi) {
    __half2 v; v.x = lo; v.y = hi;
    return *(uint32_t*)&v;
}
__device__ __forceinline__ void mma16816(float c[4], const uint32_t a[4], const uint32_t b[2]) {
    asm volatile(
        "mma.sync.aligned.m16n8k16.row.col.f32.f16.f16.f32 "
        "{%0,%1,%2,%3}, {%4,%5,%6,%7}, {%8,%9}, {%0,%1,%2,%3};"
        : "+f"(c[0]), "+f"(c[1]), "+f"(c[2]), "+f"(c[3])
        : "r"(a[0]), "r"(a[1]), "r"(a[2]), "r"(a[3]), "r"(b[0]), "r"(b[1]));
}
__device__ __forceinline__ void ldsm4(uint32_t r[4], uint32_t addr) {
    asm volatile("ldmatrix.sync.aligned.m8n8.x4.shared.b16 {%0,%1,%2,%3}, [%4];"
        : "=r"(r[0]), "=r"(r[1]), "=r"(r[2]), "=r"(r[3]) : "r"(addr));
}
__device__ __forceinline__ void cpa16(void* dst, const void* src) {
    uint32_t d = (uint32_t)__cvta_generic_to_shared(dst);
    asm volatile("cp.async.cg.shared.global [%0], [%1], 16;" :: "r"(d), "l"(src) : "memory");
}
#define CP_COMMIT() asm volatile("cp.async.commit_group;" ::: "memory")
#define CP_WAIT1()  asm volatile("cp.async.wait_group 1;" ::: "memory")
#define CP_WAIT0()  asm volatile("cp.async.wait_group 0;" ::: "memory")

// ---------------- prep kernels ----------------
__global__ void rope_tables_kernel() {
    int idx = blockIdx.x * blockDim.x + threadIdx.x;
    if (idx >= SEQ * HALF) return;
    int s = idx / HALF;
    int j = idx % HALF;
    double inv = 0.61803398874989484820 / pow(10000.0, (double)j / 64.0);
    double ang = (double)s * inv;
    double si, co;
    sincos(ang, &si, &co);
    g_cos[idx] = (float)co;
    g_sin[idx] = (float)si;
}

// RoPE -> Qh, Kh fp16
__global__ void rope_apply_split() {
    int idx = blockIdx.x * blockDim.x + threadIdx.x;
    if (idx >= SEQ * NH * HALF) return;
    int s   = idx / (NH * HALF);
    int rem = idx % (NH * HALF);
    int h   = rem / HALF;
    int j   = rem % HALF;
    int base = s * DM + h * DH + j;
    float c  = g_cos[s * HALF + j];
    float sn = g_sin[s * HALF + j];

    float q1 = g_Q[base], q2 = g_Q[base + HALF];
    g_Qh[base]        = __float2half(q1 * c - q2 * sn);
    g_Qh[base + HALF] = __float2half(q1 * sn + q2 * c);

    float k1 = g_K[base], k2 = g_K[base + HALF];
    g_Kh[base]        = __float2half(k1 * c - k2 * sn);
    g_Kh[base + HALF] = __float2half(k1 * sn + k2 * c);
}

// plain f32 -> f16 convert
__global__ void conv_f16(const float* __restrict__ s, __half* __restrict__ h, int n) {
    int i = blockIdx.x * blockDim.x + threadIdx.x;
    if (i >= n) return;
    h[i] = __float2half(s[i]);
}

// W[K][N] -> Wt [N][K] fp16
__global__ void transpose_h(const float* __restrict__ W, __half* __restrict__ Th) {
    __shared__ float tile[32][33];
    int bx = blockIdx.x * 32;
    int by = blockIdx.y * 32;
    int tx = threadIdx.x, ty = threadIdx.y;
    #pragma unroll
    for (int i = 0; i < 32; i += 8)
        tile[ty + i][tx] = W[(size_t)(by + ty + i) * DM + bx + tx];
    __syncthreads();
    #pragma unroll
    for (int i = 0; i < 32; i += 8)
        Th[(size_t)(bx + ty + i) * DM + by + tx] = __float2half(tile[tx][ty + i]);
}

// ---------------------------------------------------------------------------
// fp16 GEMM (1 pass): C = A @ B^T. cp.async double-buffered, ldmatrix.
// Two epilogue flavors: fp32 row-major (gemm_mma) and transposed-fp16
// (gemm_mma_vt -> writes Vt[col][row], eliminating the V transpose kernel).
// ---------------------------------------------------------------------------
#define AST 72
#define GBUF (2 * 128 * AST)

#define GEMM_PROLOG_AND_MAINLOOP                                                     \
    extern __shared__ __half dsm[];                                                  \
    int t    = threadIdx.x;                                                          \
    int wid  = t >> 5;                                                               \
    int lane = t & 31;                                                               \
    int wm   = (wid & 1) * 64;                                                       \
    int wn   = (wid >> 1) * 32;                                                      \
    int g    = lane >> 2;                                                            \
    int q    = lane & 3;                                                             \
    int m0 = blockIdx.y * 128;                                                       \
    int n0 = blockIdx.x * 128;                                                       \
    int lr = t >> 3;                                                                 \
    int lc = t & 7;                                                                  \
    int a_row = (lane & 7) + ((lane >> 3) & 1) * 8;                                  \
    int a_kof = (lane >> 4) * 8;                                                     \
    int b_row = (lane & 7) + (lane >> 4) * 8;                                        \
    int b_kof = ((lane >> 3) & 1) * 8;                                               \
    float acc[4][4][4];                                                              \
    _Pragma("unroll")                                                                \
    for (int mt = 0; mt < 4; mt++)                                                   \
        _Pragma("unroll")                                                            \
        for (int nt = 0; nt < 4; nt++)                                               \
            _Pragma("unroll")                                                        \
            for (int e = 0; e < 4; e++) acc[mt][nt][e] = 0.f;                        \
    uint32_t sm0 = (uint32_t)__cvta_generic_to_shared(dsm);                          \
    auto issue = [&](int ss) {                                                       \
        int k0 = ss * 64;                                                            \
        __half* As = dsm + (ss & 1) * GBUF;                                          \
        __half* Bs = As + 128 * AST;                                                 \
        _Pragma("unroll")                                                            \
        for (int i = 0; i < 4; i++) {                                                \
            int r = lr + i * 32;                                                     \
            cpa16(As + r * AST + lc * 8, Ah + (size_t)(m0 + r) * DM + k0 + lc * 8);  \
            cpa16(Bs + r * AST + lc * 8, Bh + (size_t)(n0 + r) * DM + k0 + lc * 8);  \
        }                                                                            \
        CP_COMMIT();                                                                 \
    };                                                                               \
    issue(0);                                                                        \
    for (int ss = 0; ss < 32; ss++) {                                                \
        if (ss + 1 < 32) { issue(ss + 1); CP_WAIT1(); }                              \
        else             { CP_WAIT0(); }                                             \
        __syncthreads();                                                             \
        uint32_t asb = sm0 + (uint32_t)((ss & 1) * GBUF) * 2;                        \
        uint32_t bsb = asb + 128 * AST * 2;                                          \
        uint32_t aaddr = asb + (uint32_t)((wm + a_row) * AST + a_kof) * 2;           \
        uint32_t baddr = bsb + (uint32_t)((wn + b_row) * AST + b_kof) * 2;           \
        _Pragma("unroll")                                                            \
        for (int kk = 0; kk < 64; kk += 16) {                                        \
            uint32_t a[4][4], b4[2][4];                                              \
            _Pragma("unroll")                                                        \
            for (int mt = 0; mt < 4; mt++)                                           \
                ldsm4(a[mt], aaddr + (uint32_t)(mt * 16 * AST + kk) * 2);            \
            _Pragma("unroll")                                                        \
            for (int np = 0; np < 2; np++)                                           \
                ldsm4(b4[np], baddr + (uint32_t)(np * 16 * AST + kk) * 2);           \
            _Pragma("unroll")                                                        \
            for (int mt = 0; mt < 4; mt++)                                           \
                _Pragma("unroll")                                                    \
                for (int nt = 0; nt < 4; nt++)                                       \
                    mma16816(acc[mt][nt], a[mt], &b4[nt >> 1][(nt & 1) * 2]);        \
        }                                                                            \
        __syncthreads();                                                             \
    }

__global__ void __launch_bounds__(256, 2) gemm_mma(
    const __half* __restrict__ Ah, const __half* __restrict__ Bh,
    float* __restrict__ C) {
    GEMM_PROLOG_AND_MAINLOOP

    #pragma unroll
    for (int mt = 0; mt < 4; mt++) {
        int row = m0 + wm + mt * 16 + g;
        #pragma unroll
        for (int nt = 0; nt < 4; nt++) {
            int col = n0 + wn + nt * 8 + q * 2;
            *(float2*)(C + (size_t)row * DM + col)       = make_float2(acc[mt][nt][0], acc[mt][nt][1]);
            *(float2*)(C + (size_t)(row + 8) * DM + col) = make_float2(acc[mt][nt][2], acc[mt][nt][3]);
        }
    }
}

// V projection with transposed fp16 epilogue: Vt[col][row] = C[row][col]
__global__ void __launch_bounds__(256, 2) gemm_mma_vt(
    const __half* __restrict__ Ah, const __half* __restrict__ Bh,
    __half* __restrict__ Vt) {
    GEMM_PROLOG_AND_MAINLOOP

    #pragma unroll
    for (int mt = 0; mt < 4; mt++) {
        int row = m0 + wm + mt * 16 + g;
        #pragma unroll
        for (int nt = 0; nt < 4; nt++) {
            int col = n0 + wn + nt * 8 + q * 2;
            Vt[(size_t)col * SEQ + row]           = __float2half(acc[mt][nt][0]);
            Vt[(size_t)(col + 1) * SEQ + row]     = __float2half(acc[mt][nt][1]);
            Vt[(size_t)col * SEQ + row + 8]       = __float2half(acc[mt][nt][2]);
            Vt[(size_t)(col + 1) * SEQ + row + 8] = __float2half(acc[mt][nt][3]);
        }
    }
}

// ---------------------------------------------------------------------------
// Flash attention: S = Qh Kh^T (1-pass); O = (Ph + Pl) V (2-pass on P).
// ---------------------------------------------------------------------------
#define QKSTR 136
#define VSTR  72
#define QSZ (128 * QKSTR)
#define KSZ (64 * QKSTR)
#define VSZ (128 * VSTR)
#define FBUF (KSZ + VSZ)

__global__ void __launch_bounds__(256, 1) flash_mma(
    const __half* __restrict__ Qh_, const __half* __restrict__ Kh_,
    const __half* __restrict__ Vh_, __half* __restrict__ Oh_) {
    extern __shared__ __half sb[];
    __half* sQh = sb;

    int t = threadIdx.x, wid = t >> 5, lane = t & 31;
    int g = lane >> 2, q = lane & 3;
    int h  = blockIdx.y;
    int qt = (int)gridDim.x - 1 - (int)blockIdx.x;
    int q0 = qt * 128;

    int a_row = (lane & 7) + ((lane >> 3) & 1) * 8;
    int a_kof = (lane >> 4) * 8;
    int b_row = (lane & 7) + (lane >> 4) * 8;
    int b_kof = ((lane >> 3) & 1) * 8;

    uint32_t sb0 = (uint32_t)__cvta_generic_to_shared(sb);

    // Q tile load
    #pragma unroll
    for (int i = 0; i < 8; i++) {
        int idx = t + i * 256;
        int r = idx >> 4, c = idx & 15;
        cpa16(sQh + r * QKSTR + c * 8, Qh_ + (size_t)(q0 + r) * DM + h * DH + c * 8);
    }
    CP_COMMIT();

    int nkt = 2 * qt + 2;

    auto issue_kv = [&](int kt) {
        int k0 = kt * 64;
        __half* base = sb + QSZ + (kt & 1) * FBUF;
        #pragma unroll
        for (int i = 0; i < 4; i++) {
            int idx = t + i * 256;
            int rk = idx >> 4, ck = idx & 15;
            cpa16(base + rk * QKSTR + ck * 8, Kh_ + (size_t)(k0 + rk) * DM + h * DH + ck * 8);
            int rv = idx >> 3, cv = idx & 7;
            cpa16(base + KSZ + rv * VSTR + cv * 8,
                  Vh_ + (size_t)(h * DH + rv) * SEQ + k0 + cv * 8);
        }
        CP_COMMIT();
    };
    issue_kv(0);

    float o[16][4];
    #pragma unroll
    for (int nt = 0; nt < 16; nt++)
        #pragma unroll
        for (int e = 0; e < 4; e++) o[nt][e] = 0.f;
    float m0r = -1e30f, m1r = -1e30f, l0r = 0.f, l1r = 0.f;

    const float SC2 = 0.08838834764831845f * 1.4426950408889634f;
    int i0 = q0 + wid * 16 + g;

    uint32_t qa_h = sb0 + (uint32_t)(((wid * 16 + a_row) * QKSTR + a_kof) * 2);

    for (int kt = 0; kt < nkt; kt++) {
        if (kt + 1 < nkt) { issue_kv(kt + 1); CP_WAIT1(); }
        else              { CP_WAIT0(); }
        __syncthreads();

        uint32_t kb = sb0 + (uint32_t)((QSZ + (kt & 1) * FBUF) * 2)
                    + (uint32_t)((b_row * QKSTR + b_kof) * 2);
        uint32_t vb = sb0 + (uint32_t)((QSZ + (kt & 1) * FBUF + KSZ) * 2)
                    + (uint32_t)((b_row * VSTR + b_kof) * 2);
        int k0 = kt * 64;

        // ---- S = Qh Kh^T ----
        float s[8][4];
        #pragma unroll
        for (int nt = 0; nt < 8; nt++)
            #pragma unroll
            for (int e = 0; e < 4; e++) s[nt][e] = 0.f;

        #pragma unroll
        for (int kc = 0; kc < 8; kc++) {
            uint32_t a[4], b4[4][4];
            ldsm4(a, qa_h + (uint32_t)(kc * 16 * 2));
            #pragma unroll
            for (int np = 0; np < 4; np++)
                ldsm4(b4[np], kb + (uint32_t)((np * 16 * QKSTR + kc * 16) * 2));
            #pragma unroll
            for (int nt = 0; nt < 8; nt++)
                mma16816(s[nt], a, &b4[nt >> 1][(nt & 1) * 2]);
        }

        // ---- scale + causal mask ----
        bool diag = (kt >= nkt - 2);
        #pragma unroll
        for (int nt = 0; nt < 8; nt++) {
            int j0 = k0 + nt * 8 + q * 2;
            #pragma unroll
            for (int e = 0; e < 4; e++) {
                float v = s[nt][e] * SC2;
                if (diag) {
                    int i = i0 + ((e >= 2) ? 8 : 0);
                    int j = j0 + (e & 1);
                    if (j > i) v = -1e30f;
                }
                s[nt][e] = v;
            }
        }

        // ---- online softmax ----
        float mt0 = -1e30f, mt1 = -1e30f;
        #pragma unroll
        for (int nt = 0; nt < 8; nt++) {
            mt0 = fmaxf(mt0, fmaxf(s[nt][0], s[nt][1]));
            mt1 = fmaxf(mt1, fmaxf(s[nt][2], s[nt][3]));
        }
        mt0 = fmaxf(mt0, __shfl_xor_sync(0xffffffffu, mt0, 1));
        mt0 = fmaxf(mt0, __shfl_xor_sync(0xffffffffu, mt0, 2));
        mt1 = fmaxf(mt1, __shfl_xor_sync(0xffffffffu, mt1, 1));
        mt1 = fmaxf(mt1, __shfl_xor_sync(0xffffffffu, mt1, 2));
        float mn0 = fmaxf(m0r, mt0), mn1 = fmaxf(m1r, mt1);
        float al0 = ex2f(m0r - mn0), al1 = ex2f(m1r - mn1);
        m0r = mn0; m1r = mn1;

        float sum0 = 0.f, sum1 = 0.f;
        #pragma unroll
        for (int nt = 0; nt < 8; nt++) {
            s[nt][0] = ex2f(s[nt][0] - mn0);
            s[nt][1] = ex2f(s[nt][1] - mn0);
            s[nt][2] = ex2f(s[nt][2] - mn1);
            s[nt][3] = ex2f(s[nt][3] - mn1);
            sum0 += s[nt][0] + s[nt][1];
            sum1 += s[nt][2] + s[nt][3];
        }
        sum0 += __shfl_xor_sync(0xffffffffu, sum0, 1);
        sum0 += __shfl_xor_sync(0xffffffffu, sum0, 2);
        sum1 += __shfl_xor_sync(0xffffffffu, sum1, 1);
        sum1 += __shfl_xor_sync(0xffffffffu, sum1, 2);
        l0r = l0r * al0 + sum0;
        l1r = l1r * al1 + sum1;

        #pragma unroll
        for (int nt = 0; nt < 16; nt++) {
            o[nt][0] *= al0; o[nt][1] *= al0;
            o[nt][2] *= al1; o[nt][3] *= al1;
        }

        // ---- pack P (fp16 hi/lo; output path keeps 2-pass precision) ----
        uint32_t Ph0[8], Ph1[8], Pl0[8], Pl1[8];
        #pragma unroll
        for (int nt = 0; nt < 8; nt++) {
            float p0 = s[nt][0], p1 = s[nt][1], p2 = s[nt][2], p3 = s[nt][3];
            __half b0 = __float2half(p0), b1 = __float2half(p1);
            __half b2 = __float2half(p2), b3 = __float2half(p3);
            Ph0[nt] = pack2h(b0, b1);
            Ph1[nt] = pack2h(b2, b3);
            Pl0[nt] = pack2h(__float2half(p0 - __half2float(b0)),
                             __float2half(p1 - __half2float(b1)));
            Pl1[nt] = pack2h(__float2half(p2 - __half2float(b2)),
                             __float2half(p3 - __half2float(b3)));
        }

        // ---- O += P V (2-pass on P) ----
        #pragma unroll
        for (int pass = 0; pass < 2; pass++) {
            const uint32_t* A0 = (pass == 1) ? Pl0 : Ph0;
            const uint32_t* A1 = (pass == 1) ? Pl1 : Ph1;
            #pragma unroll
            for (int kc = 0; kc < 4; kc++) {
                uint32_t a[4] = {A0[2 * kc], A1[2 * kc], A0[2 * kc + 1], A1[2 * kc + 1]};
                uint32_t b4[8][4];
                #pragma unroll
                for (int np = 0; np < 8; np++)
                    ldsm4(b4[np], vb + (uint32_t)((np * 16 * VSTR + kc * 16) * 2));
                #pragma unroll
                for (int nt = 0; nt < 16; nt++)
                    mma16816(o[nt], a, &b4[nt >> 1][(nt & 1) * 2]);
            }
        }
        __syncthreads();
    }

    // ---- epilogue: normalize, convert to fp16 ----
    float inv0 = 1.f / l0r, inv1 = 1.f / l1r;
    int row0 = q0 + wid * 16 + g;
    #pragma unroll
    for (int nt = 0; nt < 16; nt++) {
        int col = h * DH + nt * 8 + q * 2;
        *(uint32_t*)(Oh_ + (size_t)row0 * DM + col) =
            pack2h(__float2half(o[nt][0] * inv0), __float2half(o[nt][1] * inv0));
        *(uint32_t*)(Oh_ + (size_t)(row0 + 8) * DM + col) =
            pack2h(__float2half(o[nt][2] * inv1), __float2half(o[nt][3] * inv1));
    }
}

// ---------------------------------------------------------------------------
extern "C" void kernel_launch(void* const* d_in, const int* in_sizes, int n_in,
                              void* d_out, int out_size) {
    const float* x  = (const float*)d_in[0];
    const float* Wq = (const float*)d_in[1];
    const float* Wk = (const float*)d_in[2];
    const float* Wv = (const float*)d_in[3];
    const float* Wo = (const float*)d_in[4];
    float* out = (float*)d_out;

    float *pQ, *pK;
    cudaGetSymbolAddress((void**)&pQ, g_Q);
    cudaGetSymbolAddress((void**)&pK, g_K);
    __half *xh, *wqh, *wkh, *wvh, *woh, *qh, *kh, *vth;
    cudaGetSymbolAddress((void**)&xh, g_xh);
    cudaGetSymbolAddress((void**)&wqh, g_Wqh);
    cudaGetSymbolAddress((void**)&wkh, g_Wkh);
    cudaGetSymbolAddress((void**)&wvh, g_Wvh);
    cudaGetSymbolAddress((void**)&woh, g_Woh);
    cudaGetSymbolAddress((void**)&qh, g_Qh);
    cudaGetSymbolAddress((void**)&kh, g_Kh);
    cudaGetSymbolAddress((void**)&vth, g_Vth);

    size_t gsmem = (size_t)(2 * GBUF) * sizeof(__half);
    cudaFuncSetAttribute(gemm_mma, cudaFuncAttributeMaxDynamicSharedMemorySize, (int)gsmem);
    cudaFuncSetAttribute(gemm_mma_vt, cudaFuncAttributeMaxDynamicSharedMemorySize, (int)gsmem);
    size_t fsmem = (size_t)(QSZ + 2 * FBUF) * sizeof(__half);
    cudaFuncSetAttribute(flash_mma, cudaFuncAttributeMaxDynamicSharedMemorySize, (int)fsmem);

    dim3 tgrid(DM / 32, DM / 32), tblk(32, 8);
    dim3 ggrid(DM / 128, SEQ / 128);

    // Launch order arranged so ncu (-s 5 -c 1) captures gemm_mma (launch #5).
    rope_tables_kernel<<<(SEQ * HALF + 255) / 256, 256>>>();         // 0
    conv_f16<<<(SEQ * DM + 255) / 256, 256>>>(x, xh, SEQ * DM);      // 1
    transpose_h<<<tgrid, tblk>>>(Wq, wqh);                           // 2
    transpose_h<<<tgrid, tblk>>>(Wk, wkh);                           // 3
    transpose_h<<<tgrid, tblk>>>(Wv, wvh);                           // 4
    gemm_mma<<<ggrid, 256, gsmem>>>(xh, wqh, pQ);                    // 5  <- profiled
    gemm_mma<<<ggrid, 256, gsmem>>>(xh, wkh, pK);                    // 6
    gemm_mma_vt<<<ggrid, 256, gsmem>>>(xh, wvh, vth);                // 7  (V direct transposed)
    rope_apply_split<<<(SEQ * NH * HALF) / 256, 256>>>();            // 8
    transpose_h<<<tgrid, tblk>>>(Wo, woh);                           // 9
    flash_mma<<<dim3(SEQ / 128, NH), 256, fsmem>>>(qh, kh, vth, xh); // 10
    gemm_mma<<<ggrid, 256, gsmem>>>(xh, woh, out);                   // 11
}

// round 13
// speedup vs baseline: 7.5680x; 1.0985x over previous
#include <cuda_runtime.h>
#include <cuda_fp16.h>
#include <math.h>
#include <stdint.h>

#define SEQ 2048
#define DM  2048
#define NH  16
#define DH  128
#define HALF 64

// ---------------- scratch (device globals; allocation-free) ----------------
__device__ float g_Q[SEQ * DM];
__device__ float g_K[SEQ * DM];
__device__ float g_cos[SEQ * HALF];
__device__ float g_sin[SEQ * HALF];
__device__ __half g_xh[SEQ * DM];
__device__ __half g_Wqh[DM * DM];
__device__ __half g_Wkh[DM * DM];
__device__ __half g_Wvh[DM * DM];
__device__ __half g_Woh[DM * DM];
__device__ __half g_Qh[SEQ * DM];
__device__ __half g_Kh[SEQ * DM];
__device__ __half g_Vth[DM * SEQ];   // V transposed: [col][seq]

// ---------------- helpers ----------------
__device__ __forceinline__ float ex2f(float x) {
    float y;
    asm("ex2.approx.ftz.f32 %0, %1;" : "=f"(y) : "f"(x));
    return y;
}
__device__ __forceinline__ uint32_t pack2h(__half lo, __half hi) {
    __half2 v; v.x = lo; v.y = hi;
    return *(uint32_t*)&v;
}
__device__ __forceinline__ void mma16816(float c[4], const uint32_t a[4], const uint32_t b[2]) {
    asm volatile(
        "mma.sync.aligned.m16n8k16.row.col.f32.f16.f16.f32 "
        "{%0,%1,%2,%3}, {%4,%5,%6,%7}, {%8,%9}, {%0,%1,%2,%3};"
        : "+f"(c[0]), "+f"(c[1]), "+f"(c[2]), "+f"(c[3])
        : "r"(a[0]), "r"(a[1]), "r"(a[2]), "r"(a[3]), "r"(b[0]), "r"(b[1]));
}
__device__ __forceinline__ void ldsm4(uint32_t r[4], uint32_t addr) {
    asm volatile("ldmatrix.sync.aligned.m8n8.x4.shared.b16 {%0,%1,%2,%3}, [%4];"
        : "=r"(r[0]), "=r"(r[1]), "=r"(r[2]), "=r"(r[3]) : "r"(addr));
}
__device__ __forceinline__ void cpa16(void* dst, const void* src) {
    uint32_t d = (uint32_t)__cvta_generic_to_shared(dst);
    asm volatile("cp.async.cg.shared.global [%0], [%1], 16;" :: "r"(d), "l"(src) : "memory");
}
#define CP_COMMIT() asm volatile("cp.async.commit_group;" ::: "memory")
#define CP_WAIT1()  asm volatile("cp.async.wait_group 1;" ::: "memory")
#define CP_WAIT0()  asm volatile("cp.async.wait_group 0;" ::: "memory")

// ---------------- prep kernels ----------------
__global__ void rope_tables_kernel() {
    int idx = blockIdx.x * blockDim.x + threadIdx.x;
    if (idx >= SEQ * HALF) return;
    int s = idx / HALF;
    int j = idx % HALF;
    double inv = 0.61803398874989484820 / pow(10000.0, (double)j / 64.0);
    double ang = (double)s * inv;
    double si, co;
    sincos(ang, &si, &co);
    g_cos[idx] = (float)co;
    g_sin[idx] = (float)si;
}

// RoPE -> Qh, Kh fp16
__global__ void rope_apply_split() {
    int idx = blockIdx.x * blockDim.x + threadIdx.x;
    if (idx >= SEQ * NH * HALF) return;
    int s   = idx / (NH * HALF);
    int rem = idx % (NH * HALF);
    int h   = rem / HALF;
    int j   = rem % HALF;
    int base = s * DM + h * DH + j;
    float c  = g_cos[s * HALF + j];
    float sn = g_sin[s * HALF + j];

    float q1 = g_Q[base], q2 = g_Q[base + HALF];
    g_Qh[base]        = __float2half(q1 * c - q2 * sn);
    g_Qh[base + HALF] = __float2half(q1 * sn + q2 * c);

    float k1 = g_K[base], k2 = g_K[base + HALF];
    g_Kh[base]        = __float2half(k1 * c - k2 * sn);
    g_Kh[base + HALF] = __float2half(k1 * sn + k2 * c);
}

// plain f32 -> f16 convert
__global__ void conv_f16(const float* __restrict__ s, __half* __restrict__ h, int n) {
    int i = blockIdx.x * blockDim.x + threadIdx.x;
    if (i >= n) return;
    h[i] = __float2half(s[i]);
}

// W[K][N] -> Wt [N][K] fp16; vectorized (64k x 32n tile, half2 coalesced writes)
__global__ void transpose_h(const float* __restrict__ W, __half* __restrict__ Th) {
    __shared__ float tile[32][67];   // [n][k], pad 67: store banks (3c)%32 distinct
    int bk = blockIdx.y * 64;
    int bn = blockIdx.x * 32;
    int t = threadIdx.x;             // 256
    int r = t >> 5;                  // 0..7
    int c = t & 31;                  // 0..31
    #pragma unroll
    for (int i = 0; i < 8; i++)
        tile[c][r + i * 8] = W[(size_t)(bk + r + i * 8) * DM + bn + c];
    __syncthreads();
    #pragma unroll
    for (int i = 0; i < 4; i++) {
        int n = r + i * 8;           // 0..31
        __half2 v;
        v.x = __float2half(tile[n][2 * c]);
        v.y = __float2half(tile[n][2 * c + 1]);
        *(__half2*)(Th + (size_t)(bn + n) * DM + bk + 2 * c) = v;
    }
}

// ---------------------------------------------------------------------------
// fp16 GEMM (1 pass): C = A @ B^T. cp.async double-buffered, ldmatrix.
// Epilogues: fp32 row-major (gemm_mma), transposed fp16 (gemm_mma_vt).
// ---------------------------------------------------------------------------
#define AST 72
#define GBUF (2 * 128 * AST)

#define GEMM_PROLOG_AND_MAINLOOP                                                     \
    extern __shared__ __half dsm[];                                                  \
    int t    = threadIdx.x;                                                          \
    int wid  = t >> 5;                                                               \
    int lane = t & 31;                                                               \
    int wm   = (wid & 1) * 64;                                                       \
    int wn   = (wid >> 1) * 32;                                                      \
    int g    = lane >> 2;                                                            \
    int q    = lane & 3;                                                             \
    int m0 = blockIdx.y * 128;                                                       \
    int n0 = blockIdx.x * 128;                                                       \
    int lr = t >> 3;                                                                 \
    int lc = t & 7;                                                                  \
    int a_row = (lane & 7) + ((lane >> 3) & 1) * 8;                                  \
    int a_kof = (lane >> 4) * 8;                                                     \
    int b_row = (lane & 7) + (lane >> 4) * 8;                                        \
    int b_kof = ((lane >> 3) & 1) * 8;                                               \
    float acc[4][4][4];                                                              \
    _Pragma("unroll")                                                                \
    for (int mt = 0; mt < 4; mt++)                                                   \
        _Pragma("unroll")                                                            \
        for (int nt = 0; nt < 4; nt++)                                               \
            _Pragma("unroll")                                                        \
            for (int e = 0; e < 4; e++) acc[mt][nt][e] = 0.f;                        \
    uint32_t sm0 = (uint32_t)__cvta_generic_to_shared(dsm);                          \
    auto issue = [&](int ss) {                                                       \
        int k0 = ss * 64;                                                            \
        __half* As = dsm + (ss & 1) * GBUF;                                          \
        __half* Bs = As + 128 * AST;                                                 \
        _Pragma("unroll")                                                            \
        for (int i = 0; i < 4; i++) {                                                \
            int r = lr + i * 32;                                                     \
            cpa16(As + r * AST + lc * 8, Ah + (size_t)(m0 + r) * DM + k0 + lc * 8);  \
            cpa16(Bs + r * AST + lc * 8, Bh + (size_t)(n0 + r) * DM + k0 + lc * 8);  \
        }                                                                            \
        CP_COMMIT();                                                                 \
    };                                                                               \
    issue(0);                                                                        \
    for (int ss = 0; ss < 32; ss++) {                                                \
        if (ss + 1 < 32) { issue(ss + 1); CP_WAIT1(); }                              \
        else             { CP_WAIT0(); }                                             \
        __syncthreads();                                                             \
        uint32_t asb = sm0 + (uint32_t)((ss & 1) * GBUF) * 2;                        \
        uint32_t bsb = asb + 128 * AST * 2;                                          \
        uint32_t aaddr = asb + (uint32_t)((wm + a_row) * AST + a_kof) * 2;           \
        uint32_t baddr = bsb + (uint32_t)((wn + b_row) * AST + b_kof) * 2;           \
        _Pragma("unroll")                                                            \
        for (int kk = 0; kk < 64; kk += 16) {                                        \
            uint32_t a[4][4], b4[2][4];                                              \
            _Pragma("unroll")                                                        \
            for (int mt = 0; mt < 4; mt++)                                           \
                ldsm4(a[mt], aaddr + (uint32_t)(mt * 16 * AST + kk) * 2);            \
            _Pragma("unroll")                                                        \
            for (int np = 0; np < 2; np++)                                           \
                ldsm4(b4[np], baddr + (uint32_t)(np * 16 * AST + kk) * 2);           \
            _Pragma("unroll")                                                        \
            for (int mt = 0; mt < 4; mt++)                                           \
                _Pragma("unroll")                                                    \
                for (int nt = 0; nt < 4; nt++)                                       \
                    mma16816(acc[mt][nt], a[mt], &b4[nt >> 1][(nt & 1) * 2]);        \
        }                                                                            \
        __syncthreads();                                                             \
    }

__global__ void __launch_bounds__(256, 2) gemm_mma(
    const __half* __restrict__ Ah, const __half* __restrict__ Bh,
    float* __restrict__ C) {
    GEMM_PROLOG_AND_MAINLOOP

    #pragma unroll
    for (int mt = 0; mt < 4; mt++) {
        int row = m0 + wm + mt * 16 + g;
        #pragma unroll
        for (int nt = 0; nt < 4; nt++) {
            int col = n0 + wn + nt * 8 + q * 2;
            *(float2*)(C + (size_t)row * DM + col)       = make_float2(acc[mt][nt][0], acc[mt][nt][1]);
            *(float2*)(C + (size_t)(row + 8) * DM + col) = make_float2(acc[mt][nt][2], acc[mt][nt][3]);
        }
    }
}

// V projection with transposed fp16 epilogue: Vt[col][row] = C[row][col]
__global__ void __launch_bounds__(256, 2) gemm_mma_vt(
    const __half* __restrict__ Ah, const __half* __restrict__ Bh,
    __half* __restrict__ Vt) {
    GEMM_PROLOG_AND_MAINLOOP

    #pragma unroll
    for (int mt = 0; mt < 4; mt++) {
        int row = m0 + wm + mt * 16 + g;
        #pragma unroll
        for (int nt = 0; nt < 4; nt++) {
            int col = n0 + wn + nt * 8 + q * 2;
            Vt[(size_t)col * SEQ + row]           = __float2half(acc[mt][nt][0]);
            Vt[(size_t)(col + 1) * SEQ + row]     = __float2half(acc[mt][nt][1]);
            Vt[(size_t)col * SEQ + row + 8]       = __float2half(acc[mt][nt][2]);
            Vt[(size_t)(col + 1) * SEQ + row + 8] = __float2half(acc[mt][nt][3]);
        }
    }
}

// ---------------------------------------------------------------------------
// Flash attention: S = Qh Kh^T (1-pass); O = Ph V (1-pass).
// ---------------------------------------------------------------------------
#define QKSTR 136
#define VSTR  72
#define QSZ (128 * QKSTR)
#define KSZ (64 * QKSTR)
#define VSZ (128 * VSTR)
#define FBUF (KSZ + VSZ)

__global__ void __launch_bounds__(256, 1) flash_mma(
    const __half* __restrict__ Qh_, const __half* __restrict__ Kh_,
    const __half* __restrict__ Vh_, __half* __restrict__ Oh_) {
    extern __shared__ __half sb[];
    __half* sQh = sb;

    int t = threadIdx.x, wid = t >> 5, lane = t & 31;
    int g = lane >> 2, q = lane & 3;
    int h  = blockIdx.y;
    int qt = (int)gridDim.x - 1 - (int)blockIdx.x;
    int q0 = qt * 128;

    int a_row = (lane & 7) + ((lane >> 3) & 1) * 8;
    int a_kof = (lane >> 4) * 8;
    int b_row = (lane & 7) + (lane >> 4) * 8;
    int b_kof = ((lane >> 3) & 1) * 8;

    uint32_t sb0 = (uint32_t)__cvta_generic_to_shared(sb);

    // Q tile load
    #pragma unroll
    for (int i = 0; i < 8; i++) {
        int idx = t + i * 256;
        int r = idx >> 4, c = idx & 15;
        cpa16(sQh + r * QKSTR + c * 8, Qh_ + (size_t)(q0 + r) * DM + h * DH + c * 8);
    }
    CP_COMMIT();

    int nkt = 2 * qt + 2;

    auto issue_kv = [&](int kt) {
        int k0 = kt * 64;
        __half* base = sb + QSZ + (kt & 1) * FBUF;
        #pragma unroll
        for (int i = 0; i < 4; i++) {
            int idx = t + i * 256;
            int rk = idx >> 4, ck = idx & 15;
            cpa16(base + rk * QKSTR + ck * 8, Kh_ + (size_t)(k0 + rk) * DM + h * DH + ck * 8);
            int rv = idx >> 3, cv = idx & 7;
            cpa16(base + KSZ + rv * VSTR + cv * 8,
                  Vh_ + (size_t)(h * DH + rv) * SEQ + k0 + cv * 8);
        }
        CP_COMMIT();
    };
    issue_kv(0);

    float o[16][4];
    #pragma unroll
    for (int nt = 0; nt < 16; nt++)
        #pragma unroll
        for (int e = 0; e < 4; e++) o[nt][e] = 0.f;
    float m0r = -1e30f, m1r = -1e30f, l0r = 0.f, l1r = 0.f;

    const float SC2 = 0.08838834764831845f * 1.4426950408889634f;
    int i0 = q0 + wid * 16 + g;

    uint32_t qa_h = sb0 + (uint32_t)(((wid * 16 + a_row) * QKSTR + a_kof) * 2);

    for (int kt = 0; kt < nkt; kt++) {
        if (kt + 1 < nkt) { issue_kv(kt + 1); CP_WAIT1(); }
        else              { CP_WAIT0(); }
        __syncthreads();

        uint32_t kb = sb0 + (uint32_t)((QSZ + (kt & 1) * FBUF) * 2)
                    + (uint32_t)((b_row * QKSTR + b_kof) * 2);
        uint32_t vb = sb0 + (uint32_t)((QSZ + (kt & 1) * FBUF + KSZ) * 2)
                    + (uint32_t)((b_row * VSTR + b_kof) * 2);
        int k0 = kt * 64;

        // ---- S = Qh Kh^T ----
        float s[8][4];
        #pragma unroll
        for (int nt = 0; nt < 8; nt++)
            #pragma unroll
            for (int e = 0; e < 4; e++) s[nt][e] = 0.f;

        #pragma unroll
        for (int kc = 0; kc < 8; kc++) {
            uint32_t a[4], b4[4][4];
            ldsm4(a, qa_h + (uint32_t)(kc * 16 * 2));
            #pragma unroll
            for (int np = 0; np < 4; np++)
                ldsm4(b4[np], kb + (uint32_t)((np * 16 * QKSTR + kc * 16) * 2));
            #pragma unroll
            for (int nt = 0; nt < 8; nt++)
                mma16816(s[nt], a, &b4[nt >> 1][(nt & 1) * 2]);
        }

        // ---- scale + causal mask ----
        bool diag = (kt >= nkt - 2);
        #pragma unroll
        for (int nt = 0; nt < 8; nt++) {
            int j0 = k0 + nt * 8 + q * 2;
            #pragma unroll
            for (int e = 0; e < 4; e++) {
                float v = s[nt][e] * SC2;
                if (diag) {
                    int i = i0 + ((e >= 2) ? 8 : 0);
                    int j = j0 + (e & 1);
                    if (j > i) v = -1e30f;
                }
                s[nt][e] = v;
            }
        }

        // ---- online softmax ----
        float mt0 = -1e30f, mt1 = -1e30f;
        #pragma unroll
        for (int nt = 0; nt < 8; nt++) {
            mt0 = fmaxf(mt0, fmaxf(s[nt][0], s[nt][1]));
            mt1 = fmaxf(mt1, fmaxf(s[nt][2], s[nt][3]));
        }
        mt0 = fmaxf(mt0, __shfl_xor_sync(0xffffffffu, mt0, 1));
        mt0 = fmaxf(mt0, __shfl_xor_sync(0xffffffffu, mt0, 2));
        mt1 = fmaxf(mt1, __shfl_xor_sync(0xffffffffu, mt1, 1));
        mt1 = fmaxf(mt1, __shfl_xor_sync(0xffffffffu, mt1, 2));
        float mn0 = fmaxf(m0r, mt0), mn1 = fmaxf(m1r, mt1);
        float al0 = ex2f(m0r - mn0), al1 = ex2f(m1r - mn1);
        m0r = mn0; m1r = mn1;

        float sum0 = 0.f, sum1 = 0.f;
        #pragma unroll
        for (int nt = 0; nt < 8; nt++) {
            s[nt][0] = ex2f(s[nt][0] - mn0);
            s[nt][1] = ex2f(s[nt][1] - mn0);
            s[nt][2] = ex2f(s[nt][2] - mn1);
            s[nt][3] = ex2f(s[nt][3] - mn1);
            sum0 += s[nt][0] + s[nt][1];
            sum1 += s[nt][2] + s[nt][3];
        }
        sum0 += __shfl_xor_sync(0xffffffffu, sum0, 1);
        sum0 += __shfl_xor_sync(0xffffffffu, sum0, 2);
        sum1 += __shfl_xor_sync(0xffffffffu, sum1, 1);
        sum1 += __shfl_xor_sync(0xffffffffu, sum1, 2);
        l0r = l0r * al0 + sum0;
        l1r = l1r * al1 + sum1;

        #pragma unroll
        for (int nt = 0; nt < 16; nt++) {
            o[nt][0] *= al0; o[nt][1] *= al0;
            o[nt][2] *= al1; o[nt][3] *= al1;
        }

        // ---- pack P (fp16 hi only) ----
        uint32_t Ph0[8], Ph1[8];
        #pragma unroll
        for (int nt = 0; nt < 8; nt++) {
            Ph0[nt] = pack2h(__float2half(s[nt][0]), __float2half(s[nt][1]));
            Ph1[nt] = pack2h(__float2half(s[nt][2]), __float2half(s[nt][3]));
        }

        // ---- O += P V (1 pass) ----
        #pragma unroll
        for (int kc = 0; kc < 4; kc++) {
            uint32_t a[4] = {Ph0[2 * kc], Ph1[2 * kc], Ph0[2 * kc + 1], Ph1[2 * kc + 1]};
            uint32_t b4[8][4];
            #pragma unroll
            for (int np = 0; np < 8; np++)
                ldsm4(b4[np], vb + (uint32_t)((np * 16 * VSTR + kc * 16) * 2));
            #pragma unroll
            for (int nt = 0; nt < 16; nt++)
                mma16816(o[nt], a, &b4[nt >> 1][(nt & 1) * 2]);
        }
        __syncthreads();
    }

    // ---- epilogue: normalize, convert to fp16 ----
    float inv0 = 1.f / l0r, inv1 = 1.f / l1r;
    int row0 = q0 + wid * 16 + g;
    #pragma unroll
    for (int nt = 0; nt < 16; nt++) {
        int col = h * DH + nt * 8 + q * 2;
        *(uint32_t*)(Oh_ + (size_t)row0 * DM + col) =
            pack2h(__float2half(o[nt][0] * inv0), __float2half(o[nt][1] * inv0));
        *(uint32_t*)(Oh_ + (size_t)(row0 + 8) * DM + col) =
            pack2h(__float2half(o[nt][2] * inv1), __float2half(o[nt][3] * inv1));
    }
}

// ---------------------------------------------------------------------------
extern "C" void kernel_launch(void* const* d_in, const int* in_sizes, int n_in,
                              void* d_out, int out_size) {
    const float* x  = (const float*)d_in[0];
    const float* Wq = (const float*)d_in[1];
    const float* Wk = (const float*)d_in[2];
    const float* Wv = (const float*)d_in[3];
    const float* Wo = (const float*)d_in[4];
    float* out = (float*)d_out;

    float *pQ, *pK;
    cudaGetSymbolAddress((void**)&pQ, g_Q);
    cudaGetSymbolAddress((void**)&pK, g_K);
    __half *xh, *wqh, *wkh, *wvh, *woh, *qh, *kh, *vth;
    cudaGetSymbolAddress((void**)&xh, g_xh);
    cudaGetSymbolAddress((void**)&wqh, g_Wqh);
    cudaGetSymbolAddress((void**)&wkh, g_Wkh);
    cudaGetSymbolAddress((void**)&wvh, g_Wvh);
    cudaGetSymbolAddress((void**)&woh, g_Woh);
    cudaGetSymbolAddress((void**)&qh, g_Qh);
    cudaGetSymbolAddress((void**)&kh, g_Kh);
    cudaGetSymbolAddress((void**)&vth, g_Vth);

    size_t gsmem = (size_t)(2 * GBUF) * sizeof(__half);
    cudaFuncSetAttribute(gemm_mma, cudaFuncAttributeMaxDynamicSharedMemorySize, (int)gsmem);
    cudaFuncSetAttribute(gemm_mma_vt, cudaFuncAttributeMaxDynamicSharedMemorySize, (int)gsmem);
    size_t fsmem = (size_t)(QSZ + 2 * FBUF) * sizeof(__half);
    cudaFuncSetAttribute(flash_mma, cudaFuncAttributeMaxDynamicSharedMemorySize, (int)fsmem);

    dim3 tgrid(DM / 32, DM / 64), tblk(256);
    dim3 ggrid(DM / 128, SEQ / 128);

    // Launch order arranged so ncu (-s 5 -c 1) captures gemm_mma (launch #5).
    rope_tables_kernel<<<(SEQ * HALF + 255) / 256, 256>>>();         // 0
    conv_f16<<<(SEQ * DM + 255) / 256, 256>>>(x, xh, SEQ * DM);      // 1
    transpose_h<<<tgrid, tblk>>>(Wq, wqh);                           // 2
    transpose_h<<<tgrid, tblk>>>(Wk, wkh);                           // 3
    transpose_h<<<tgrid, tblk>>>(Wv, wvh);                           // 4
    gemm_mma<<<ggrid, 256, gsmem>>>(xh, wqh, pQ);                    // 5  <- profiled
    gemm_mma<<<ggrid, 256, gsmem>>>(xh, wkh, pK);                    // 6
    gemm_mma_vt<<<ggrid, 256, gsmem>>>(xh, wvh, vth);                // 7
    rope_apply_split<<<(SEQ * NH * HALF) / 256, 256>>>();            // 8
    transpose_h<<<tgrid, tblk>>>(Wo, woh);                           // 9
    flash_mma<<<dim3(SEQ / 128, NH), 256, fsmem>>>(qh, kh, vth, xh); // 10
    gemm_mma<<<ggrid, 256, gsmem>>>(xh, woh, out);                   // 11
}